// round 2
// baseline (speedup 1.0000x reference)
#include <cuda_runtime.h>
#include <math.h>

#define Dh     1024
#define NH     16
#define HD     64
#define SEQ    2048
#define BATCH  4
#define MROWS  8192   // BATCH*SEQ

// ---------------- scratch (static device globals; no allocation) -------------
__device__ float g_q[(size_t)BATCH * NH * SEQ * HD];   // [B,H,S,DH]
__device__ float g_k[(size_t)BATCH * NH * SEQ * HD];
__device__ float g_v[(size_t)BATCH * NH * SEQ * HD];
__device__ float g_ctx[(size_t)MROWS * Dh];            // [B,S,D]

// ---------------- GEMM: out[m,n] = sum_k A[m,k]*W[n,k] + bias[n] -------------
#define BM 128
#define BN 128
#define BK 16

__global__ __launch_bounds__(256, 2) void sgemm_bias(
    const float* __restrict__ A, const float* __restrict__ W,
    const float* __restrict__ bias, float* __restrict__ out, int headLayout)
{
    __shared__ float As[BK][BM];
    __shared__ float Ws[BK][BN];

    const int tid = threadIdx.x;
    const int m0 = blockIdx.y * BM;
    const int n0 = blockIdx.x * BN;
    const int ty = tid >> 4;      // 0..15
    const int tx = tid & 15;      // 0..15

    float acc[8][8];
#pragma unroll
    for (int i = 0; i < 8; ++i)
#pragma unroll
        for (int j = 0; j < 8; ++j) acc[i][j] = 0.f;

    // loader mapping: each thread loads 2 float4 from A and 2 from W per K-tile
    const int lr = tid >> 2;           // 0..63
    const int lc = (tid & 3) * 4;      // 0,4,8,12
    const float* Ap = A + (size_t)(m0 + lr) * Dh + lc;
    const float* Wp = W + (size_t)(n0 + lr) * Dh + lc;

    for (int k0 = 0; k0 < Dh; k0 += BK) {
        __syncthreads();
        float4 a0 = *(const float4*)(Ap + k0);
        float4 a1 = *(const float4*)(Ap + (size_t)64 * Dh + k0);
        float4 w0 = *(const float4*)(Wp + k0);
        float4 w1 = *(const float4*)(Wp + (size_t)64 * Dh + k0);
        As[lc + 0][lr]      = a0.x; As[lc + 1][lr]      = a0.y;
        As[lc + 2][lr]      = a0.z; As[lc + 3][lr]      = a0.w;
        As[lc + 0][lr + 64] = a1.x; As[lc + 1][lr + 64] = a1.y;
        As[lc + 2][lr + 64] = a1.z; As[lc + 3][lr + 64] = a1.w;
        Ws[lc + 0][lr]      = w0.x; Ws[lc + 1][lr]      = w0.y;
        Ws[lc + 2][lr]      = w0.z; Ws[lc + 3][lr]      = w0.w;
        Ws[lc + 0][lr + 64] = w1.x; Ws[lc + 1][lr + 64] = w1.y;
        Ws[lc + 2][lr + 64] = w1.z; Ws[lc + 3][lr + 64] = w1.w;
        __syncthreads();

#pragma unroll
        for (int kk = 0; kk < BK; ++kk) {
            float4 A0 = *(const float4*)&As[kk][ty * 8];
            float4 A1 = *(const float4*)&As[kk][ty * 8 + 4];
            float4 B0 = *(const float4*)&Ws[kk][tx * 8];
            float4 B1 = *(const float4*)&Ws[kk][tx * 8 + 4];
            float av[8] = {A0.x, A0.y, A0.z, A0.w, A1.x, A1.y, A1.z, A1.w};
            float bv[8] = {B0.x, B0.y, B0.z, B0.w, B1.x, B1.y, B1.z, B1.w};
#pragma unroll
            for (int i = 0; i < 8; ++i)
#pragma unroll
                for (int j = 0; j < 8; ++j) acc[i][j] += av[i] * bv[j];
        }
    }

    float bj[8];
#pragma unroll
    for (int j = 0; j < 8; ++j) bj[j] = bias[n0 + tx * 8 + j];

    if (headLayout) {
#pragma unroll
        for (int i = 0; i < 8; ++i) {
            int m = m0 + ty * 8 + i;
            int b = m >> 11, s = m & 2047;
#pragma unroll
            for (int j = 0; j < 8; ++j) {
                int n = n0 + tx * 8 + j;
                int h = n >> 6, dh = n & 63;
                out[(((size_t)((b << 4) + h) << 11) + s) * HD + dh] = acc[i][j] + bj[j];
            }
        }
    } else {
#pragma unroll
        for (int i = 0; i < 8; ++i) {
            int m = m0 + ty * 8 + i;
#pragma unroll
            for (int j = 0; j < 8; ++j) {
                out[(size_t)m * Dh + n0 + tx * 8 + j] = acc[i][j] + bj[j];
            }
        }
    }
}

// ---------------- Flash attention (fp32, online softmax) ---------------------
// grid: (SEQ/64, BATCH*NH), 256 threads
#define QT  64
#define PAD 68          // row stride in floats (keeps float4 alignment)

__global__ __launch_bounds__(256, 2) void attn_kernel(
    const float* __restrict__ Q, const float* __restrict__ K,
    const float* __restrict__ V, float* __restrict__ ctx)
{
    extern __shared__ float sm[];
    float* Qs  = sm;                    // [64][PAD]
    float* Ks  = Qs + 64 * PAD;
    float* Vs  = Ks + 64 * PAD;
    float* Ps  = Vs + 64 * PAD;
    float* m_s = Ps + 64 * PAD;         // [64]
    float* l_s = m_s + 64;              // [64]
    float* c_s = l_s + 64;              // [64]

    const int tid = threadIdx.x;
    const int qb  = blockIdx.x;
    const int bh  = blockIdx.y;

    const float* Qb = Q + ((size_t)bh * SEQ + (size_t)qb * QT) * HD;
    const float* Kb = K + (size_t)bh * SEQ * HD;
    const float* Vb = V + (size_t)bh * SEQ * HD;

    // load Q tile
    for (int i = tid; i < 64 * 16; i += 256) {
        int r = i >> 4, c4 = (i & 15) * 4;
        *(float4*)&Qs[r * PAD + c4] = *(const float4*)(Qb + r * HD + c4);
    }
    if (tid < 64) { m_s[tid] = -1e30f; l_s[tid] = 0.f; }

    const int ty = tid >> 4, tx = tid & 15;
    const int ty4 = ty * 4, tx4 = tx * 4;

    float acc[4][4];
#pragma unroll
    for (int i = 0; i < 4; ++i)
#pragma unroll
        for (int j = 0; j < 4; ++j) acc[i][j] = 0.f;

    for (int kt = 0; kt < SEQ / QT; ++kt) {
        __syncthreads();
        const float* Kt = Kb + (size_t)kt * QT * HD;
        const float* Vt = Vb + (size_t)kt * QT * HD;
        for (int i = tid; i < 64 * 16; i += 256) {
            int r = i >> 4, c4 = (i & 15) * 4;
            *(float4*)&Ks[r * PAD + c4] = *(const float4*)(Kt + r * HD + c4);
            *(float4*)&Vs[r * PAD + c4] = *(const float4*)(Vt + r * HD + c4);
        }
        __syncthreads();

        // scores: s[i][j] = sum_d Qs[ty4+i][d] * Ks[tx4+j][d]
        float sc[4][4];
#pragma unroll
        for (int i = 0; i < 4; ++i)
#pragma unroll
            for (int j = 0; j < 4; ++j) sc[i][j] = 0.f;

#pragma unroll 4
        for (int d = 0; d < HD; d += 4) {
            float4 q[4], k[4];
#pragma unroll
            for (int i = 0; i < 4; ++i) q[i] = *(const float4*)&Qs[(ty4 + i) * PAD + d];
#pragma unroll
            for (int j = 0; j < 4; ++j) k[j] = *(const float4*)&Ks[(tx4 + j) * PAD + d];
#pragma unroll
            for (int i = 0; i < 4; ++i)
#pragma unroll
                for (int j = 0; j < 4; ++j) {
                    sc[i][j] += q[i].x * k[j].x + q[i].y * k[j].y +
                                q[i].z * k[j].z + q[i].w * k[j].w;
                }
        }
#pragma unroll
        for (int i = 0; i < 4; ++i)
#pragma unroll
            for (int j = 0; j < 4; ++j)
                Ps[(ty4 + i) * PAD + tx4 + j] = sc[i][j] * 0.125f;  // 1/sqrt(64)
        __syncthreads();

        // online softmax: 4 threads per row, 16 cols each
        {
            const int row = tid >> 2, seg = tid & 3;
            float* prow = &Ps[row * PAD + seg * 16];
            float mloc = -1e30f;
#pragma unroll
            for (int c = 0; c < 16; ++c) mloc = fmaxf(mloc, prow[c]);
            mloc = fmaxf(mloc, __shfl_xor_sync(0xffffffffu, mloc, 1));
            mloc = fmaxf(mloc, __shfl_xor_sync(0xffffffffu, mloc, 2));
            float mold = m_s[row];
            float mnew = fmaxf(mold, mloc);
            float csc  = __expf(mold - mnew);
            float lsum = 0.f;
#pragma unroll
            for (int c = 0; c < 16; ++c) {
                float e = __expf(prow[c] - mnew);
                prow[c] = e;
                lsum += e;
            }
            lsum += __shfl_xor_sync(0xffffffffu, lsum, 1);
            lsum += __shfl_xor_sync(0xffffffffu, lsum, 2);
            if (seg == 0) {
                m_s[row] = mnew;
                c_s[row] = csc;
                l_s[row] = l_s[row] * csc + lsum;
            }
        }
        __syncthreads();

        // rescale accumulators + PV
        float cf[4];
#pragma unroll
        for (int i = 0; i < 4; ++i) cf[i] = c_s[ty4 + i];
#pragma unroll
        for (int i = 0; i < 4; ++i)
#pragma unroll
            for (int j = 0; j < 4; ++j) acc[i][j] *= cf[i];

#pragma unroll 4
        for (int j0 = 0; j0 < QT; j0 += 4) {
            float4 v0 = *(const float4*)&Vs[(j0 + 0) * PAD + tx4];
            float4 v1 = *(const float4*)&Vs[(j0 + 1) * PAD + tx4];
            float4 v2 = *(const float4*)&Vs[(j0 + 2) * PAD + tx4];
            float4 v3 = *(const float4*)&Vs[(j0 + 3) * PAD + tx4];
#pragma unroll
            for (int i = 0; i < 4; ++i) {
                float4 p = *(const float4*)&Ps[(ty4 + i) * PAD + j0];
                acc[i][0] += p.x * v0.x + p.y * v1.x + p.z * v2.x + p.w * v3.x;
                acc[i][1] += p.x * v0.y + p.y * v1.y + p.z * v2.y + p.w * v3.y;
                acc[i][2] += p.x * v0.z + p.y * v1.z + p.z * v2.z + p.w * v3.z;
                acc[i][3] += p.x * v0.w + p.y * v1.w + p.z * v2.w + p.w * v3.w;
            }
        }
    }

    // normalize + write ctx [B,S,D] with D index = h*64 + dh
    const int b = bh >> 4, h = bh & 15;
#pragma unroll
    for (int i = 0; i < 4; ++i) {
        int srow = qb * QT + ty4 + i;
        float inv = 1.f / l_s[ty4 + i];
        float4 o;
        o.x = acc[i][0] * inv; o.y = acc[i][1] * inv;
        o.z = acc[i][2] * inv; o.w = acc[i][3] * inv;
        *(float4*)&ctx[((size_t)(b * SEQ + srow)) * Dh + h * HD + tx4] = o;
    }
}

// ---------------- launch ------------------------------------------------------
extern "C" void kernel_launch(void* const* d_in, const int* in_sizes, int n_in,
                              void* d_out, int out_size)
{
    const float* X  = (const float*)d_in[0];
    const float* Wq = (const float*)d_in[1];
    const float* bq = (const float*)d_in[2];
    const float* Wk = (const float*)d_in[3];
    const float* bk = (const float*)d_in[4];
    const float* Wv = (const float*)d_in[5];
    const float* bv = (const float*)d_in[6];
    const float* Wo = (const float*)d_in[7];
    const float* bo = (const float*)d_in[8];
    float* out = (float*)d_out;

    float *qp, *kp, *vp, *cp;
    cudaGetSymbolAddress((void**)&qp, g_q);
    cudaGetSymbolAddress((void**)&kp, g_k);
    cudaGetSymbolAddress((void**)&vp, g_v);
    cudaGetSymbolAddress((void**)&cp, g_ctx);

    const int attnSmem = (4 * 64 * PAD + 3 * 64) * (int)sizeof(float);  // 70400 B
    cudaFuncSetAttribute(attn_kernel, cudaFuncAttributeMaxDynamicSharedMemorySize, attnSmem);

    dim3 thr(256);
    dim3 gg(Dh / BN, MROWS / BM);       // (8, 64)
    sgemm_bias<<<gg, thr>>>(X, Wq, bq, qp, 1);
    sgemm_bias<<<gg, thr>>>(X, Wk, bk, kp, 1);
    sgemm_bias<<<gg, thr>>>(X, Wv, bv, vp, 1);

    dim3 ga(SEQ / QT, BATCH * NH);      // (32, 64)
    attn_kernel<<<ga, thr, attnSmem>>>(qp, kp, vp, cp);

    sgemm_bias<<<gg, thr>>>(cp, Wo, bo, out, 0);
}

// round 5
// speedup vs baseline: 1.2019x; 1.2019x over previous
#include <cuda_runtime.h>
#include <cstdint>
#include <math.h>

#define Dh     1024
#define NH     16
#define HD     64
#define SEQ    2048
#define BATCH  4
#define MROWS  8192   // BATCH*SEQ

// ---------------- scratch (static device globals; no allocation) -------------
__device__ float g_q[(size_t)BATCH * NH * SEQ * HD];   // [B,H,S,DH]
__device__ float g_k[(size_t)BATCH * NH * SEQ * HD];
__device__ float g_v[(size_t)BATCH * NH * SEQ * HD];
__device__ float g_ctx[(size_t)MROWS * Dh];            // [B,S,D]

// ======================= helpers =============================================
__device__ __forceinline__ uint32_t smem_u32(const void* p) {
    uint32_t a;
    asm("{ .reg .u64 t; cvta.to.shared.u64 t, %1; cvt.u32.u64 %0, t; }" : "=r"(a) : "l"(p));
    return a;
}
__device__ __forceinline__ uint32_t cvt_tf32(float x) {
    uint32_t u;
    asm("cvt.rna.tf32.f32 %0, %1;" : "=r"(u) : "f"(x));
    return u;
}
__device__ __forceinline__ void mma_tf32(float d[4],
                                         uint32_t a0, uint32_t a1, uint32_t a2, uint32_t a3,
                                         uint32_t b0, uint32_t b1) {
    asm volatile(
        "mma.sync.aligned.m16n8k8.row.col.f32.tf32.tf32.f32 "
        "{%0,%1,%2,%3}, {%4,%5,%6,%7}, {%8,%9}, {%0,%1,%2,%3};"
        : "+f"(d[0]), "+f"(d[1]), "+f"(d[2]), "+f"(d[3])
        : "r"(a0), "r"(a1), "r"(a2), "r"(a3), "r"(b0), "r"(b1));
}
#define CP_ASYNC16(dst_u32, src_ptr) \
    asm volatile("cp.async.ca.shared.global [%0], [%1], 16;" :: "r"(dst_u32), "l"(src_ptr))
#define CP_COMMIT() asm volatile("cp.async.commit_group;" ::: "memory")
#define CP_WAIT(n)  asm volatile("cp.async.wait_group %0;" :: "n"(n) : "memory")

// ================== TF32x3 mma.sync GEMM =====================================
// out[m,n] = sum_k A[m,k]*W[n,k] + bias[n];  M=8192, N=K=1024
// 128x128 tile, K-chunks of 32, cp.async double buffer, warp tile 32x64.
#define BKC       32
#define ASTRIDE   36                       // floats per smem row (32 + 4 pad)
#define STAGE_F   (128 * ASTRIDE)          // 4608 floats = 18432 B per matrix per stage
#define GEMM_SMEM (4 * STAGE_F * 4)        // 2 stages x (A + W) = 73728 B

__global__ __launch_bounds__(256) void gemm_mma(
    const float* __restrict__ A, const float* __restrict__ W,
    const float* __restrict__ bias, float* __restrict__ out, int headLayout)
{
    extern __shared__ float sm[];
    float* AsBase = sm;                    // [2][128][ASTRIDE]
    float* WsBase = sm + 2 * STAGE_F;

    const int tid   = threadIdx.x;
    const int lane  = tid & 31;
    const int wid   = tid >> 5;
    const int warpM = wid >> 1;            // 0..3 -> 32-row slice
    const int warpN = wid & 1;             // 0..1 -> 64-col slice
    const int m0 = blockIdx.y * 128;
    const int n0 = blockIdx.x * 128;

    const int gid = lane >> 2;             // groupID
    const int tig = lane & 3;              // threadID_in_group

    float d[2][8][4];
#pragma unroll
    for (int mt = 0; mt < 2; ++mt)
#pragma unroll
        for (int nt = 0; nt < 8; ++nt)
#pragma unroll
            for (int q = 0; q < 4; ++q) d[mt][nt][q] = 0.f;

    // per-thread cp.async mapping: 1024 16B-chunks per matrix per stage, 4 per thread
    const int cr = tid >> 1;               // unused helper replaced below
    (void)cr;

    const uint32_t asmem = smem_u32(AsBase);
    const uint32_t wsmem = smem_u32(WsBase);

    // issue chunk c into stage c&1
#define ISSUE(c) do {                                                            \
    const int stg = (c) & 1;                                                     \
    const uint32_t da = asmem + (uint32_t)stg * STAGE_F * 4;                     \
    const uint32_t dw = wsmem + (uint32_t)stg * STAGE_F * 4;                     \
    const float* srcA = A + (size_t)m0 * Dh + (c) * BKC;                         \
    const float* srcW = W + (size_t)n0 * Dh + (c) * BKC;                         \
    _Pragma("unroll")                                                            \
    for (int rep = 0; rep < 4; ++rep) {                                          \
        int idx = rep * 256 + tid;        /* 0..1023 */                          \
        int r = idx >> 3, q = idx & 7;                                           \
        CP_ASYNC16(da + (uint32_t)(r * ASTRIDE + q * 4) * 4, srcA + (size_t)r * Dh + q * 4); \
        CP_ASYNC16(dw + (uint32_t)(r * ASTRIDE + q * 4) * 4, srcW + (size_t)r * Dh + q * 4); \
    }                                                                            \
    CP_COMMIT();                                                                 \
} while (0)

    ISSUE(0);

    for (int c = 0; c < Dh / BKC; ++c) {
        if (c + 1 < Dh / BKC) { ISSUE(c + 1); CP_WAIT(1); }
        else                  { CP_WAIT(0); }
        __syncthreads();

        const float* as = AsBase + (c & 1) * STAGE_F;
        const float* ws = WsBase + (c & 1) * STAGE_F;

#pragma unroll
        for (int kk = 0; kk < 4; ++kk) {             // 4 k8-steps per chunk
            const int kb = kk * 8;
            // ---- A fragments (2 m16 tiles), split to high/low tf32 ----
            uint32_t ah[2][4], al[2][4];
#pragma unroll
            for (int mt = 0; mt < 2; ++mt) {
                const int mrow = warpM * 32 + mt * 16;
                float f0 = as[(mrow + gid)     * ASTRIDE + kb + tig];
                float f1 = as[(mrow + gid + 8) * ASTRIDE + kb + tig];
                float f2 = as[(mrow + gid)     * ASTRIDE + kb + tig + 4];
                float f3 = as[(mrow + gid + 8) * ASTRIDE + kb + tig + 4];
                ah[mt][0] = cvt_tf32(f0); al[mt][0] = cvt_tf32(f0 - __uint_as_float(ah[mt][0]));
                ah[mt][1] = cvt_tf32(f1); al[mt][1] = cvt_tf32(f1 - __uint_as_float(ah[mt][1]));
                ah[mt][2] = cvt_tf32(f2); al[mt][2] = cvt_tf32(f2 - __uint_as_float(ah[mt][2]));
                ah[mt][3] = cvt_tf32(f3); al[mt][3] = cvt_tf32(f3 - __uint_as_float(ah[mt][3]));
            }
            // ---- B fragments (8 n8 tiles) ----
#pragma unroll
            for (int nt = 0; nt < 8; ++nt) {
                const int nrow = warpN * 64 + nt * 8;
                float g0 = ws[(nrow + gid) * ASTRIDE + kb + tig];
                float g1 = ws[(nrow + gid) * ASTRIDE + kb + tig + 4];
                uint32_t bh0 = cvt_tf32(g0), bl0 = cvt_tf32(g0 - __uint_as_float(bh0));
                uint32_t bh1 = cvt_tf32(g1), bl1 = cvt_tf32(g1 - __uint_as_float(bh1));
#pragma unroll
                for (int mt = 0; mt < 2; ++mt) {
                    mma_tf32(d[mt][nt], ah[mt][0], ah[mt][1], ah[mt][2], ah[mt][3], bh0, bh1);
                    mma_tf32(d[mt][nt], ah[mt][0], ah[mt][1], ah[mt][2], ah[mt][3], bl0, bl1);
                    mma_tf32(d[mt][nt], al[mt][0], al[mt][1], al[mt][2], al[mt][3], bh0, bh1);
                }
            }
        }
        __syncthreads();
    }
#undef ISSUE

    // ---- epilogue: lane (gid,tig) owns rows {r, r+8}, col pair 2*tig ----
#pragma unroll
    for (int mt = 0; mt < 2; ++mt) {
        const int mrow = m0 + warpM * 32 + mt * 16 + gid;
#pragma unroll
        for (int nt = 0; nt < 8; ++nt) {
            const int ncol = n0 + warpN * 64 + nt * 8 + tig * 2;
            const float b0 = bias[ncol], b1 = bias[ncol + 1];
            float2 lo = make_float2(d[mt][nt][0] + b0, d[mt][nt][1] + b1);
            float2 hi = make_float2(d[mt][nt][2] + b0, d[mt][nt][3] + b1);
            if (headLayout) {
                const int h = ncol >> 6, dh0 = ncol & 63;
                {
                    const int m = mrow;
                    const int bb = m >> 11, s = m & 2047;
                    *(float2*)&out[(((size_t)(bb * NH + h) * SEQ + s) * HD) + dh0] = lo;
                }
                {
                    const int m = mrow + 8;
                    const int bb = m >> 11, s = m & 2047;
                    *(float2*)&out[(((size_t)(bb * NH + h) * SEQ + s) * HD) + dh0] = hi;
                }
            } else {
                *(float2*)&out[(size_t)mrow * Dh + ncol]       = lo;
                *(float2*)&out[(size_t)(mrow + 8) * Dh + ncol] = hi;
            }
        }
    }
}

// ---------------- Flash attention (fp32, online softmax) ---------------------
// grid: (SEQ/64, BATCH*NH), 256 threads
#define QT  64
#define PAD 68          // row stride in floats (keeps float4 alignment)

__global__ __launch_bounds__(256, 2) void attn_kernel(
    const float* __restrict__ Q, const float* __restrict__ K,
    const float* __restrict__ V, float* __restrict__ ctx)
{
    extern __shared__ float smf[];
    float* Qs  = smf;                   // [64][PAD]
    float* Ks  = Qs + 64 * PAD;
    float* Vs  = Ks + 64 * PAD;
    float* Ps  = Vs + 64 * PAD;
    float* m_s = Ps + 64 * PAD;         // [64]
    float* l_s = m_s + 64;              // [64]
    float* c_s = l_s + 64;              // [64]

    const int tid = threadIdx.x;
    const int qb  = blockIdx.x;
    const int bh  = blockIdx.y;

    const float* Qb = Q + ((size_t)bh * SEQ + (size_t)qb * QT) * HD;
    const float* Kb = K + (size_t)bh * SEQ * HD;
    const float* Vb = V + (size_t)bh * SEQ * HD;

    for (int i = tid; i < 64 * 16; i += 256) {
        int r = i >> 4, c4 = (i & 15) * 4;
        *(float4*)&Qs[r * PAD + c4] = *(const float4*)(Qb + r * HD + c4);
    }
    if (tid < 64) { m_s[tid] = -1e30f; l_s[tid] = 0.f; }

    const int ty = tid >> 4, tx = tid & 15;
    const int ty4 = ty * 4, tx4 = tx * 4;

    float acc[4][4];
#pragma unroll
    for (int i = 0; i < 4; ++i)
#pragma unroll
        for (int j = 0; j < 4; ++j) acc[i][j] = 0.f;

    for (int kt = 0; kt < SEQ / QT; ++kt) {
        __syncthreads();
        const float* Kt = Kb + (size_t)kt * QT * HD;
        const float* Vt = Vb + (size_t)kt * QT * HD;
        for (int i = tid; i < 64 * 16; i += 256) {
            int r = i >> 4, c4 = (i & 15) * 4;
            *(float4*)&Ks[r * PAD + c4] = *(const float4*)(Kt + r * HD + c4);
            *(float4*)&Vs[r * PAD + c4] = *(const float4*)(Vt + r * HD + c4);
        }
        __syncthreads();

        float sc[4][4];
#pragma unroll
        for (int i = 0; i < 4; ++i)
#pragma unroll
            for (int j = 0; j < 4; ++j) sc[i][j] = 0.f;

#pragma unroll 4
        for (int dloop = 0; dloop < HD; dloop += 4) {
            float4 q[4], k[4];
#pragma unroll
            for (int i = 0; i < 4; ++i) q[i] = *(const float4*)&Qs[(ty4 + i) * PAD + dloop];
#pragma unroll
            for (int j = 0; j < 4; ++j) k[j] = *(const float4*)&Ks[(tx4 + j) * PAD + dloop];
#pragma unroll
            for (int i = 0; i < 4; ++i)
#pragma unroll
                for (int j = 0; j < 4; ++j) {
                    sc[i][j] += q[i].x * k[j].x + q[i].y * k[j].y +
                                q[i].z * k[j].z + q[i].w * k[j].w;
                }
        }
#pragma unroll
        for (int i = 0; i < 4; ++i)
#pragma unroll
            for (int j = 0; j < 4; ++j)
                Ps[(ty4 + i) * PAD + tx4 + j] = sc[i][j] * 0.125f;
        __syncthreads();

        {
            const int row = tid >> 2, seg = tid & 3;
            float* prow = &Ps[row * PAD + seg * 16];
            float mloc = -1e30f;
#pragma unroll
            for (int c = 0; c < 16; ++c) mloc = fmaxf(mloc, prow[c]);
            mloc = fmaxf(mloc, __shfl_xor_sync(0xffffffffu, mloc, 1));
            mloc = fmaxf(mloc, __shfl_xor_sync(0xffffffffu, mloc, 2));
            float mold = m_s[row];
            float mnew = fmaxf(mold, mloc);
            float csc  = __expf(mold - mnew);
            float lsum = 0.f;
#pragma unroll
            for (int c = 0; c < 16; ++c) {
                float e = __expf(prow[c] - mnew);
                prow[c] = e;
                lsum += e;
            }
            lsum += __shfl_xor_sync(0xffffffffu, lsum, 1);
            lsum += __shfl_xor_sync(0xffffffffu, lsum, 2);
            if (seg == 0) {
                m_s[row] = mnew;
                c_s[row] = csc;
                l_s[row] = l_s[row] * csc + lsum;
            }
        }
        __syncthreads();

        float cf[4];
#pragma unroll
        for (int i = 0; i < 4; ++i) cf[i] = c_s[ty4 + i];
#pragma unroll
        for (int i = 0; i < 4; ++i)
#pragma unroll
            for (int j = 0; j < 4; ++j) acc[i][j] *= cf[i];

#pragma unroll 4
        for (int j0 = 0; j0 < QT; j0 += 4) {
            float4 v0 = *(const float4*)&Vs[(j0 + 0) * PAD + tx4];
            float4 v1 = *(const float4*)&Vs[(j0 + 1) * PAD + tx4];
            float4 v2 = *(const float4*)&Vs[(j0 + 2) * PAD + tx4];
            float4 v3 = *(const float4*)&Vs[(j0 + 3) * PAD + tx4];
#pragma unroll
            for (int i = 0; i < 4; ++i) {
                float4 p = *(const float4*)&Ps[(ty4 + i) * PAD + j0];
                acc[i][0] += p.x * v0.x + p.y * v1.x + p.z * v2.x + p.w * v3.x;
                acc[i][1] += p.x * v0.y + p.y * v1.y + p.z * v2.y + p.w * v3.y;
                acc[i][2] += p.x * v0.z + p.y * v1.z + p.z * v2.z + p.w * v3.z;
                acc[i][3] += p.x * v0.w + p.y * v1.w + p.z * v2.w + p.w * v3.w;
            }
        }
    }

    const int b = bh >> 4, h = bh & 15;
#pragma unroll
    for (int i = 0; i < 4; ++i) {
        int srow = qb * QT + ty4 + i;
        float inv = 1.f / l_s[ty4 + i];
        float4 o;
        o.x = acc[i][0] * inv; o.y = acc[i][1] * inv;
        o.z = acc[i][2] * inv; o.w = acc[i][3] * inv;
        *(float4*)&ctx[((size_t)(b * SEQ + srow)) * Dh + h * HD + tx4] = o;
    }
}

// ---------------- launch ------------------------------------------------------
extern "C" void kernel_launch(void* const* d_in, const int* in_sizes, int n_in,
                              void* d_out, int out_size)
{
    const float* X  = (const float*)d_in[0];
    const float* Wq = (const float*)d_in[1];
    const float* bq = (const float*)d_in[2];
    const float* Wk = (const float*)d_in[3];
    const float* bk = (const float*)d_in[4];
    const float* Wv = (const float*)d_in[5];
    const float* bv = (const float*)d_in[6];
    const float* Wo = (const float*)d_in[7];
    const float* bo = (const float*)d_in[8];
    float* out = (float*)d_out;

    float *qp, *kp, *vp, *cp;
    cudaGetSymbolAddress((void**)&qp, g_q);
    cudaGetSymbolAddress((void**)&kp, g_k);
    cudaGetSymbolAddress((void**)&vp, g_v);
    cudaGetSymbolAddress((void**)&cp, g_ctx);

    const int attnSmem = (4 * 64 * PAD + 3 * 64) * (int)sizeof(float);  // 70400 B
    cudaFuncSetAttribute(attn_kernel, cudaFuncAttributeMaxDynamicSharedMemorySize, attnSmem);
    cudaFuncSetAttribute(gemm_mma, cudaFuncAttributeMaxDynamicSharedMemorySize, GEMM_SMEM);

    dim3 thr(256);
    dim3 gg(Dh / 128, MROWS / 128);     // (8, 64)
    gemm_mma<<<gg, thr, GEMM_SMEM>>>(X, Wq, bq, qp, 1);
    gemm_mma<<<gg, thr, GEMM_SMEM>>>(X, Wk, bk, kp, 1);
    gemm_mma<<<gg, thr, GEMM_SMEM>>>(X, Wv, bv, vp, 1);

    dim3 ga(SEQ / QT, BATCH * NH);      // (32, 64)
    attn_kernel<<<ga, thr, attnSmem>>>(qp, kp, vp, cp);

    gemm_mma<<<gg, thr, GEMM_SMEM>>>(cp, Wo, bo, out, 0);
}

// round 6
// speedup vs baseline: 2.7201x; 2.2631x over previous
#include <cuda_runtime.h>
#include <cuda_bf16.h>
#include <cstdint>
#include <math.h>

#define Dh     1024
#define NH     16
#define HD     64
#define SEQ    2048
#define BATCH  4
#define MROWS  8192   // BATCH*SEQ

typedef __nv_bfloat16 bf16;

// ---------------- scratch (static device globals; no allocation) -------------
__device__ bf16  g_qh[(size_t)MROWS * Dh];   // [B,H,S,DH] (pre-scaled by 0.125)
__device__ bf16  g_ql[(size_t)MROWS * Dh];
__device__ bf16  g_kh[(size_t)MROWS * Dh];   // [B,H,S,DH]
__device__ bf16  g_kl[(size_t)MROWS * Dh];
__device__ bf16  g_vh[(size_t)MROWS * Dh];   // [B,H,DH,S]  (transposed)
__device__ bf16  g_vl[(size_t)MROWS * Dh];
__device__ float g_ctx[(size_t)MROWS * Dh];  // [B,S,D]

// ======================= helpers =============================================
__device__ __forceinline__ uint32_t smem_u32(const void* p) {
    uint32_t a;
    asm("{ .reg .u64 t; cvta.to.shared.u64 t, %1; cvt.u32.u64 %0, t; }" : "=r"(a) : "l"(p));
    return a;
}
__device__ __forceinline__ uint32_t cvt_tf32(float x) {
    uint32_t u;
    asm("cvt.rna.tf32.f32 %0, %1;" : "=r"(u) : "f"(x));
    return u;
}
__device__ __forceinline__ void mma_tf32(float d[4],
                                         uint32_t a0, uint32_t a1, uint32_t a2, uint32_t a3,
                                         uint32_t b0, uint32_t b1) {
    asm volatile(
        "mma.sync.aligned.m16n8k8.row.col.f32.tf32.tf32.f32 "
        "{%0,%1,%2,%3}, {%4,%5,%6,%7}, {%8,%9}, {%0,%1,%2,%3};"
        : "+f"(d[0]), "+f"(d[1]), "+f"(d[2]), "+f"(d[3])
        : "r"(a0), "r"(a1), "r"(a2), "r"(a3), "r"(b0), "r"(b1));
}
__device__ __forceinline__ void mma_bf16(float d[4],
                                         uint32_t a0, uint32_t a1, uint32_t a2, uint32_t a3,
                                         uint32_t b0, uint32_t b1) {
    asm volatile(
        "mma.sync.aligned.m16n8k16.row.col.f32.bf16.bf16.f32 "
        "{%0,%1,%2,%3}, {%4,%5,%6,%7}, {%8,%9}, {%0,%1,%2,%3};"
        : "+f"(d[0]), "+f"(d[1]), "+f"(d[2]), "+f"(d[3])
        : "r"(a0), "r"(a1), "r"(a2), "r"(a3), "r"(b0), "r"(b1));
}
// pack two f32 -> bf16x2 {hi=v1, lo=v0}, plus residual pack
__device__ __forceinline__ void split_pack(float v0, float v1, uint32_t& ph, uint32_t& pl) {
    asm("cvt.rn.bf16x2.f32 %0, %1, %2;" : "=r"(ph) : "f"(v1), "f"(v0));
    float lo = __uint_as_float(ph << 16);
    float hi = __uint_as_float(ph & 0xffff0000u);
    asm("cvt.rn.bf16x2.f32 %0, %1, %2;" : "=r"(pl) : "f"(v1 - hi), "f"(v0 - lo));
}
#define CP_ASYNC16(dst_u32, src_ptr) \
    asm volatile("cp.async.ca.shared.global [%0], [%1], 16;" :: "r"(dst_u32), "l"(src_ptr))
#define CP_COMMIT() asm volatile("cp.async.commit_group;" ::: "memory")
#define CP_WAIT(n)  asm volatile("cp.async.wait_group %0;" :: "n"(n) : "memory")

// ================== TF32x3 mma.sync GEMM =====================================
// out[m,n] = sum_k A[m,k]*W[n,k] + bias[n];  M=8192, N=K=1024
// mode 0: fp32 flat [M,1024] -> outF
// mode 1: bf16 split pair, head layout [B,H,S,DH] -> outH/outL
// mode 2: bf16 split pair, transposed  [B,H,DH,S] -> outH/outL
// mode 3: like mode 1 but scaled by 0.125 (Q)
#define BKC       32
#define ASTRIDE   36
#define STAGE_F   (128 * ASTRIDE)
#define GEMM_SMEM (4 * STAGE_F * 4)

__global__ __launch_bounds__(256) void gemm_mma(
    const float* __restrict__ A, const float* __restrict__ W,
    const float* __restrict__ bias, float* __restrict__ outF,
    bf16* __restrict__ outH, bf16* __restrict__ outL, int mode)
{
    extern __shared__ float sm[];
    float* AsBase = sm;
    float* WsBase = sm + 2 * STAGE_F;

    const int tid   = threadIdx.x;
    const int lane  = tid & 31;
    const int wid   = tid >> 5;
    const int warpM = wid >> 1;
    const int warpN = wid & 1;
    const int m0 = blockIdx.y * 128;
    const int n0 = blockIdx.x * 128;
    const int gid = lane >> 2;
    const int tig = lane & 3;

    float d[2][8][4];
#pragma unroll
    for (int mt = 0; mt < 2; ++mt)
#pragma unroll
        for (int nt = 0; nt < 8; ++nt)
#pragma unroll
            for (int q = 0; q < 4; ++q) d[mt][nt][q] = 0.f;

    const uint32_t asmem = smem_u32(AsBase);
    const uint32_t wsmem = smem_u32(WsBase);

#define ISSUE(c) do {                                                            \
    const int stg = (c) & 1;                                                     \
    const uint32_t da = asmem + (uint32_t)stg * STAGE_F * 4;                     \
    const uint32_t dw = wsmem + (uint32_t)stg * STAGE_F * 4;                     \
    const float* srcA = A + (size_t)m0 * Dh + (c) * BKC;                         \
    const float* srcW = W + (size_t)n0 * Dh + (c) * BKC;                         \
    _Pragma("unroll")                                                            \
    for (int rep = 0; rep < 4; ++rep) {                                          \
        int idx = rep * 256 + tid;                                               \
        int r = idx >> 3, q = idx & 7;                                           \
        CP_ASYNC16(da + (uint32_t)(r * ASTRIDE + q * 4) * 4, srcA + (size_t)r * Dh + q * 4); \
        CP_ASYNC16(dw + (uint32_t)(r * ASTRIDE + q * 4) * 4, srcW + (size_t)r * Dh + q * 4); \
    }                                                                            \
    CP_COMMIT();                                                                 \
} while (0)

    ISSUE(0);

    for (int c = 0; c < Dh / BKC; ++c) {
        if (c + 1 < Dh / BKC) { ISSUE(c + 1); CP_WAIT(1); }
        else                  { CP_WAIT(0); }
        __syncthreads();

        const float* as = AsBase + (c & 1) * STAGE_F;
        const float* ws = WsBase + (c & 1) * STAGE_F;

#pragma unroll
        for (int kk = 0; kk < 4; ++kk) {
            const int kb = kk * 8;
            uint32_t ah[2][4], al[2][4];
#pragma unroll
            for (int mt = 0; mt < 2; ++mt) {
                const int mrow = warpM * 32 + mt * 16;
                float f0 = as[(mrow + gid)     * ASTRIDE + kb + tig];
                float f1 = as[(mrow + gid + 8) * ASTRIDE + kb + tig];
                float f2 = as[(mrow + gid)     * ASTRIDE + kb + tig + 4];
                float f3 = as[(mrow + gid + 8) * ASTRIDE + kb + tig + 4];
                ah[mt][0] = cvt_tf32(f0); al[mt][0] = cvt_tf32(f0 - __uint_as_float(ah[mt][0]));
                ah[mt][1] = cvt_tf32(f1); al[mt][1] = cvt_tf32(f1 - __uint_as_float(ah[mt][1]));
                ah[mt][2] = cvt_tf32(f2); al[mt][2] = cvt_tf32(f2 - __uint_as_float(ah[mt][2]));
                ah[mt][3] = cvt_tf32(f3); al[mt][3] = cvt_tf32(f3 - __uint_as_float(ah[mt][3]));
            }
#pragma unroll
            for (int nt = 0; nt < 8; ++nt) {
                const int nrow = warpN * 64 + nt * 8;
                float g0 = ws[(nrow + gid) * ASTRIDE + kb + tig];
                float g1 = ws[(nrow + gid) * ASTRIDE + kb + tig + 4];
                uint32_t bh0 = cvt_tf32(g0), bl0 = cvt_tf32(g0 - __uint_as_float(bh0));
                uint32_t bh1 = cvt_tf32(g1), bl1 = cvt_tf32(g1 - __uint_as_float(bh1));
#pragma unroll
                for (int mt = 0; mt < 2; ++mt) {
                    mma_tf32(d[mt][nt], ah[mt][0], ah[mt][1], ah[mt][2], ah[mt][3], bh0, bh1);
                    mma_tf32(d[mt][nt], ah[mt][0], ah[mt][1], ah[mt][2], ah[mt][3], bl0, bl1);
                    mma_tf32(d[mt][nt], al[mt][0], al[mt][1], al[mt][2], al[mt][3], bh0, bh1);
                }
            }
        }
        __syncthreads();
    }
#undef ISSUE

    const float scl = (mode == 3) ? 0.125f : 1.f;
#pragma unroll
    for (int mt = 0; mt < 2; ++mt) {
        const int mrow = m0 + warpM * 32 + mt * 16 + gid;
#pragma unroll
        for (int nt = 0; nt < 8; ++nt) {
            const int ncol = n0 + warpN * 64 + nt * 8 + tig * 2;
            const float b0 = bias[ncol], b1 = bias[ncol + 1];
            if (mode == 0) {
                *(float2*)&outF[(size_t)mrow * Dh + ncol] =
                    make_float2(d[mt][nt][0] + b0, d[mt][nt][1] + b1);
                *(float2*)&outF[(size_t)(mrow + 8) * Dh + ncol] =
                    make_float2(d[mt][nt][2] + b0, d[mt][nt][3] + b1);
            } else if (mode == 2) {
                // transposed [B,H,DH,S]
                const int h = ncol >> 6, dh0 = ncol & 63;
#pragma unroll
                for (int rr = 0; rr < 2; ++rr) {
                    const int m = mrow + rr * 8;
                    const int bb = m >> 11, s = m & 2047;
                    float v0 = d[mt][nt][rr * 2 + 0] + b0;
                    float v1 = d[mt][nt][rr * 2 + 1] + b1;
                    size_t base = ((size_t)(bb * NH + h) * HD) * SEQ + s;
                    bf16 h0 = __float2bfloat16_rn(v0);
                    bf16 h1 = __float2bfloat16_rn(v1);
                    outH[base + (size_t)dh0 * SEQ]       = h0;
                    outH[base + (size_t)(dh0 + 1) * SEQ] = h1;
                    outL[base + (size_t)dh0 * SEQ]       = __float2bfloat16_rn(v0 - __bfloat162float(h0));
                    outL[base + (size_t)(dh0 + 1) * SEQ] = __float2bfloat16_rn(v1 - __bfloat162float(h1));
                }
            } else {
                // head layout [B,H,S,DH], optional scale
                const int h = ncol >> 6, dh0 = ncol & 63;
#pragma unroll
                for (int rr = 0; rr < 2; ++rr) {
                    const int m = mrow + rr * 8;
                    const int bb = m >> 11, s = m & 2047;
                    float v0 = (d[mt][nt][rr * 2 + 0] + b0) * scl;
                    float v1 = (d[mt][nt][rr * 2 + 1] + b1) * scl;
                    uint32_t ph, pl;
                    split_pack(v0, v1, ph, pl);
                    size_t off = ((size_t)(bb * NH + h) * SEQ + s) * HD + dh0;
                    *(uint32_t*)&outH[off] = ph;
                    *(uint32_t*)&outL[off] = pl;
                }
            }
        }
    }
}

// ================ bf16x3 flash attention (mma.sync) ==========================
// grid (SEQ/128, B*H), 256 threads (8 warps, each owns 16 q rows)
#define AT_STRIDE 72          // smem row stride in bf16 (64 + 8 pad)

__global__ __launch_bounds__(256, 2) void attn_mma(
    const bf16* __restrict__ Qh, const bf16* __restrict__ Ql,
    const bf16* __restrict__ Kh, const bf16* __restrict__ Kl,
    const bf16* __restrict__ Vh, const bf16* __restrict__ Vl,
    float* __restrict__ ctx)
{
    __shared__ bf16 smem[4 * 64 * AT_STRIDE];
    bf16* KH = smem;
    bf16* KL = smem + 64 * AT_STRIDE;
    bf16* VH = smem + 2 * 64 * AT_STRIDE;
    bf16* VL = smem + 3 * 64 * AT_STRIDE;

    const int tid  = threadIdx.x;
    const int lane = tid & 31;
    const int wid  = tid >> 5;
    const int gid  = lane >> 2;
    const int tig  = lane & 3;
    const int bh   = blockIdx.y;
    const int q0   = blockIdx.x * 128;
    const int wq   = q0 + wid * 16;

    // ---- Q fragments (registers, persistent) ----
    uint32_t qfh[4][4], qfl[4][4];
    {
        const bf16* bqh = Qh + ((size_t)bh * SEQ + wq) * HD;
        const bf16* bql = Ql + ((size_t)bh * SEQ + wq) * HD;
#pragma unroll
        for (int j = 0; j < 4; ++j) {
            int e0 = 16 * j + 2 * tig;
            qfh[j][0] = *(const uint32_t*)(bqh + (size_t)gid * HD + e0);
            qfh[j][1] = *(const uint32_t*)(bqh + (size_t)(gid + 8) * HD + e0);
            qfh[j][2] = *(const uint32_t*)(bqh + (size_t)gid * HD + e0 + 8);
            qfh[j][3] = *(const uint32_t*)(bqh + (size_t)(gid + 8) * HD + e0 + 8);
            qfl[j][0] = *(const uint32_t*)(bql + (size_t)gid * HD + e0);
            qfl[j][1] = *(const uint32_t*)(bql + (size_t)(gid + 8) * HD + e0);
            qfl[j][2] = *(const uint32_t*)(bql + (size_t)gid * HD + e0 + 8);
            qfl[j][3] = *(const uint32_t*)(bql + (size_t)(gid + 8) * HD + e0 + 8);
        }
    }

    float cx[8][4];
#pragma unroll
    for (int nt = 0; nt < 8; ++nt)
#pragma unroll
        for (int q = 0; q < 4; ++q) cx[nt][q] = 0.f;
    float m0 = -1e30f, m1 = -1e30f, l0 = 0.f, l1 = 0.f;

    const bf16* bkh = Kh + (size_t)bh * SEQ * HD;
    const bf16* bkl = Kl + (size_t)bh * SEQ * HD;
    const bf16* bvh = Vh + (size_t)bh * SEQ * HD;   // [DH][SEQ]
    const bf16* bvl = Vl + (size_t)bh * SEQ * HD;

    for (int kt = 0; kt < SEQ / 64; ++kt) {
        __syncthreads();
        // load K tile [64 keys][64 d] and Vt tile [64 d][64 keys]
        {
            const uint4* sKH = (const uint4*)(bkh + (size_t)kt * 64 * HD);
            const uint4* sKL = (const uint4*)(bkl + (size_t)kt * 64 * HD);
#pragma unroll
            for (int rep = 0; rep < 2; ++rep) {
                int chunk = tid * 2 + rep;             // 0..511
                int row = chunk >> 3, col8 = (chunk & 7) * 8;
                *(uint4*)&KH[row * AT_STRIDE + col8] = sKH[chunk];
                *(uint4*)&KL[row * AT_STRIDE + col8] = sKL[chunk];
                // V transposed in gmem: row = d, key offset kt*64
                const uint4* sVH = (const uint4*)(bvh + (size_t)row * SEQ + kt * 64);
                const uint4* sVL = (const uint4*)(bvl + (size_t)row * SEQ + kt * 64);
                *(uint4*)&VH[row * AT_STRIDE + col8] = sVH[col8 >> 3];
                *(uint4*)&VL[row * AT_STRIDE + col8] = sVL[col8 >> 3];
            }
        }
        __syncthreads();

        // ---- S = Q K^T (x3 split) ----
        float sacc[8][4];
#pragma unroll
        for (int nt = 0; nt < 8; ++nt)
#pragma unroll
            for (int q = 0; q < 4; ++q) sacc[nt][q] = 0.f;

#pragma unroll
        for (int j = 0; j < 4; ++j) {
            const int p0 = 2 * (tig + 8 * j);
            const int p1 = 2 * (tig + 4 + 8 * j);
#pragma unroll
            for (int nt = 0; nt < 8; ++nt) {
                const int krow = (8 * nt + gid) * AT_STRIDE;
                uint32_t kb0 = *(const uint32_t*)&KH[krow + p0];
                uint32_t kb1 = *(const uint32_t*)&KH[krow + p1];
                uint32_t kc0 = *(const uint32_t*)&KL[krow + p0];
                uint32_t kc1 = *(const uint32_t*)&KL[krow + p1];
                mma_bf16(sacc[nt], qfh[j][0], qfh[j][1], qfh[j][2], qfh[j][3], kb0, kb1);
                mma_bf16(sacc[nt], qfl[j][0], qfl[j][1], qfl[j][2], qfl[j][3], kb0, kb1);
                mma_bf16(sacc[nt], qfh[j][0], qfh[j][1], qfh[j][2], qfh[j][3], kc0, kc1);
            }
        }

        // ---- online softmax (per-warp, rows gid / gid+8) ----
        float mx0 = -1e30f, mx1 = -1e30f;
#pragma unroll
        for (int nt = 0; nt < 8; ++nt) {
            mx0 = fmaxf(mx0, fmaxf(sacc[nt][0], sacc[nt][1]));
            mx1 = fmaxf(mx1, fmaxf(sacc[nt][2], sacc[nt][3]));
        }
        mx0 = fmaxf(mx0, __shfl_xor_sync(0xffffffffu, mx0, 1));
        mx0 = fmaxf(mx0, __shfl_xor_sync(0xffffffffu, mx0, 2));
        mx1 = fmaxf(mx1, __shfl_xor_sync(0xffffffffu, mx1, 1));
        mx1 = fmaxf(mx1, __shfl_xor_sync(0xffffffffu, mx1, 2));
        float mn0 = fmaxf(m0, mx0), mn1 = fmaxf(m1, mx1);
        float r0 = __expf(m0 - mn0), r1 = __expf(m1 - mn1);
        m0 = mn0; m1 = mn1;

        float s0 = 0.f, s1 = 0.f;
#pragma unroll
        for (int nt = 0; nt < 8; ++nt) {
            float e0 = __expf(sacc[nt][0] - mn0);
            float e1 = __expf(sacc[nt][1] - mn0);
            float e2 = __expf(sacc[nt][2] - mn1);
            float e3 = __expf(sacc[nt][3] - mn1);
            sacc[nt][0] = e0; sacc[nt][1] = e1; sacc[nt][2] = e2; sacc[nt][3] = e3;
            s0 += e0 + e1; s1 += e2 + e3;
        }
        s0 += __shfl_xor_sync(0xffffffffu, s0, 1);
        s0 += __shfl_xor_sync(0xffffffffu, s0, 2);
        s1 += __shfl_xor_sync(0xffffffffu, s1, 1);
        s1 += __shfl_xor_sync(0xffffffffu, s1, 2);
        l0 = l0 * r0 + s0; l1 = l1 * r1 + s1;

#pragma unroll
        for (int nt = 0; nt < 8; ++nt) {
            cx[nt][0] *= r0; cx[nt][1] *= r0;
            cx[nt][2] *= r1; cx[nt][3] *= r1;
        }

        // ---- ctx += P V (x3 split); P packed from registers ----
#pragma unroll
        for (int j = 0; j < 4; ++j) {
            uint32_t pah[4], pal[4];
            split_pack(sacc[2*j][0],   sacc[2*j][1],   pah[0], pal[0]);
            split_pack(sacc[2*j][2],   sacc[2*j][3],   pah[1], pal[1]);
            split_pack(sacc[2*j+1][0], sacc[2*j+1][1], pah[2], pal[2]);
            split_pack(sacc[2*j+1][2], sacc[2*j+1][3], pah[3], pal[3]);
            const int p0 = 2 * (tig + 8 * j);
            const int p1 = 2 * (tig + 4 + 8 * j);
#pragma unroll
            for (int nt = 0; nt < 8; ++nt) {
                const int vrow = (8 * nt + gid) * AT_STRIDE;
                uint32_t vb0 = *(const uint32_t*)&VH[vrow + p0];
                uint32_t vb1 = *(const uint32_t*)&VH[vrow + p1];
                uint32_t vc0 = *(const uint32_t*)&VL[vrow + p0];
                uint32_t vc1 = *(const uint32_t*)&VL[vrow + p1];
                mma_bf16(cx[nt], pah[0], pah[1], pah[2], pah[3], vb0, vb1);
                mma_bf16(cx[nt], pal[0], pal[1], pal[2], pal[3], vb0, vb1);
                mma_bf16(cx[nt], pah[0], pah[1], pah[2], pah[3], vc0, vc1);
            }
        }
    }

    // ---- epilogue: ctx [B,S,D] fp32 ----
    const int b = bh >> 4, h = bh & 15;
    const float inv0 = 1.f / l0, inv1 = 1.f / l1;
    const int row0 = wq + gid, row1 = wq + gid + 8;
#pragma unroll
    for (int nt = 0; nt < 8; ++nt) {
        const int dcol = h * HD + 8 * nt + 2 * tig;
        *(float2*)&ctx[(size_t)(b * SEQ + row0) * Dh + dcol] =
            make_float2(cx[nt][0] * inv0, cx[nt][1] * inv0);
        *(float2*)&ctx[(size_t)(b * SEQ + row1) * Dh + dcol] =
            make_float2(cx[nt][2] * inv1, cx[nt][3] * inv1);
    }
}

// ---------------- launch ------------------------------------------------------
extern "C" void kernel_launch(void* const* d_in, const int* in_sizes, int n_in,
                              void* d_out, int out_size)
{
    const float* X  = (const float*)d_in[0];
    const float* Wq = (const float*)d_in[1];
    const float* bq = (const float*)d_in[2];
    const float* Wk = (const float*)d_in[3];
    const float* bk = (const float*)d_in[4];
    const float* Wv = (const float*)d_in[5];
    const float* bv = (const float*)d_in[6];
    const float* Wo = (const float*)d_in[7];
    const float* bo = (const float*)d_in[8];
    float* out = (float*)d_out;

    bf16 *qh, *ql, *kh, *kl, *vh, *vl;
    float* cp;
    cudaGetSymbolAddress((void**)&qh, g_qh);
    cudaGetSymbolAddress((void**)&ql, g_ql);
    cudaGetSymbolAddress((void**)&kh, g_kh);
    cudaGetSymbolAddress((void**)&kl, g_kl);
    cudaGetSymbolAddress((void**)&vh, g_vh);
    cudaGetSymbolAddress((void**)&vl, g_vl);
    cudaGetSymbolAddress((void**)&cp, g_ctx);

    cudaFuncSetAttribute(gemm_mma, cudaFuncAttributeMaxDynamicSharedMemorySize, GEMM_SMEM);

    dim3 thr(256);
    dim3 gg(Dh / 128, MROWS / 128);     // (8, 64)
    gemm_mma<<<gg, thr, GEMM_SMEM>>>(X, Wq, bq, nullptr, qh, ql, 3);
    gemm_mma<<<gg, thr, GEMM_SMEM>>>(X, Wk, bk, nullptr, kh, kl, 1);
    gemm_mma<<<gg, thr, GEMM_SMEM>>>(X, Wv, bv, nullptr, vh, vl, 2);

    dim3 ga(SEQ / 128, BATCH * NH);     // (16, 64)
    attn_mma<<<ga, thr>>>(qh, ql, kh, kl, vh, vl, cp);

    gemm_mma<<<gg, thr, GEMM_SMEM>>>(cp, Wo, bo, out, nullptr, nullptr, 0);
}

// round 7
// speedup vs baseline: 3.8380x; 1.4110x over previous
#include <cuda_runtime.h>
#include <cuda_bf16.h>
#include <cstdint>
#include <math.h>

#define Dh     1024
#define NH     16
#define HD     64
#define SEQ    2048
#define BATCH  4
#define MROWS  8192   // BATCH*SEQ

typedef __nv_bfloat16 bf16;

// ---------------- scratch (static device globals; no allocation) -------------
__device__ bf16  g_xh[(size_t)MROWS * Dh];   // X split [M,1024]
__device__ bf16  g_xl[(size_t)MROWS * Dh];
__device__ bf16  g_wqh[(size_t)Dh * Dh], g_wql[(size_t)Dh * Dh];
__device__ bf16  g_wkh[(size_t)Dh * Dh], g_wkl[(size_t)Dh * Dh];
__device__ bf16  g_wvh[(size_t)Dh * Dh], g_wvl[(size_t)Dh * Dh];
__device__ bf16  g_woh[(size_t)Dh * Dh], g_wol[(size_t)Dh * Dh];
__device__ bf16  g_qh[(size_t)MROWS * Dh];   // [B,H,S,DH] (pre-scaled by 0.125)
__device__ bf16  g_ql[(size_t)MROWS * Dh];
__device__ bf16  g_kh[(size_t)MROWS * Dh];   // [B,H,S,DH]
__device__ bf16  g_kl[(size_t)MROWS * Dh];
__device__ bf16  g_vh[(size_t)MROWS * Dh];   // [B,H,DH,S]  (transposed)
__device__ bf16  g_vl[(size_t)MROWS * Dh];
__device__ bf16  g_cxh[(size_t)MROWS * Dh];  // ctx split [M,1024]
__device__ bf16  g_cxl[(size_t)MROWS * Dh];

// ======================= helpers =============================================
__device__ __forceinline__ uint32_t smem_u32(const void* p) {
    uint32_t a;
    asm("{ .reg .u64 t; cvta.to.shared.u64 t, %1; cvt.u32.u64 %0, t; }" : "=r"(a) : "l"(p));
    return a;
}
__device__ __forceinline__ void mma_bf16(float d[4],
                                         uint32_t a0, uint32_t a1, uint32_t a2, uint32_t a3,
                                         uint32_t b0, uint32_t b1) {
    asm volatile(
        "mma.sync.aligned.m16n8k16.row.col.f32.bf16.bf16.f32 "
        "{%0,%1,%2,%3}, {%4,%5,%6,%7}, {%8,%9}, {%0,%1,%2,%3};"
        : "+f"(d[0]), "+f"(d[1]), "+f"(d[2]), "+f"(d[3])
        : "r"(a0), "r"(a1), "r"(a2), "r"(a3), "r"(b0), "r"(b1));
}
// pack two f32 -> bf16x2 {hi=v1, lo=v0}, plus residual pack
__device__ __forceinline__ void split_pack(float v0, float v1, uint32_t& ph, uint32_t& pl) {
    asm("cvt.rn.bf16x2.f32 %0, %1, %2;" : "=r"(ph) : "f"(v1), "f"(v0));
    float lo = __uint_as_float(ph << 16);
    float hi = __uint_as_float(ph & 0xffff0000u);
    asm("cvt.rn.bf16x2.f32 %0, %1, %2;" : "=r"(pl) : "f"(v1 - hi), "f"(v0 - lo));
}
#define CP_ASYNC16(dst_u32, src_ptr) \
    asm volatile("cp.async.ca.shared.global [%0], [%1], 16;" :: "r"(dst_u32), "l"(src_ptr))
#define CP_COMMIT() asm volatile("cp.async.commit_group;" ::: "memory")
#define CP_WAIT(n)  asm volatile("cp.async.wait_group %0;" :: "n"(n) : "memory")

// ================== fp32 -> bf16 (hi,lo) split ================================
__global__ __launch_bounds__(256) void split2(const float* __restrict__ in,
                                              bf16* __restrict__ hi, bf16* __restrict__ lo,
                                              int n4)
{
    int i = blockIdx.x * 256 + threadIdx.x;
    if (i >= n4) return;
    float4 v = ((const float4*)in)[i];
    uint32_t ph0, pl0, ph1, pl1;
    split_pack(v.x, v.y, ph0, pl0);
    split_pack(v.z, v.w, ph1, pl1);
    *(uint2*)&hi[(size_t)i * 4] = make_uint2(ph0, ph1);
    *(uint2*)&lo[(size_t)i * 4] = make_uint2(pl0, pl1);
}

// ================== bf16x3 mma.sync GEMM =====================================
// out[m,n] = sum_k A[m,k]*W[n,k] + bias[n];  M=8192, N=K=1024
// A,W given as bf16 (hi,lo) pairs. 128x128 tile, BK=32, cp.async double buffer.
// mode 0: fp32 flat [M,1024] -> outF
// mode 1: bf16 split pair, head layout [B,H,S,DH] -> outH/outL
// mode 2: bf16 split pair, transposed  [B,H,DH,S] -> outH/outL
// mode 3: like mode 1 but scaled by 0.125 (Q)
#define AS        40                       // smem row stride in bf16 (32 + 8 pad)
#define MSTG      (128 * AS)               // 5120 bf16 per matrix per stage
#define STG_SPAN  (4 * MSTG)               // AH,AL,WH,WL = 20480 bf16
#define GEMM_SMEM (2 * STG_SPAN * 2)       // 81920 bytes

__global__ __launch_bounds__(256) void gemm_bf16x3(
    const bf16* __restrict__ Ah, const bf16* __restrict__ Al,
    const bf16* __restrict__ Wh, const bf16* __restrict__ Wl,
    const float* __restrict__ bias, float* __restrict__ outF,
    bf16* __restrict__ outH, bf16* __restrict__ outL, int mode)
{
    extern __shared__ bf16 sb[];

    const int tid   = threadIdx.x;
    const int lane  = tid & 31;
    const int wid   = tid >> 5;
    const int warpM = wid >> 1;            // 0..3 -> 32-row slice
    const int warpN = wid & 1;             // 0..1 -> 64-col slice
    const int m0 = blockIdx.y * 128;
    const int n0 = blockIdx.x * 128;
    const int gid = lane >> 2;
    const int tig = lane & 3;

    float d[2][8][4];
#pragma unroll
    for (int mt = 0; mt < 2; ++mt)
#pragma unroll
        for (int nt = 0; nt < 8; ++nt)
#pragma unroll
            for (int q = 0; q < 4; ++q) d[mt][nt][q] = 0.f;

    const uint32_t sbu = smem_u32(sb);

#define ISSUE(c) do {                                                              \
    const int stg = (c) & 1;                                                       \
    const uint32_t ob = sbu + (uint32_t)stg * STG_SPAN * 2;                        \
    const bf16* sAh = Ah + (size_t)m0 * Dh + (c) * 32;                             \
    const bf16* sAl = Al + (size_t)m0 * Dh + (c) * 32;                             \
    const bf16* sWh = Wh + (size_t)n0 * Dh + (c) * 32;                             \
    const bf16* sWl = Wl + (size_t)n0 * Dh + (c) * 32;                             \
    _Pragma("unroll")                                                              \
    for (int rep = 0; rep < 2; ++rep) {                                            \
        int idx = rep * 256 + tid;         /* 0..511 */                            \
        int r = idx >> 2, c8 = (idx & 3) * 8;                                      \
        uint32_t doff = (uint32_t)(r * AS + c8) * 2;                               \
        CP_ASYNC16(ob + doff,                sAh + (size_t)r * Dh + c8);           \
        CP_ASYNC16(ob + MSTG * 2 + doff,     sAl + (size_t)r * Dh + c8);           \
        CP_ASYNC16(ob + 2 * MSTG * 2 + doff, sWh + (size_t)r * Dh + c8);           \
        CP_ASYNC16(ob + 3 * MSTG * 2 + doff, sWl + (size_t)r * Dh + c8);           \
    }                                                                              \
    CP_COMMIT();                                                                   \
} while (0)

    ISSUE(0);

    for (int c = 0; c < Dh / 32; ++c) {
        if (c + 1 < Dh / 32) { ISSUE(c + 1); CP_WAIT(1); }
        else                 { CP_WAIT(0); }
        __syncthreads();

        const bf16* aH = sb + (c & 1) * STG_SPAN;
        const bf16* aL = aH + MSTG;
        const bf16* wH = aH + 2 * MSTG;
        const bf16* wL = aH + 3 * MSTG;

#pragma unroll
        for (int kk = 0; kk < 2; ++kk) {             // 2 k16-steps per chunk
            const int kb = kk * 16;
            const int p0 = kb + 2 * tig;
            const int p1 = kb + 2 * tig + 8;

            uint32_t ah[2][4], al[2][4];
#pragma unroll
            for (int mt = 0; mt < 2; ++mt) {
                const int r0 = (warpM * 32 + mt * 16 + gid) * AS;
                const int r1 = r0 + 8 * AS;
                ah[mt][0] = *(const uint32_t*)&aH[r0 + p0];
                ah[mt][1] = *(const uint32_t*)&aH[r1 + p0];
                ah[mt][2] = *(const uint32_t*)&aH[r0 + p1];
                ah[mt][3] = *(const uint32_t*)&aH[r1 + p1];
                al[mt][0] = *(const uint32_t*)&aL[r0 + p0];
                al[mt][1] = *(const uint32_t*)&aL[r1 + p0];
                al[mt][2] = *(const uint32_t*)&aL[r0 + p1];
                al[mt][3] = *(const uint32_t*)&aL[r1 + p1];
            }
#pragma unroll
            for (int nt = 0; nt < 8; ++nt) {
                const int nr = (warpN * 64 + nt * 8 + gid) * AS;
                uint32_t bh0 = *(const uint32_t*)&wH[nr + p0];
                uint32_t bh1 = *(const uint32_t*)&wH[nr + p1];
                uint32_t bl0 = *(const uint32_t*)&wL[nr + p0];
                uint32_t bl1 = *(const uint32_t*)&wL[nr + p1];
#pragma unroll
                for (int mt = 0; mt < 2; ++mt) {
                    mma_bf16(d[mt][nt], ah[mt][0], ah[mt][1], ah[mt][2], ah[mt][3], bh0, bh1);
                    mma_bf16(d[mt][nt], al[mt][0], al[mt][1], al[mt][2], al[mt][3], bh0, bh1);
                    mma_bf16(d[mt][nt], ah[mt][0], ah[mt][1], ah[mt][2], ah[mt][3], bl0, bl1);
                }
            }
        }
        __syncthreads();
    }
#undef ISSUE

    const float scl = (mode == 3) ? 0.125f : 1.f;
#pragma unroll
    for (int mt = 0; mt < 2; ++mt) {
        const int mrow = m0 + warpM * 32 + mt * 16 + gid;
#pragma unroll
        for (int nt = 0; nt < 8; ++nt) {
            const int ncol = n0 + warpN * 64 + nt * 8 + tig * 2;
            const float b0 = bias[ncol], b1 = bias[ncol + 1];
            if (mode == 0) {
                *(float2*)&outF[(size_t)mrow * Dh + ncol] =
                    make_float2(d[mt][nt][0] + b0, d[mt][nt][1] + b1);
                *(float2*)&outF[(size_t)(mrow + 8) * Dh + ncol] =
                    make_float2(d[mt][nt][2] + b0, d[mt][nt][3] + b1);
            } else if (mode == 2) {
                // transposed [B,H,DH,S]
                const int h = ncol >> 6, dh0 = ncol & 63;
#pragma unroll
                for (int rr = 0; rr < 2; ++rr) {
                    const int m = mrow + rr * 8;
                    const int bb = m >> 11, s = m & 2047;
                    float v0 = d[mt][nt][rr * 2 + 0] + b0;
                    float v1 = d[mt][nt][rr * 2 + 1] + b1;
                    size_t base = ((size_t)(bb * NH + h) * HD) * SEQ + s;
                    bf16 h0 = __float2bfloat16_rn(v0);
                    bf16 h1 = __float2bfloat16_rn(v1);
                    outH[base + (size_t)dh0 * SEQ]       = h0;
                    outH[base + (size_t)(dh0 + 1) * SEQ] = h1;
                    outL[base + (size_t)dh0 * SEQ]       = __float2bfloat16_rn(v0 - __bfloat162float(h0));
                    outL[base + (size_t)(dh0 + 1) * SEQ] = __float2bfloat16_rn(v1 - __bfloat162float(h1));
                }
            } else {
                // head layout [B,H,S,DH], optional scale
                const int h = ncol >> 6, dh0 = ncol & 63;
#pragma unroll
                for (int rr = 0; rr < 2; ++rr) {
                    const int m = mrow + rr * 8;
                    const int bb = m >> 11, s = m & 2047;
                    float v0 = (d[mt][nt][rr * 2 + 0] + b0) * scl;
                    float v1 = (d[mt][nt][rr * 2 + 1] + b1) * scl;
                    uint32_t ph, pl;
                    split_pack(v0, v1, ph, pl);
                    size_t off = ((size_t)(bb * NH + h) * SEQ + s) * HD + dh0;
                    *(uint32_t*)&outH[off] = ph;
                    *(uint32_t*)&outL[off] = pl;
                }
            }
        }
    }
}

// ================ bf16x3 flash attention (mma.sync) ==========================
// grid (SEQ/128, B*H), 256 threads (8 warps, each owns 16 q rows)
#define AT_STRIDE 72          // smem row stride in bf16 (64 + 8 pad)

__global__ __launch_bounds__(256, 2) void attn_mma(
    const bf16* __restrict__ Qh, const bf16* __restrict__ Ql,
    const bf16* __restrict__ Kh, const bf16* __restrict__ Kl,
    const bf16* __restrict__ Vh, const bf16* __restrict__ Vl,
    bf16* __restrict__ ctxh, bf16* __restrict__ ctxl)
{
    __shared__ bf16 smem[4 * 64 * AT_STRIDE];
    bf16* KH = smem;
    bf16* KL = smem + 64 * AT_STRIDE;
    bf16* VH = smem + 2 * 64 * AT_STRIDE;
    bf16* VL = smem + 3 * 64 * AT_STRIDE;

    const int tid  = threadIdx.x;
    const int lane = tid & 31;
    const int wid  = tid >> 5;
    const int gid  = lane >> 2;
    const int tig  = lane & 3;
    const int bh   = blockIdx.y;
    const int q0   = blockIdx.x * 128;
    const int wq   = q0 + wid * 16;

    uint32_t qfh[4][4], qfl[4][4];
    {
        const bf16* bqh = Qh + ((size_t)bh * SEQ + wq) * HD;
        const bf16* bql = Ql + ((size_t)bh * SEQ + wq) * HD;
#pragma unroll
        for (int j = 0; j < 4; ++j) {
            int e0 = 16 * j + 2 * tig;
            qfh[j][0] = *(const uint32_t*)(bqh + (size_t)gid * HD + e0);
            qfh[j][1] = *(const uint32_t*)(bqh + (size_t)(gid + 8) * HD + e0);
            qfh[j][2] = *(const uint32_t*)(bqh + (size_t)gid * HD + e0 + 8);
            qfh[j][3] = *(const uint32_t*)(bqh + (size_t)(gid + 8) * HD + e0 + 8);
            qfl[j][0] = *(const uint32_t*)(bql + (size_t)gid * HD + e0);
            qfl[j][1] = *(const uint32_t*)(bql + (size_t)(gid + 8) * HD + e0);
            qfl[j][2] = *(const uint32_t*)(bql + (size_t)gid * HD + e0 + 8);
            qfl[j][3] = *(const uint32_t*)(bql + (size_t)(gid + 8) * HD + e0 + 8);
        }
    }

    float cx[8][4];
#pragma unroll
    for (int nt = 0; nt < 8; ++nt)
#pragma unroll
        for (int q = 0; q < 4; ++q) cx[nt][q] = 0.f;
    float m0 = -1e30f, m1 = -1e30f, l0 = 0.f, l1 = 0.f;

    const bf16* bkh = Kh + (size_t)bh * SEQ * HD;
    const bf16* bkl = Kl + (size_t)bh * SEQ * HD;
    const bf16* bvh = Vh + (size_t)bh * SEQ * HD;   // [DH][SEQ]
    const bf16* bvl = Vl + (size_t)bh * SEQ * HD;

    for (int kt = 0; kt < SEQ / 64; ++kt) {
        __syncthreads();
        {
            const uint4* sKH = (const uint4*)(bkh + (size_t)kt * 64 * HD);
            const uint4* sKL = (const uint4*)(bkl + (size_t)kt * 64 * HD);
#pragma unroll
            for (int rep = 0; rep < 2; ++rep) {
                int chunk = tid * 2 + rep;             // 0..511
                int row = chunk >> 3, col8 = (chunk & 7) * 8;
                *(uint4*)&KH[row * AT_STRIDE + col8] = sKH[chunk];
                *(uint4*)&KL[row * AT_STRIDE + col8] = sKL[chunk];
                const uint4* sVH = (const uint4*)(bvh + (size_t)row * SEQ + kt * 64);
                const uint4* sVL = (const uint4*)(bvl + (size_t)row * SEQ + kt * 64);
                *(uint4*)&VH[row * AT_STRIDE + col8] = sVH[col8 >> 3];
                *(uint4*)&VL[row * AT_STRIDE + col8] = sVL[col8 >> 3];
            }
        }
        __syncthreads();

        float sacc[8][4];
#pragma unroll
        for (int nt = 0; nt < 8; ++nt)
#pragma unroll
            for (int q = 0; q < 4; ++q) sacc[nt][q] = 0.f;

#pragma unroll
        for (int j = 0; j < 4; ++j) {
            const int p0 = 2 * (tig + 8 * j);
            const int p1 = 2 * (tig + 4 + 8 * j);
#pragma unroll
            for (int nt = 0; nt < 8; ++nt) {
                const int krow = (8 * nt + gid) * AT_STRIDE;
                uint32_t kb0 = *(const uint32_t*)&KH[krow + p0];
                uint32_t kb1 = *(const uint32_t*)&KH[krow + p1];
                uint32_t kc0 = *(const uint32_t*)&KL[krow + p0];
                uint32_t kc1 = *(const uint32_t*)&KL[krow + p1];
                mma_bf16(sacc[nt], qfh[j][0], qfh[j][1], qfh[j][2], qfh[j][3], kb0, kb1);
                mma_bf16(sacc[nt], qfl[j][0], qfl[j][1], qfl[j][2], qfl[j][3], kb0, kb1);
                mma_bf16(sacc[nt], qfh[j][0], qfh[j][1], qfh[j][2], qfh[j][3], kc0, kc1);
            }
        }

        float mx0 = -1e30f, mx1 = -1e30f;
#pragma unroll
        for (int nt = 0; nt < 8; ++nt) {
            mx0 = fmaxf(mx0, fmaxf(sacc[nt][0], sacc[nt][1]));
            mx1 = fmaxf(mx1, fmaxf(sacc[nt][2], sacc[nt][3]));
        }
        mx0 = fmaxf(mx0, __shfl_xor_sync(0xffffffffu, mx0, 1));
        mx0 = fmaxf(mx0, __shfl_xor_sync(0xffffffffu, mx0, 2));
        mx1 = fmaxf(mx1, __shfl_xor_sync(0xffffffffu, mx1, 1));
        mx1 = fmaxf(mx1, __shfl_xor_sync(0xffffffffu, mx1, 2));
        float mn0 = fmaxf(m0, mx0), mn1 = fmaxf(m1, mx1);
        float r0 = __expf(m0 - mn0), r1 = __expf(m1 - mn1);
        m0 = mn0; m1 = mn1;

        float s0 = 0.f, s1 = 0.f;
#pragma unroll
        for (int nt = 0; nt < 8; ++nt) {
            float e0 = __expf(sacc[nt][0] - mn0);
            float e1 = __expf(sacc[nt][1] - mn0);
            float e2 = __expf(sacc[nt][2] - mn1);
            float e3 = __expf(sacc[nt][3] - mn1);
            sacc[nt][0] = e0; sacc[nt][1] = e1; sacc[nt][2] = e2; sacc[nt][3] = e3;
            s0 += e0 + e1; s1 += e2 + e3;
        }
        s0 += __shfl_xor_sync(0xffffffffu, s0, 1);
        s0 += __shfl_xor_sync(0xffffffffu, s0, 2);
        s1 += __shfl_xor_sync(0xffffffffu, s1, 1);
        s1 += __shfl_xor_sync(0xffffffffu, s1, 2);
        l0 = l0 * r0 + s0; l1 = l1 * r1 + s1;

#pragma unroll
        for (int nt = 0; nt < 8; ++nt) {
            cx[nt][0] *= r0; cx[nt][1] *= r0;
            cx[nt][2] *= r1; cx[nt][3] *= r1;
        }

#pragma unroll
        for (int j = 0; j < 4; ++j) {
            uint32_t pah[4], pal[4];
            split_pack(sacc[2*j][0],   sacc[2*j][1],   pah[0], pal[0]);
            split_pack(sacc[2*j][2],   sacc[2*j][3],   pah[1], pal[1]);
            split_pack(sacc[2*j+1][0], sacc[2*j+1][1], pah[2], pal[2]);
            split_pack(sacc[2*j+1][2], sacc[2*j+1][3], pah[3], pal[3]);
            const int p0 = 2 * (tig + 8 * j);
            const int p1 = 2 * (tig + 4 + 8 * j);
#pragma unroll
            for (int nt = 0; nt < 8; ++nt) {
                const int vrow = (8 * nt + gid) * AT_STRIDE;
                uint32_t vb0 = *(const uint32_t*)&VH[vrow + p0];
                uint32_t vb1 = *(const uint32_t*)&VH[vrow + p1];
                uint32_t vc0 = *(const uint32_t*)&VL[vrow + p0];
                uint32_t vc1 = *(const uint32_t*)&VL[vrow + p1];
                mma_bf16(cx[nt], pah[0], pah[1], pah[2], pah[3], vb0, vb1);
                mma_bf16(cx[nt], pal[0], pal[1], pal[2], pal[3], vb0, vb1);
                mma_bf16(cx[nt], pah[0], pah[1], pah[2], pah[3], vc0, vc1);
            }
        }
    }

    // ---- epilogue: ctx split to bf16 (hi,lo), flat [M,1024] ----
    const int b = bh >> 4, h = bh & 15;
    const float inv0 = 1.f / l0, inv1 = 1.f / l1;
    const int row0 = wq + gid, row1 = wq + gid + 8;
#pragma unroll
    for (int nt = 0; nt < 8; ++nt) {
        const int dcol = h * HD + 8 * nt + 2 * tig;
        uint32_t ph, pl;
        split_pack(cx[nt][0] * inv0, cx[nt][1] * inv0, ph, pl);
        size_t o0 = (size_t)(b * SEQ + row0) * Dh + dcol;
        *(uint32_t*)&ctxh[o0] = ph;
        *(uint32_t*)&ctxl[o0] = pl;
        split_pack(cx[nt][2] * inv1, cx[nt][3] * inv1, ph, pl);
        size_t o1 = (size_t)(b * SEQ + row1) * Dh + dcol;
        *(uint32_t*)&ctxh[o1] = ph;
        *(uint32_t*)&ctxl[o1] = pl;
    }
}

// ---------------- launch ------------------------------------------------------
extern "C" void kernel_launch(void* const* d_in, const int* in_sizes, int n_in,
                              void* d_out, int out_size)
{
    const float* X  = (const float*)d_in[0];
    const float* Wq = (const float*)d_in[1];
    const float* bq = (const float*)d_in[2];
    const float* Wk = (const float*)d_in[3];
    const float* bk = (const float*)d_in[4];
    const float* Wv = (const float*)d_in[5];
    const float* bv = (const float*)d_in[6];
    const float* Wo = (const float*)d_in[7];
    const float* bo = (const float*)d_in[8];
    float* out = (float*)d_out;

    bf16 *xh, *xl, *wqh, *wql, *wkh, *wkl, *wvh, *wvl, *woh, *wol;
    bf16 *qh, *ql, *kh, *kl, *vh, *vl, *cxh, *cxl;
    cudaGetSymbolAddress((void**)&xh,  g_xh);  cudaGetSymbolAddress((void**)&xl,  g_xl);
    cudaGetSymbolAddress((void**)&wqh, g_wqh); cudaGetSymbolAddress((void**)&wql, g_wql);
    cudaGetSymbolAddress((void**)&wkh, g_wkh); cudaGetSymbolAddress((void**)&wkl, g_wkl);
    cudaGetSymbolAddress((void**)&wvh, g_wvh); cudaGetSymbolAddress((void**)&wvl, g_wvl);
    cudaGetSymbolAddress((void**)&woh, g_woh); cudaGetSymbolAddress((void**)&wol, g_wol);
    cudaGetSymbolAddress((void**)&qh,  g_qh);  cudaGetSymbolAddress((void**)&ql,  g_ql);
    cudaGetSymbolAddress((void**)&kh,  g_kh);  cudaGetSymbolAddress((void**)&kl,  g_kl);
    cudaGetSymbolAddress((void**)&vh,  g_vh);  cudaGetSymbolAddress((void**)&vl,  g_vl);
    cudaGetSymbolAddress((void**)&cxh, g_cxh); cudaGetSymbolAddress((void**)&cxl, g_cxl);

    cudaFuncSetAttribute(gemm_bf16x3, cudaFuncAttributeMaxDynamicSharedMemorySize, GEMM_SMEM);

    dim3 thr(256);
    // splits
    split2<<<(MROWS * Dh / 4 + 255) / 256, thr>>>(X,  xh,  xl,  MROWS * Dh / 4);
    split2<<<(Dh * Dh / 4 + 255) / 256, thr>>>(Wq, wqh, wql, Dh * Dh / 4);
    split2<<<(Dh * Dh / 4 + 255) / 256, thr>>>(Wk, wkh, wkl, Dh * Dh / 4);
    split2<<<(Dh * Dh / 4 + 255) / 256, thr>>>(Wv, wvh, wvl, Dh * Dh / 4);
    split2<<<(Dh * Dh / 4 + 255) / 256, thr>>>(Wo, woh, wol, Dh * Dh / 4);

    dim3 gg(Dh / 128, MROWS / 128);     // (8, 64)
    gemm_bf16x3<<<gg, thr, GEMM_SMEM>>>(xh, xl, wqh, wql, bq, nullptr, qh, ql, 3);
    gemm_bf16x3<<<gg, thr, GEMM_SMEM>>>(xh, xl, wkh, wkl, bk, nullptr, kh, kl, 1);
    gemm_bf16x3<<<gg, thr, GEMM_SMEM>>>(xh, xl, wvh, wvl, bv, nullptr, vh, vl, 2);

    dim3 ga(SEQ / 128, BATCH * NH);     // (16, 64)
    attn_mma<<<ga, thr>>>(qh, ql, kh, kl, vh, vl, cxh, cxl);

    gemm_bf16x3<<<gg, thr, GEMM_SMEM>>>(cxh, cxl, woh, wol, bo, out, nullptr, nullptr, 0);
}

// round 8
// speedup vs baseline: 4.2483x; 1.1069x over previous
#include <cuda_runtime.h>
#include <cuda_bf16.h>
#include <cstdint>
#include <math.h>

#define Dh     1024
#define NH     16
#define HD     64
#define SEQ    2048
#define BATCH  4
#define MROWS  8192   // BATCH*SEQ

typedef __nv_bfloat16 bf16;

// ---------------- scratch (static device globals; no allocation) -------------
__device__ bf16  g_xh[(size_t)MROWS * Dh];   // X split [M,1024]
__device__ bf16  g_xl[(size_t)MROWS * Dh];
__device__ bf16  g_wqh[(size_t)Dh * Dh], g_wql[(size_t)Dh * Dh];
__device__ bf16  g_wkh[(size_t)Dh * Dh], g_wkl[(size_t)Dh * Dh];
__device__ bf16  g_wvh[(size_t)Dh * Dh], g_wvl[(size_t)Dh * Dh];
__device__ bf16  g_woh[(size_t)Dh * Dh], g_wol[(size_t)Dh * Dh];
__device__ bf16  g_qh[(size_t)MROWS * Dh];   // [B,H,S,DH] (pre-scaled by 0.125)
__device__ bf16  g_ql[(size_t)MROWS * Dh];
__device__ bf16  g_kh[(size_t)MROWS * Dh];   // [B,H,S,DH]
__device__ bf16  g_kl[(size_t)MROWS * Dh];
__device__ bf16  g_vh[(size_t)MROWS * Dh];   // [B,H,DH,S]  (transposed)
__device__ bf16  g_vl[(size_t)MROWS * Dh];
__device__ bf16  g_cxh[(size_t)MROWS * Dh];  // ctx split [M,1024]
__device__ bf16  g_cxl[(size_t)MROWS * Dh];

// ======================= helpers =============================================
__device__ __forceinline__ uint32_t smem_u32(const void* p) {
    uint32_t a;
    asm("{ .reg .u64 t; cvta.to.shared.u64 t, %1; cvt.u32.u64 %0, t; }" : "=r"(a) : "l"(p));
    return a;
}
__device__ __forceinline__ void mma_bf16(float d[4],
                                         uint32_t a0, uint32_t a1, uint32_t a2, uint32_t a3,
                                         uint32_t b0, uint32_t b1) {
    asm volatile(
        "mma.sync.aligned.m16n8k16.row.col.f32.bf16.bf16.f32 "
        "{%0,%1,%2,%3}, {%4,%5,%6,%7}, {%8,%9}, {%0,%1,%2,%3};"
        : "+f"(d[0]), "+f"(d[1]), "+f"(d[2]), "+f"(d[3])
        : "r"(a0), "r"(a1), "r"(a2), "r"(a3), "r"(b0), "r"(b1));
}
__device__ __forceinline__ void ldm_x4(uint32_t& r0, uint32_t& r1, uint32_t& r2,
                                       uint32_t& r3, uint32_t addr) {
    asm volatile("ldmatrix.sync.aligned.m8n8.x4.shared.b16 {%0,%1,%2,%3}, [%4];"
        : "=r"(r0), "=r"(r1), "=r"(r2), "=r"(r3) : "r"(addr));
}
// pack two f32 -> bf16x2 {hi=v1, lo=v0}, plus residual pack
__device__ __forceinline__ void split_pack(float v0, float v1, uint32_t& ph, uint32_t& pl) {
    asm("cvt.rn.bf16x2.f32 %0, %1, %2;" : "=r"(ph) : "f"(v1), "f"(v0));
    float lo = __uint_as_float(ph << 16);
    float hi = __uint_as_float(ph & 0xffff0000u);
    asm("cvt.rn.bf16x2.f32 %0, %1, %2;" : "=r"(pl) : "f"(v1 - hi), "f"(v0 - lo));
}
#define CP_ASYNC16(dst_u32, src_ptr) \
    asm volatile("cp.async.ca.shared.global [%0], [%1], 16;" :: "r"(dst_u32), "l"(src_ptr))
#define CP_COMMIT() asm volatile("cp.async.commit_group;" ::: "memory")
#define CP_WAIT(n)  asm volatile("cp.async.wait_group %0;" :: "n"(n) : "memory")

// ================== fp32 -> bf16 (hi,lo) split ================================
__global__ __launch_bounds__(256) void split2(const float* __restrict__ in,
                                              bf16* __restrict__ hi, bf16* __restrict__ lo,
                                              int n4)
{
    int i = blockIdx.x * 256 + threadIdx.x;
    if (i >= n4) return;
    float4 v = ((const float4*)in)[i];
    uint32_t ph0, pl0, ph1, pl1;
    split_pack(v.x, v.y, ph0, pl0);
    split_pack(v.z, v.w, ph1, pl1);
    *(uint2*)&hi[(size_t)i * 4] = make_uint2(ph0, ph1);
    *(uint2*)&lo[(size_t)i * 4] = make_uint2(pl0, pl1);
}

// ================== bf16x3 mma.sync GEMM (ldmatrix) ==========================
#define AS        40                       // smem row stride in bf16 (32 + 8 pad)
#define MSTG      (128 * AS)
#define STG_SPAN  (4 * MSTG)
#define GEMM_SMEM (2 * STG_SPAN * 2)       // 81920 bytes

__global__ __launch_bounds__(256) void gemm_bf16x3(
    const bf16* __restrict__ Ah, const bf16* __restrict__ Al,
    const bf16* __restrict__ Wh, const bf16* __restrict__ Wl,
    const float* __restrict__ bias, float* __restrict__ outF,
    bf16* __restrict__ outH, bf16* __restrict__ outL, int mode)
{
    extern __shared__ bf16 sb[];

    const int tid   = threadIdx.x;
    const int lane  = tid & 31;
    const int wid   = tid >> 5;
    const int warpM = wid >> 1;
    const int warpN = wid & 1;
    const int m0 = blockIdx.y * 128;
    const int n0 = blockIdx.x * 128;
    const int gid = lane >> 2;
    const int tig = lane & 3;

    // ldmatrix per-lane address components
    const int aRow = (lane & 7) + ((lane >> 3) & 1) * 8;   // A: m order {r0-7@k, r8-15@k, r0-7@k+8, r8-15@k+8}
    const int aCol = (lane >> 4) * 8;
    const int bRow = (lane & 7) + (lane >> 4) * 8;         // B: m order {t0@k, t0@k+8, t1@k, t1@k+8}
    const int bCol = ((lane >> 3) & 1) * 8;

    float d[2][8][4];
#pragma unroll
    for (int mt = 0; mt < 2; ++mt)
#pragma unroll
        for (int nt = 0; nt < 8; ++nt)
#pragma unroll
            for (int q = 0; q < 4; ++q) d[mt][nt][q] = 0.f;

    const uint32_t sbu = smem_u32(sb);

#define ISSUE(c) do {                                                              \
    const int stg = (c) & 1;                                                       \
    const uint32_t ob = sbu + (uint32_t)stg * STG_SPAN * 2;                        \
    const bf16* sAh = Ah + (size_t)m0 * Dh + (c) * 32;                             \
    const bf16* sAl = Al + (size_t)m0 * Dh + (c) * 32;                             \
    const bf16* sWh = Wh + (size_t)n0 * Dh + (c) * 32;                             \
    const bf16* sWl = Wl + (size_t)n0 * Dh + (c) * 32;                             \
    _Pragma("unroll")                                                              \
    for (int rep = 0; rep < 2; ++rep) {                                            \
        int idx = rep * 256 + tid;                                                 \
        int r = idx >> 2, c8 = (idx & 3) * 8;                                      \
        uint32_t doff = (uint32_t)(r * AS + c8) * 2;                               \
        CP_ASYNC16(ob + doff,                sAh + (size_t)r * Dh + c8);           \
        CP_ASYNC16(ob + MSTG * 2 + doff,     sAl + (size_t)r * Dh + c8);           \
        CP_ASYNC16(ob + 2 * MSTG * 2 + doff, sWh + (size_t)r * Dh + c8);           \
        CP_ASYNC16(ob + 3 * MSTG * 2 + doff, sWl + (size_t)r * Dh + c8);           \
    }                                                                              \
    CP_COMMIT();                                                                   \
} while (0)

    ISSUE(0);

    for (int c = 0; c < Dh / 32; ++c) {
        if (c + 1 < Dh / 32) { ISSUE(c + 1); CP_WAIT(1); }
        else                 { CP_WAIT(0); }
        __syncthreads();

        const uint32_t base = sbu + (uint32_t)(c & 1) * STG_SPAN * 2;
        const uint32_t aHb = base;
        const uint32_t aLb = base + MSTG * 2;
        const uint32_t wHb = base + 2 * MSTG * 2;
        const uint32_t wLb = base + 3 * MSTG * 2;

#pragma unroll
        for (int kk = 0; kk < 2; ++kk) {
            const int kb = kk * 16;

            uint32_t ah[2][4], al[2][4];
#pragma unroll
            for (int mt = 0; mt < 2; ++mt) {
                const uint32_t off = (uint32_t)((warpM * 32 + mt * 16 + aRow) * AS + kb + aCol) * 2;
                ldm_x4(ah[mt][0], ah[mt][1], ah[mt][2], ah[mt][3], aHb + off);
                ldm_x4(al[mt][0], al[mt][1], al[mt][2], al[mt][3], aLb + off);
            }
#pragma unroll
            for (int P = 0; P < 4; ++P) {
                const uint32_t off = (uint32_t)((warpN * 64 + P * 16 + bRow) * AS + kb + bCol) * 2;
                uint32_t wh0, wh1, wh2, wh3, wl0, wl1, wl2, wl3;
                ldm_x4(wh0, wh1, wh2, wh3, wHb + off);
                ldm_x4(wl0, wl1, wl2, wl3, wLb + off);
#pragma unroll
                for (int mt = 0; mt < 2; ++mt) {
                    mma_bf16(d[mt][2*P],   ah[mt][0], ah[mt][1], ah[mt][2], ah[mt][3], wh0, wh1);
                    mma_bf16(d[mt][2*P],   al[mt][0], al[mt][1], al[mt][2], al[mt][3], wh0, wh1);
                    mma_bf16(d[mt][2*P],   ah[mt][0], ah[mt][1], ah[mt][2], ah[mt][3], wl0, wl1);
                    mma_bf16(d[mt][2*P+1], ah[mt][0], ah[mt][1], ah[mt][2], ah[mt][3], wh2, wh3);
                    mma_bf16(d[mt][2*P+1], al[mt][0], al[mt][1], al[mt][2], al[mt][3], wh2, wh3);
                    mma_bf16(d[mt][2*P+1], ah[mt][0], ah[mt][1], ah[mt][2], ah[mt][3], wl2, wl3);
                }
            }
        }
        __syncthreads();
    }
#undef ISSUE

    const float scl = (mode == 3) ? 0.125f : 1.f;
#pragma unroll
    for (int mt = 0; mt < 2; ++mt) {
        const int mrow = m0 + warpM * 32 + mt * 16 + gid;
#pragma unroll
        for (int nt = 0; nt < 8; ++nt) {
            const int ncol = n0 + warpN * 64 + nt * 8 + tig * 2;
            const float b0 = bias[ncol], b1 = bias[ncol + 1];
            if (mode == 0) {
                *(float2*)&outF[(size_t)mrow * Dh + ncol] =
                    make_float2(d[mt][nt][0] + b0, d[mt][nt][1] + b1);
                *(float2*)&outF[(size_t)(mrow + 8) * Dh + ncol] =
                    make_float2(d[mt][nt][2] + b0, d[mt][nt][3] + b1);
            } else if (mode == 2) {
                const int h = ncol >> 6, dh0 = ncol & 63;
#pragma unroll
                for (int rr = 0; rr < 2; ++rr) {
                    const int m = mrow + rr * 8;
                    const int bb = m >> 11, s = m & 2047;
                    float v0 = d[mt][nt][rr * 2 + 0] + b0;
                    float v1 = d[mt][nt][rr * 2 + 1] + b1;
                    size_t base = ((size_t)(bb * NH + h) * HD) * SEQ + s;
                    bf16 h0 = __float2bfloat16_rn(v0);
                    bf16 h1 = __float2bfloat16_rn(v1);
                    outH[base + (size_t)dh0 * SEQ]       = h0;
                    outH[base + (size_t)(dh0 + 1) * SEQ] = h1;
                    outL[base + (size_t)dh0 * SEQ]       = __float2bfloat16_rn(v0 - __bfloat162float(h0));
                    outL[base + (size_t)(dh0 + 1) * SEQ] = __float2bfloat16_rn(v1 - __bfloat162float(h1));
                }
            } else {
                const int h = ncol >> 6, dh0 = ncol & 63;
#pragma unroll
                for (int rr = 0; rr < 2; ++rr) {
                    const int m = mrow + rr * 8;
                    const int bb = m >> 11, s = m & 2047;
                    float v0 = (d[mt][nt][rr * 2 + 0] + b0) * scl;
                    float v1 = (d[mt][nt][rr * 2 + 1] + b1) * scl;
                    uint32_t ph, pl;
                    split_pack(v0, v1, ph, pl);
                    size_t off = ((size_t)(bb * NH + h) * SEQ + s) * HD + dh0;
                    *(uint32_t*)&outH[off] = ph;
                    *(uint32_t*)&outL[off] = pl;
                }
            }
        }
    }
}

// ================ bf16x3 flash attention (mma.sync + ldmatrix) ===============
#define AT_STRIDE 72          // smem row stride in bf16 (64 + 8 pad)

__global__ __launch_bounds__(256, 2) void attn_mma(
    const bf16* __restrict__ Qh, const bf16* __restrict__ Ql,
    const bf16* __restrict__ Kh, const bf16* __restrict__ Kl,
    const bf16* __restrict__ Vh, const bf16* __restrict__ Vl,
    bf16* __restrict__ ctxh, bf16* __restrict__ ctxl)
{
    __shared__ bf16 smem[4 * 64 * AT_STRIDE];
    bf16* KH = smem;
    bf16* KL = smem + 64 * AT_STRIDE;
    bf16* VH = smem + 2 * 64 * AT_STRIDE;
    bf16* VL = smem + 3 * 64 * AT_STRIDE;

    const int tid  = threadIdx.x;
    const int lane = tid & 31;
    const int wid  = tid >> 5;
    const int gid  = lane >> 2;
    const int tig  = lane & 3;
    const int bh   = blockIdx.y;
    const int q0   = blockIdx.x * 128;
    const int wq   = q0 + wid * 16;

    const int bRow = (lane & 7) + (lane >> 4) * 8;
    const int bCol = ((lane >> 3) & 1) * 8;
    const uint32_t uKH = smem_u32(KH), uKL = smem_u32(KL);
    const uint32_t uVH = smem_u32(VH), uVL = smem_u32(VL);

    uint32_t qfh[4][4], qfl[4][4];
    {
        const bf16* bqh = Qh + ((size_t)bh * SEQ + wq) * HD;
        const bf16* bql = Ql + ((size_t)bh * SEQ + wq) * HD;
#pragma unroll
        for (int j = 0; j < 4; ++j) {
            int e0 = 16 * j + 2 * tig;
            qfh[j][0] = *(const uint32_t*)(bqh + (size_t)gid * HD + e0);
            qfh[j][1] = *(const uint32_t*)(bqh + (size_t)(gid + 8) * HD + e0);
            qfh[j][2] = *(const uint32_t*)(bqh + (size_t)gid * HD + e0 + 8);
            qfh[j][3] = *(const uint32_t*)(bqh + (size_t)(gid + 8) * HD + e0 + 8);
            qfl[j][0] = *(const uint32_t*)(bql + (size_t)gid * HD + e0);
            qfl[j][1] = *(const uint32_t*)(bql + (size_t)(gid + 8) * HD + e0);
            qfl[j][2] = *(const uint32_t*)(bql + (size_t)gid * HD + e0 + 8);
            qfl[j][3] = *(const uint32_t*)(bql + (size_t)(gid + 8) * HD + e0 + 8);
        }
    }

    float cx[8][4];
#pragma unroll
    for (int nt = 0; nt < 8; ++nt)
#pragma unroll
        for (int q = 0; q < 4; ++q) cx[nt][q] = 0.f;
    float m0 = -1e30f, m1 = -1e30f, l0 = 0.f, l1 = 0.f;

    const bf16* bkh = Kh + (size_t)bh * SEQ * HD;
    const bf16* bkl = Kl + (size_t)bh * SEQ * HD;
    const bf16* bvh = Vh + (size_t)bh * SEQ * HD;   // [DH][SEQ]
    const bf16* bvl = Vl + (size_t)bh * SEQ * HD;

    for (int kt = 0; kt < SEQ / 64; ++kt) {
        __syncthreads();
        {
            const uint4* sKH = (const uint4*)(bkh + (size_t)kt * 64 * HD);
            const uint4* sKL = (const uint4*)(bkl + (size_t)kt * 64 * HD);
#pragma unroll
            for (int rep = 0; rep < 2; ++rep) {
                int chunk = tid * 2 + rep;
                int row = chunk >> 3, col8 = (chunk & 7) * 8;
                *(uint4*)&KH[row * AT_STRIDE + col8] = sKH[chunk];
                *(uint4*)&KL[row * AT_STRIDE + col8] = sKL[chunk];
                const uint4* sVH = (const uint4*)(bvh + (size_t)row * SEQ + kt * 64);
                const uint4* sVL = (const uint4*)(bvl + (size_t)row * SEQ + kt * 64);
                *(uint4*)&VH[row * AT_STRIDE + col8] = sVH[col8 >> 3];
                *(uint4*)&VL[row * AT_STRIDE + col8] = sVL[col8 >> 3];
            }
        }
        __syncthreads();

        float sacc[8][4];
#pragma unroll
        for (int nt = 0; nt < 8; ++nt)
#pragma unroll
            for (int q = 0; q < 4; ++q) sacc[nt][q] = 0.f;

#pragma unroll
        for (int j = 0; j < 4; ++j) {
            const uint32_t coff = (uint32_t)(16 * j + bCol) * 2;
#pragma unroll
            for (int P = 0; P < 4; ++P) {
                const uint32_t off = (uint32_t)((P * 16 + bRow) * AT_STRIDE) * 2 + coff;
                uint32_t kh0, kh1, kh2, kh3, kl0, kl1, kl2, kl3;
                ldm_x4(kh0, kh1, kh2, kh3, uKH + off);
                ldm_x4(kl0, kl1, kl2, kl3, uKL + off);
                mma_bf16(sacc[2*P],   qfh[j][0], qfh[j][1], qfh[j][2], qfh[j][3], kh0, kh1);
                mma_bf16(sacc[2*P],   qfl[j][0], qfl[j][1], qfl[j][2], qfl[j][3], kh0, kh1);
                mma_bf16(sacc[2*P],   qfh[j][0], qfh[j][1], qfh[j][2], qfh[j][3], kl0, kl1);
                mma_bf16(sacc[2*P+1], qfh[j][0], qfh[j][1], qfh[j][2], qfh[j][3], kh2, kh3);
                mma_bf16(sacc[2*P+1], qfl[j][0], qfl[j][1], qfl[j][2], qfl[j][3], kh2, kh3);
                mma_bf16(sacc[2*P+1], qfh[j][0], qfh[j][1], qfh[j][2], qfh[j][3], kl2, kl3);
            }
        }

        float mx0 = -1e30f, mx1 = -1e30f;
#pragma unroll
        for (int nt = 0; nt < 8; ++nt) {
            mx0 = fmaxf(mx0, fmaxf(sacc[nt][0], sacc[nt][1]));
            mx1 = fmaxf(mx1, fmaxf(sacc[nt][2], sacc[nt][3]));
        }
        mx0 = fmaxf(mx0, __shfl_xor_sync(0xffffffffu, mx0, 1));
        mx0 = fmaxf(mx0, __shfl_xor_sync(0xffffffffu, mx0, 2));
        mx1 = fmaxf(mx1, __shfl_xor_sync(0xffffffffu, mx1, 1));
        mx1 = fmaxf(mx1, __shfl_xor_sync(0xffffffffu, mx1, 2));
        float mn0 = fmaxf(m0, mx0), mn1 = fmaxf(m1, mx1);
        float r0 = __expf(m0 - mn0), r1 = __expf(m1 - mn1);
        m0 = mn0; m1 = mn1;

        float s0 = 0.f, s1 = 0.f;
#pragma unroll
        for (int nt = 0; nt < 8; ++nt) {
            float e0 = __expf(sacc[nt][0] - mn0);
            float e1 = __expf(sacc[nt][1] - mn0);
            float e2 = __expf(sacc[nt][2] - mn1);
            float e3 = __expf(sacc[nt][3] - mn1);
            sacc[nt][0] = e0; sacc[nt][1] = e1; sacc[nt][2] = e2; sacc[nt][3] = e3;
            s0 += e0 + e1; s1 += e2 + e3;
        }
        s0 += __shfl_xor_sync(0xffffffffu, s0, 1);
        s0 += __shfl_xor_sync(0xffffffffu, s0, 2);
        s1 += __shfl_xor_sync(0xffffffffu, s1, 1);
        s1 += __shfl_xor_sync(0xffffffffu, s1, 2);
        l0 = l0 * r0 + s0; l1 = l1 * r1 + s1;

#pragma unroll
        for (int nt = 0; nt < 8; ++nt) {
            cx[nt][0] *= r0; cx[nt][1] *= r0;
            cx[nt][2] *= r1; cx[nt][3] *= r1;
        }

#pragma unroll
        for (int j = 0; j < 4; ++j) {
            uint32_t pah[4], pal[4];
            split_pack(sacc[2*j][0],   sacc[2*j][1],   pah[0], pal[0]);
            split_pack(sacc[2*j][2],   sacc[2*j][3],   pah[1], pal[1]);
            split_pack(sacc[2*j+1][0], sacc[2*j+1][1], pah[2], pal[2]);
            split_pack(sacc[2*j+1][2], sacc[2*j+1][3], pah[3], pal[3]);
            const uint32_t coff = (uint32_t)(16 * j + bCol) * 2;
#pragma unroll
            for (int P = 0; P < 4; ++P) {
                const uint32_t off = (uint32_t)((P * 16 + bRow) * AT_STRIDE) * 2 + coff;
                uint32_t vh0, vh1, vh2, vh3, vl0_, vl1_, vl2_, vl3_;
                ldm_x4(vh0, vh1, vh2, vh3, uVH + off);
                ldm_x4(vl0_, vl1_, vl2_, vl3_, uVL + off);
                mma_bf16(cx[2*P],   pah[0], pah[1], pah[2], pah[3], vh0, vh1);
                mma_bf16(cx[2*P],   pal[0], pal[1], pal[2], pal[3], vh0, vh1);
                mma_bf16(cx[2*P],   pah[0], pah[1], pah[2], pah[3], vl0_, vl1_);
                mma_bf16(cx[2*P+1], pah[0], pah[1], pah[2], pah[3], vh2, vh3);
                mma_bf16(cx[2*P+1], pal[0], pal[1], pal[2], pal[3], vh2, vh3);
                mma_bf16(cx[2*P+1], pah[0], pah[1], pah[2], pah[3], vl2_, vl3_);
            }
        }
    }

    // ---- epilogue: ctx split to bf16 (hi,lo), flat [M,1024] ----
    const int b = bh >> 4, h = bh & 15;
    const float inv0 = 1.f / l0, inv1 = 1.f / l1;
    const int row0 = wq + gid, row1 = wq + gid + 8;
#pragma unroll
    for (int nt = 0; nt < 8; ++nt) {
        const int dcol = h * HD + 8 * nt + 2 * tig;
        uint32_t ph, pl;
        split_pack(cx[nt][0] * inv0, cx[nt][1] * inv0, ph, pl);
        size_t o0 = (size_t)(b * SEQ + row0) * Dh + dcol;
        *(uint32_t*)&ctxh[o0] = ph;
        *(uint32_t*)&ctxl[o0] = pl;
        split_pack(cx[nt][2] * inv1, cx[nt][3] * inv1, ph, pl);
        size_t o1 = (size_t)(b * SEQ + row1) * Dh + dcol;
        *(uint32_t*)&ctxh[o1] = ph;
        *(uint32_t*)&ctxl[o1] = pl;
    }
}

// ---------------- launch ------------------------------------------------------
extern "C" void kernel_launch(void* const* d_in, const int* in_sizes, int n_in,
                              void* d_out, int out_size)
{
    const float* X  = (const float*)d_in[0];
    const float* Wq = (const float*)d_in[1];
    const float* bq = (const float*)d_in[2];
    const float* Wk = (const float*)d_in[3];
    const float* bk = (const float*)d_in[4];
    const float* Wv = (const float*)d_in[5];
    const float* bv = (const float*)d_in[6];
    const float* Wo = (const float*)d_in[7];
    const float* bo = (const float*)d_in[8];
    float* out = (float*)d_out;

    bf16 *xh, *xl, *wqh, *wql, *wkh, *wkl, *wvh, *wvl, *woh, *wol;
    bf16 *qh, *ql, *kh, *kl, *vh, *vl, *cxh, *cxl;
    cudaGetSymbolAddress((void**)&xh,  g_xh);  cudaGetSymbolAddress((void**)&xl,  g_xl);
    cudaGetSymbolAddress((void**)&wqh, g_wqh); cudaGetSymbolAddress((void**)&wql, g_wql);
    cudaGetSymbolAddress((void**)&wkh, g_wkh); cudaGetSymbolAddress((void**)&wkl, g_wkl);
    cudaGetSymbolAddress((void**)&wvh, g_wvh); cudaGetSymbolAddress((void**)&wvl, g_wvl);
    cudaGetSymbolAddress((void**)&woh, g_woh); cudaGetSymbolAddress((void**)&wol, g_wol);
    cudaGetSymbolAddress((void**)&qh,  g_qh);  cudaGetSymbolAddress((void**)&ql,  g_ql);
    cudaGetSymbolAddress((void**)&kh,  g_kh);  cudaGetSymbolAddress((void**)&kl,  g_kl);
    cudaGetSymbolAddress((void**)&vh,  g_vh);  cudaGetSymbolAddress((void**)&vl,  g_vl);
    cudaGetSymbolAddress((void**)&cxh, g_cxh); cudaGetSymbolAddress((void**)&cxl, g_cxl);

    cudaFuncSetAttribute(gemm_bf16x3, cudaFuncAttributeMaxDynamicSharedMemorySize, GEMM_SMEM);

    dim3 thr(256);
    split2<<<(MROWS * Dh / 4 + 255) / 256, thr>>>(X,  xh,  xl,  MROWS * Dh / 4);
    split2<<<(Dh * Dh / 4 + 255) / 256, thr>>>(Wq, wqh, wql, Dh * Dh / 4);
    split2<<<(Dh * Dh / 4 + 255) / 256, thr>>>(Wk, wkh, wkl, Dh * Dh / 4);
    split2<<<(Dh * Dh / 4 + 255) / 256, thr>>>(Wv, wvh, wvl, Dh * Dh / 4);
    split2<<<(Dh * Dh / 4 + 255) / 256, thr>>>(Wo, woh, wol, Dh * Dh / 4);

    dim3 gg(Dh / 128, MROWS / 128);     // (8, 64)
    gemm_bf16x3<<<gg, thr, GEMM_SMEM>>>(xh, xl, wqh, wql, bq, nullptr, qh, ql, 3);
    gemm_bf16x3<<<gg, thr, GEMM_SMEM>>>(xh, xl, wkh, wkl, bk, nullptr, kh, kl, 1);
    gemm_bf16x3<<<gg, thr, GEMM_SMEM>>>(xh, xl, wvh, wvl, bv, nullptr, vh, vl, 2);

    dim3 ga(SEQ / 128, BATCH * NH);     // (16, 64)
    attn_mma<<<ga, thr>>>(qh, ql, kh, kl, vh, vl, cxh, cxl);

    gemm_bf16x3<<<gg, thr, GEMM_SMEM>>>(cxh, cxl, woh, wol, bo, out, nullptr, nullptr, 0);
}

// round 9
// speedup vs baseline: 4.4781x; 1.0541x over previous
#include <cuda_runtime.h>
#include <cuda_bf16.h>
#include <cstdint>
#include <math.h>

#define Dh     1024
#define NH     16
#define HD     64
#define SEQ    2048
#define BATCH  4
#define MROWS  8192   // BATCH*SEQ

typedef __nv_bfloat16 bf16;

// ---------------- scratch (static device globals; no allocation) -------------
__device__ bf16  g_xh[(size_t)MROWS * Dh];   // X split [M,1024]
__device__ bf16  g_xl[(size_t)MROWS * Dh];
__device__ bf16  g_wqh[(size_t)Dh * Dh], g_wql[(size_t)Dh * Dh];
__device__ bf16  g_wkh[(size_t)Dh * Dh], g_wkl[(size_t)Dh * Dh];
__device__ bf16  g_wvh[(size_t)Dh * Dh], g_wvl[(size_t)Dh * Dh];
__device__ bf16  g_woh[(size_t)Dh * Dh], g_wol[(size_t)Dh * Dh];
__device__ bf16  g_qh[(size_t)MROWS * Dh];   // [B,H,S,DH] (pre-scaled by 0.125)
__device__ bf16  g_ql[(size_t)MROWS * Dh];
__device__ bf16  g_kh[(size_t)MROWS * Dh];   // [B,H,S,DH]
__device__ bf16  g_kl[(size_t)MROWS * Dh];
__device__ bf16  g_vh[(size_t)MROWS * Dh];   // [B,H,DH,S]  (transposed)
__device__ bf16  g_vl[(size_t)MROWS * Dh];
__device__ bf16  g_cxh[(size_t)MROWS * Dh];  // ctx split [M,1024]
__device__ bf16  g_cxl[(size_t)MROWS * Dh];

// ======================= helpers =============================================
__device__ __forceinline__ uint32_t smem_u32(const void* p) {
    uint32_t a;
    asm("{ .reg .u64 t; cvta.to.shared.u64 t, %1; cvt.u32.u64 %0, t; }" : "=r"(a) : "l"(p));
    return a;
}
__device__ __forceinline__ void mma_bf16(float d[4],
                                         uint32_t a0, uint32_t a1, uint32_t a2, uint32_t a3,
                                         uint32_t b0, uint32_t b1) {
    asm volatile(
        "mma.sync.aligned.m16n8k16.row.col.f32.bf16.bf16.f32 "
        "{%0,%1,%2,%3}, {%4,%5,%6,%7}, {%8,%9}, {%0,%1,%2,%3};"
        : "+f"(d[0]), "+f"(d[1]), "+f"(d[2]), "+f"(d[3])
        : "r"(a0), "r"(a1), "r"(a2), "r"(a3), "r"(b0), "r"(b1));
}
__device__ __forceinline__ void ldm_x4(uint32_t& r0, uint32_t& r1, uint32_t& r2,
                                       uint32_t& r3, uint32_t addr) {
    asm volatile("ldmatrix.sync.aligned.m8n8.x4.shared.b16 {%0,%1,%2,%3}, [%4];"
        : "=r"(r0), "=r"(r1), "=r"(r2), "=r"(r3) : "r"(addr));
}
// pack two f32 -> bf16x2 {hi=v1, lo=v0}, plus residual pack
__device__ __forceinline__ void split_pack(float v0, float v1, uint32_t& ph, uint32_t& pl) {
    asm("cvt.rn.bf16x2.f32 %0, %1, %2;" : "=r"(ph) : "f"(v1), "f"(v0));
    float lo = __uint_as_float(ph << 16);
    float hi = __uint_as_float(ph & 0xffff0000u);
    asm("cvt.rn.bf16x2.f32 %0, %1, %2;" : "=r"(pl) : "f"(v1 - hi), "f"(v0 - lo));
}
#define CP_ASYNC16(dst_u32, src_ptr) \
    asm volatile("cp.async.ca.shared.global [%0], [%1], 16;" :: "r"(dst_u32), "l"(src_ptr))
#define CP_COMMIT() asm volatile("cp.async.commit_group;" ::: "memory")
#define CP_WAIT(n)  asm volatile("cp.async.wait_group %0;" :: "n"(n) : "memory")

// ================== fp32 -> bf16 (hi,lo) split ================================
__global__ __launch_bounds__(256) void split2(const float* __restrict__ in,
                                              bf16* __restrict__ hi, bf16* __restrict__ lo,
                                              int n4)
{
    int i = blockIdx.x * 256 + threadIdx.x;
    if (i >= n4) return;
    float4 v = ((const float4*)in)[i];
    uint32_t ph0, pl0, ph1, pl1;
    split_pack(v.x, v.y, ph0, pl0);
    split_pack(v.z, v.w, ph1, pl1);
    *(uint2*)&hi[(size_t)i * 4] = make_uint2(ph0, ph1);
    *(uint2*)&lo[(size_t)i * 4] = make_uint2(pl0, pl1);
}

// ================== bf16x3 mma.sync GEMM (256x128 tile, 512 thr) =============
#define AS        40                       // smem row stride in bf16 (32 + 8 pad)
#define A_STG     (256 * AS)               // bf16 per A matrix per stage
#define W_STG     (128 * AS)
#define SPAN      (2 * A_STG + 2 * W_STG)  // 30720 bf16
#define GEMM_SMEM (2 * SPAN * 2)           // 122880 bytes

__global__ __launch_bounds__(512, 1) void gemm_bf16x3(
    const bf16* __restrict__ Ah, const bf16* __restrict__ Al,
    const bf16* __restrict__ Wh, const bf16* __restrict__ Wl,
    const float* __restrict__ bias, float* __restrict__ outF,
    bf16* __restrict__ outH, bf16* __restrict__ outL, int mode)
{
    extern __shared__ bf16 sb[];

    const int tid   = threadIdx.x;
    const int lane  = tid & 31;
    const int wid   = tid >> 5;
    const int warpM = wid >> 1;            // 0..7 -> 32-row slice of 256
    const int warpN = wid & 1;             // 0..1 -> 64-col slice
    const int m0 = blockIdx.y * 256;
    const int n0 = blockIdx.x * 128;
    const int gid = lane >> 2;
    const int tig = lane & 3;

    const int aRow = (lane & 7) + ((lane >> 3) & 1) * 8;
    const int aCol = (lane >> 4) * 8;
    const int bRow = (lane & 7) + (lane >> 4) * 8;
    const int bCol = ((lane >> 3) & 1) * 8;

    float d[2][8][4];
#pragma unroll
    for (int mt = 0; mt < 2; ++mt)
#pragma unroll
        for (int nt = 0; nt < 8; ++nt)
#pragma unroll
            for (int q = 0; q < 4; ++q) d[mt][nt][q] = 0.f;

    const uint32_t sbu = smem_u32(sb);

#define ISSUE(c) do {                                                              \
    const int stg = (c) & 1;                                                       \
    const uint32_t ob = sbu + (uint32_t)stg * SPAN * 2;                            \
    const bf16* sAh = Ah + (size_t)m0 * Dh + (c) * 32;                             \
    const bf16* sAl = Al + (size_t)m0 * Dh + (c) * 32;                             \
    const bf16* sWh = Wh + (size_t)n0 * Dh + (c) * 32;                             \
    const bf16* sWl = Wl + (size_t)n0 * Dh + (c) * 32;                             \
    _Pragma("unroll")                                                              \
    for (int rep = 0; rep < 2; ++rep) {                                            \
        int idx = rep * 512 + tid;         /* 0..1023: A chunks */                 \
        int r = idx >> 2, c8 = (idx & 3) * 8;                                      \
        uint32_t doff = (uint32_t)(r * AS + c8) * 2;                               \
        CP_ASYNC16(ob + doff,             sAh + (size_t)r * Dh + c8);              \
        CP_ASYNC16(ob + A_STG * 2 + doff, sAl + (size_t)r * Dh + c8);              \
    }                                                                              \
    {                                                                              \
        int r = tid >> 2, c8 = (tid & 3) * 8;  /* 512 W chunks */                  \
        uint32_t doff = (uint32_t)(r * AS + c8) * 2;                               \
        CP_ASYNC16(ob + 2 * A_STG * 2 + doff,             sWh + (size_t)r * Dh + c8); \
        CP_ASYNC16(ob + (2 * A_STG + W_STG) * 2 + doff,   sWl + (size_t)r * Dh + c8); \
    }                                                                              \
    CP_COMMIT();                                                                   \
} while (0)

    ISSUE(0);

    for (int c = 0; c < Dh / 32; ++c) {
        if (c + 1 < Dh / 32) { ISSUE(c + 1); CP_WAIT(1); }
        else                 { CP_WAIT(0); }
        __syncthreads();

        const uint32_t base = sbu + (uint32_t)(c & 1) * SPAN * 2;
        const uint32_t aHb = base;
        const uint32_t aLb = base + A_STG * 2;
        const uint32_t wHb = base + 2 * A_STG * 2;
        const uint32_t wLb = base + (2 * A_STG + W_STG) * 2;

#pragma unroll
        for (int kk = 0; kk < 2; ++kk) {
            const int kb = kk * 16;

            uint32_t ah[2][4], al[2][4];
#pragma unroll
            for (int mt = 0; mt < 2; ++mt) {
                const uint32_t off = (uint32_t)((warpM * 32 + mt * 16 + aRow) * AS + kb + aCol) * 2;
                ldm_x4(ah[mt][0], ah[mt][1], ah[mt][2], ah[mt][3], aHb + off);
                ldm_x4(al[mt][0], al[mt][1], al[mt][2], al[mt][3], aLb + off);
            }
#pragma unroll
            for (int P = 0; P < 4; ++P) {
                const uint32_t off = (uint32_t)((warpN * 64 + P * 16 + bRow) * AS + kb + bCol) * 2;
                uint32_t wh0, wh1, wh2, wh3, wl0, wl1, wl2, wl3;
                ldm_x4(wh0, wh1, wh2, wh3, wHb + off);
                ldm_x4(wl0, wl1, wl2, wl3, wLb + off);
#pragma unroll
                for (int mt = 0; mt < 2; ++mt) {
                    mma_bf16(d[mt][2*P],   ah[mt][0], ah[mt][1], ah[mt][2], ah[mt][3], wh0, wh1);
                    mma_bf16(d[mt][2*P],   al[mt][0], al[mt][1], al[mt][2], al[mt][3], wh0, wh1);
                    mma_bf16(d[mt][2*P],   ah[mt][0], ah[mt][1], ah[mt][2], ah[mt][3], wl0, wl1);
                    mma_bf16(d[mt][2*P+1], ah[mt][0], ah[mt][1], ah[mt][2], ah[mt][3], wh2, wh3);
                    mma_bf16(d[mt][2*P+1], al[mt][0], al[mt][1], al[mt][2], al[mt][3], wh2, wh3);
                    mma_bf16(d[mt][2*P+1], ah[mt][0], ah[mt][1], ah[mt][2], ah[mt][3], wl2, wl3);
                }
            }
        }
        __syncthreads();
    }
#undef ISSUE

    const float scl = (mode == 3) ? 0.125f : 1.f;
#pragma unroll
    for (int mt = 0; mt < 2; ++mt) {
        const int mrow = m0 + warpM * 32 + mt * 16 + gid;
#pragma unroll
        for (int nt = 0; nt < 8; ++nt) {
            const int ncol = n0 + warpN * 64 + nt * 8 + tig * 2;
            const float b0 = bias[ncol], b1 = bias[ncol + 1];
            if (mode == 0) {
                *(float2*)&outF[(size_t)mrow * Dh + ncol] =
                    make_float2(d[mt][nt][0] + b0, d[mt][nt][1] + b1);
                *(float2*)&outF[(size_t)(mrow + 8) * Dh + ncol] =
                    make_float2(d[mt][nt][2] + b0, d[mt][nt][3] + b1);
            } else if (mode == 2) {
                const int h = ncol >> 6, dh0 = ncol & 63;
#pragma unroll
                for (int rr = 0; rr < 2; ++rr) {
                    const int m = mrow + rr * 8;
                    const int bb = m >> 11, s = m & 2047;
                    float v0 = d[mt][nt][rr * 2 + 0] + b0;
                    float v1 = d[mt][nt][rr * 2 + 1] + b1;
                    size_t base = ((size_t)(bb * NH + h) * HD) * SEQ + s;
                    bf16 h0 = __float2bfloat16_rn(v0);
                    bf16 h1 = __float2bfloat16_rn(v1);
                    outH[base + (size_t)dh0 * SEQ]       = h0;
                    outH[base + (size_t)(dh0 + 1) * SEQ] = h1;
                    outL[base + (size_t)dh0 * SEQ]       = __float2bfloat16_rn(v0 - __bfloat162float(h0));
                    outL[base + (size_t)(dh0 + 1) * SEQ] = __float2bfloat16_rn(v1 - __bfloat162float(h1));
                }
            } else {
                const int h = ncol >> 6, dh0 = ncol & 63;
#pragma unroll
                for (int rr = 0; rr < 2; ++rr) {
                    const int m = mrow + rr * 8;
                    const int bb = m >> 11, s = m & 2047;
                    float v0 = (d[mt][nt][rr * 2 + 0] + b0) * scl;
                    float v1 = (d[mt][nt][rr * 2 + 1] + b1) * scl;
                    uint32_t ph, pl;
                    split_pack(v0, v1, ph, pl);
                    size_t off = ((size_t)(bb * NH + h) * SEQ + s) * HD + dh0;
                    *(uint32_t*)&outH[off] = ph;
                    *(uint32_t*)&outL[off] = pl;
                }
            }
        }
    }
}

// ========= bf16x3 flash attention (mma.sync + ldmatrix + cp.async) ===========
#define AT_STRIDE 72                        // smem row stride in bf16 (64 + 8 pad)
#define AT_MAT    (64 * AT_STRIDE)          // one 64x64 matrix (bf16 units)
#define ATT_SPAN  (4 * AT_MAT)              // KH,KL,VH,VL per stage
#define ATT_SMEM  (2 * ATT_SPAN * 2)        // 73728 bytes

__global__ __launch_bounds__(256, 2) void attn_mma(
    const bf16* __restrict__ Qh, const bf16* __restrict__ Ql,
    const bf16* __restrict__ Kh, const bf16* __restrict__ Kl,
    const bf16* __restrict__ Vh, const bf16* __restrict__ Vl,
    bf16* __restrict__ ctxh, bf16* __restrict__ ctxl)
{
    extern __shared__ bf16 asm_[];

    const int tid  = threadIdx.x;
    const int lane = tid & 31;
    const int wid  = tid >> 5;
    const int gid  = lane >> 2;
    const int tig  = lane & 3;
    const int bh   = blockIdx.y;
    const int q0   = blockIdx.x * 128;
    const int wq   = q0 + wid * 16;

    const int bRow = (lane & 7) + (lane >> 4) * 8;
    const int bCol = ((lane >> 3) & 1) * 8;
    const uint32_t smu = smem_u32(asm_);

    const bf16* bkh = Kh + (size_t)bh * SEQ * HD;
    const bf16* bkl = Kl + (size_t)bh * SEQ * HD;
    const bf16* bvh = Vh + (size_t)bh * SEQ * HD;   // [DH][SEQ]
    const bf16* bvl = Vl + (size_t)bh * SEQ * HD;

#define ISSUEA(t) do {                                                             \
    const int stg = (t) & 1;                                                       \
    const uint32_t ob = smu + (uint32_t)stg * ATT_SPAN * 2;                        \
    const bf16* pKH = bkh + (size_t)(t) * 64 * HD;                                 \
    const bf16* pKL = bkl + (size_t)(t) * 64 * HD;                                 \
    _Pragma("unroll")                                                              \
    for (int rep = 0; rep < 2; ++rep) {                                            \
        int idx = rep * 256 + tid;          /* 0..511 */                           \
        int row = idx >> 3, col8 = (idx & 7) * 8;                                  \
        uint32_t doff = (uint32_t)(row * AT_STRIDE + col8) * 2;                    \
        CP_ASYNC16(ob + doff,                 pKH + (size_t)row * HD + col8);      \
        CP_ASYNC16(ob + AT_MAT * 2 + doff,    pKL + (size_t)row * HD + col8);      \
        CP_ASYNC16(ob + 2 * AT_MAT * 2 + doff, bvh + (size_t)row * SEQ + (t) * 64 + col8); \
        CP_ASYNC16(ob + 3 * AT_MAT * 2 + doff, bvl + (size_t)row * SEQ + (t) * 64 + col8); \
    }                                                                              \
    CP_COMMIT();                                                                   \
} while (0)

    uint32_t qfh[4][4], qfl[4][4];
    {
        const bf16* bqh = Qh + ((size_t)bh * SEQ + wq) * HD;
        const bf16* bql = Ql + ((size_t)bh * SEQ + wq) * HD;
#pragma unroll
        for (int j = 0; j < 4; ++j) {
            int e0 = 16 * j + 2 * tig;
            qfh[j][0] = *(const uint32_t*)(bqh + (size_t)gid * HD + e0);
            qfh[j][1] = *(const uint32_t*)(bqh + (size_t)(gid + 8) * HD + e0);
            qfh[j][2] = *(const uint32_t*)(bqh + (size_t)gid * HD + e0 + 8);
            qfh[j][3] = *(const uint32_t*)(bqh + (size_t)(gid + 8) * HD + e0 + 8);
            qfl[j][0] = *(const uint32_t*)(bql + (size_t)gid * HD + e0);
            qfl[j][1] = *(const uint32_t*)(bql + (size_t)(gid + 8) * HD + e0);
            qfl[j][2] = *(const uint32_t*)(bql + (size_t)gid * HD + e0 + 8);
            qfl[j][3] = *(const uint32_t*)(bql + (size_t)(gid + 8) * HD + e0 + 8);
        }
    }

    float cx[8][4];
#pragma unroll
    for (int nt = 0; nt < 8; ++nt)
#pragma unroll
        for (int q = 0; q < 4; ++q) cx[nt][q] = 0.f;
    float m0 = -1e30f, m1 = -1e30f, l0 = 0.f, l1 = 0.f;

    ISSUEA(0);

    for (int kt = 0; kt < SEQ / 64; ++kt) {
        __syncthreads();                        // all warps done with stage (kt+1)&1
        if (kt + 1 < SEQ / 64) { ISSUEA(kt + 1); CP_WAIT(1); }
        else                   { CP_WAIT(0); }
        __syncthreads();                        // stage kt&1 data visible

        const uint32_t sbase = smu + (uint32_t)(kt & 1) * ATT_SPAN * 2;
        const uint32_t uKH = sbase;
        const uint32_t uKL = sbase + AT_MAT * 2;
        const uint32_t uVH = sbase + 2 * AT_MAT * 2;
        const uint32_t uVL = sbase + 3 * AT_MAT * 2;

        float sacc[8][4];
#pragma unroll
        for (int nt = 0; nt < 8; ++nt)
#pragma unroll
            for (int q = 0; q < 4; ++q) sacc[nt][q] = 0.f;

#pragma unroll
        for (int j = 0; j < 4; ++j) {
            const uint32_t coff = (uint32_t)(16 * j + bCol) * 2;
#pragma unroll
            for (int P = 0; P < 4; ++P) {
                const uint32_t off = (uint32_t)((P * 16 + bRow) * AT_STRIDE) * 2 + coff;
                uint32_t kh0, kh1, kh2, kh3, kl0, kl1, kl2, kl3;
                ldm_x4(kh0, kh1, kh2, kh3, uKH + off);
                ldm_x4(kl0, kl1, kl2, kl3, uKL + off);
                mma_bf16(sacc[2*P],   qfh[j][0], qfh[j][1], qfh[j][2], qfh[j][3], kh0, kh1);
                mma_bf16(sacc[2*P],   qfl[j][0], qfl[j][1], qfl[j][2], qfl[j][3], kh0, kh1);
                mma_bf16(sacc[2*P],   qfh[j][0], qfh[j][1], qfh[j][2], qfh[j][3], kl0, kl1);
                mma_bf16(sacc[2*P+1], qfh[j][0], qfh[j][1], qfh[j][2], qfh[j][3], kh2, kh3);
                mma_bf16(sacc[2*P+1], qfl[j][0], qfl[j][1], qfl[j][2], qfl[j][3], kh2, kh3);
                mma_bf16(sacc[2*P+1], qfh[j][0], qfh[j][1], qfh[j][2], qfh[j][3], kl2, kl3);
            }
        }

        float mx0 = -1e30f, mx1 = -1e30f;
#pragma unroll
        for (int nt = 0; nt < 8; ++nt) {
            mx0 = fmaxf(mx0, fmaxf(sacc[nt][0], sacc[nt][1]));
            mx1 = fmaxf(mx1, fmaxf(sacc[nt][2], sacc[nt][3]));
        }
        mx0 = fmaxf(mx0, __shfl_xor_sync(0xffffffffu, mx0, 1));
        mx0 = fmaxf(mx0, __shfl_xor_sync(0xffffffffu, mx0, 2));
        mx1 = fmaxf(mx1, __shfl_xor_sync(0xffffffffu, mx1, 1));
        mx1 = fmaxf(mx1, __shfl_xor_sync(0xffffffffu, mx1, 2));
        float mn0 = fmaxf(m0, mx0), mn1 = fmaxf(m1, mx1);
        float r0 = __expf(m0 - mn0), r1 = __expf(m1 - mn1);
        m0 = mn0; m1 = mn1;

        float s0 = 0.f, s1 = 0.f;
#pragma unroll
        for (int nt = 0; nt < 8; ++nt) {
            float e0 = __expf(sacc[nt][0] - mn0);
            float e1 = __expf(sacc[nt][1] - mn0);
            float e2 = __expf(sacc[nt][2] - mn1);
            float e3 = __expf(sacc[nt][3] - mn1);
            sacc[nt][0] = e0; sacc[nt][1] = e1; sacc[nt][2] = e2; sacc[nt][3] = e3;
            s0 += e0 + e1; s1 += e2 + e3;
        }
        s0 += __shfl_xor_sync(0xffffffffu, s0, 1);
        s0 += __shfl_xor_sync(0xffffffffu, s0, 2);
        s1 += __shfl_xor_sync(0xffffffffu, s1, 1);
        s1 += __shfl_xor_sync(0xffffffffu, s1, 2);
        l0 = l0 * r0 + s0; l1 = l1 * r1 + s1;

#pragma unroll
        for (int nt = 0; nt < 8; ++nt) {
            cx[nt][0] *= r0; cx[nt][1] *= r0;
            cx[nt][2] *= r1; cx[nt][3] *= r1;
        }

#pragma unroll
        for (int j = 0; j < 4; ++j) {
            uint32_t pah[4], pal[4];
            split_pack(sacc[2*j][0],   sacc[2*j][1],   pah[0], pal[0]);
            split_pack(sacc[2*j][2],   sacc[2*j][3],   pah[1], pal[1]);
            split_pack(sacc[2*j+1][0], sacc[2*j+1][1], pah[2], pal[2]);
            split_pack(sacc[2*j+1][2], sacc[2*j+1][3], pah[3], pal[3]);
            const uint32_t coff = (uint32_t)(16 * j + bCol) * 2;
#pragma unroll
            for (int P = 0; P < 4; ++P) {
                const uint32_t off = (uint32_t)((P * 16 + bRow) * AT_STRIDE) * 2 + coff;
                uint32_t vh0, vh1, vh2, vh3, vl0_, vl1_, vl2_, vl3_;
                ldm_x4(vh0, vh1, vh2, vh3, uVH + off);
                ldm_x4(vl0_, vl1_, vl2_, vl3_, uVL + off);
                mma_bf16(cx[2*P],   pah[0], pah[1], pah[2], pah[3], vh0, vh1);
                mma_bf16(cx[2*P],   pal[0], pal[1], pal[2], pal[3], vh0, vh1);
                mma_bf16(cx[2*P],   pah[0], pah[1], pah[2], pah[3], vl0_, vl1_);
                mma_bf16(cx[2*P+1], pah[0], pah[1], pah[2], pah[3], vh2, vh3);
                mma_bf16(cx[2*P+1], pal[0], pal[1], pal[2], pal[3], vh2, vh3);
                mma_bf16(cx[2*P+1], pah[0], pah[1], pah[2], pah[3], vl2_, vl3_);
            }
        }
    }
#undef ISSUEA

    // ---- epilogue: ctx split to bf16 (hi,lo), flat [M,1024] ----
    const int b = bh >> 4, h = bh & 15;
    const float inv0 = 1.f / l0, inv1 = 1.f / l1;
    const int row0 = wq + gid, row1 = wq + gid + 8;
#pragma unroll
    for (int nt = 0; nt < 8; ++nt) {
        const int dcol = h * HD + 8 * nt + 2 * tig;
        uint32_t ph, pl;
        split_pack(cx[nt][0] * inv0, cx[nt][1] * inv0, ph, pl);
        size_t o0 = (size_t)(b * SEQ + row0) * Dh + dcol;
        *(uint32_t*)&ctxh[o0] = ph;
        *(uint32_t*)&ctxl[o0] = pl;
        split_pack(cx[nt][2] * inv1, cx[nt][3] * inv1, ph, pl);
        size_t o1 = (size_t)(b * SEQ + row1) * Dh + dcol;
        *(uint32_t*)&ctxh[o1] = ph;
        *(uint32_t*)&ctxl[o1] = pl;
    }
}

// ---------------- launch ------------------------------------------------------
extern "C" void kernel_launch(void* const* d_in, const int* in_sizes, int n_in,
                              void* d_out, int out_size)
{
    const float* X  = (const float*)d_in[0];
    const float* Wq = (const float*)d_in[1];
    const float* bq = (const float*)d_in[2];
    const float* Wk = (const float*)d_in[3];
    const float* bk = (const float*)d_in[4];
    const float* Wv = (const float*)d_in[5];
    const float* bv = (const float*)d_in[6];
    const float* Wo = (const float*)d_in[7];
    const float* bo = (const float*)d_in[8];
    float* out = (float*)d_out;

    bf16 *xh, *xl, *wqh, *wql, *wkh, *wkl, *wvh, *wvl, *woh, *wol;
    bf16 *qh, *ql, *kh, *kl, *vh, *vl, *cxh, *cxl;
    cudaGetSymbolAddress((void**)&xh,  g_xh);  cudaGetSymbolAddress((void**)&xl,  g_xl);
    cudaGetSymbolAddress((void**)&wqh, g_wqh); cudaGetSymbolAddress((void**)&wql, g_wql);
    cudaGetSymbolAddress((void**)&wkh, g_wkh); cudaGetSymbolAddress((void**)&wkl, g_wkl);
    cudaGetSymbolAddress((void**)&wvh, g_wvh); cudaGetSymbolAddress((void**)&wvl, g_wvl);
    cudaGetSymbolAddress((void**)&woh, g_woh); cudaGetSymbolAddress((void**)&wol, g_wol);
    cudaGetSymbolAddress((void**)&qh,  g_qh);  cudaGetSymbolAddress((void**)&ql,  g_ql);
    cudaGetSymbolAddress((void**)&kh,  g_kh);  cudaGetSymbolAddress((void**)&kl,  g_kl);
    cudaGetSymbolAddress((void**)&vh,  g_vh);  cudaGetSymbolAddress((void**)&vl,  g_vl);
    cudaGetSymbolAddress((void**)&cxh, g_cxh); cudaGetSymbolAddress((void**)&cxl, g_cxl);

    cudaFuncSetAttribute(gemm_bf16x3, cudaFuncAttributeMaxDynamicSharedMemorySize, GEMM_SMEM);
    cudaFuncSetAttribute(attn_mma,    cudaFuncAttributeMaxDynamicSharedMemorySize, ATT_SMEM);

    dim3 thr(256);
    split2<<<(MROWS * Dh / 4 + 255) / 256, thr>>>(X,  xh,  xl,  MROWS * Dh / 4);
    split2<<<(Dh * Dh / 4 + 255) / 256, thr>>>(Wq, wqh, wql, Dh * Dh / 4);
    split2<<<(Dh * Dh / 4 + 255) / 256, thr>>>(Wk, wkh, wkl, Dh * Dh / 4);
    split2<<<(Dh * Dh / 4 + 255) / 256, thr>>>(Wv, wvh, wvl, Dh * Dh / 4);
    split2<<<(Dh * Dh / 4 + 255) / 256, thr>>>(Wo, woh, wol, Dh * Dh / 4);

    dim3 gthr(512);
    dim3 gg(Dh / 128, MROWS / 256);     // (8, 32)
    gemm_bf16x3<<<gg, gthr, GEMM_SMEM>>>(xh, xl, wqh, wql, bq, nullptr, qh, ql, 3);
    gemm_bf16x3<<<gg, gthr, GEMM_SMEM>>>(xh, xl, wkh, wkl, bk, nullptr, kh, kl, 1);
    gemm_bf16x3<<<gg, gthr, GEMM_SMEM>>>(xh, xl, wvh, wvl, bv, nullptr, vh, vl, 2);

    dim3 ga(SEQ / 128, BATCH * NH);     // (16, 64)
    attn_mma<<<ga, thr, ATT_SMEM>>>(qh, ql, kh, kl, vh, vl, cxh, cxl);

    gemm_bf16x3<<<gg, gthr, GEMM_SMEM>>>(cxh, cxl, woh, wol, bo, out, nullptr, nullptr, 0);
}

// round 10
// speedup vs baseline: 5.2169x; 1.1650x over previous
#include <cuda_runtime.h>
#include <cuda_bf16.h>
#include <cuda_fp16.h>
#include <cstdint>
#include <math.h>

#define Dh     1024
#define NH     16
#define HD     64
#define SEQ    2048
#define BATCH  4
#define MROWS  8192   // BATCH*SEQ

typedef __nv_bfloat16 bf16;

// ---------------- scratch (static device globals; no allocation) -------------
__device__ half  g_x16[(size_t)MROWS * Dh];                 // X fp16 [M,1024]
__device__ half  g_wq16h[(size_t)Dh * Dh], g_wq16l[(size_t)Dh * Dh];
__device__ half  g_wk16h[(size_t)Dh * Dh], g_wk16l[(size_t)Dh * Dh];
__device__ half  g_wv16h[(size_t)Dh * Dh], g_wv16l[(size_t)Dh * Dh];
__device__ half  g_wo16h[(size_t)Dh * Dh], g_wo16l[(size_t)Dh * Dh];
__device__ bf16  g_qh[(size_t)MROWS * Dh];   // [B,H,S,DH] (pre-scaled by 0.125)
__device__ bf16  g_ql[(size_t)MROWS * Dh];
__device__ bf16  g_kh[(size_t)MROWS * Dh];   // [B,H,S,DH]
__device__ bf16  g_kl[(size_t)MROWS * Dh];
__device__ bf16  g_vh[(size_t)MROWS * Dh];   // [B,H,DH,S]  (transposed)
__device__ bf16  g_vl[(size_t)MROWS * Dh];
__device__ half  g_cx16[(size_t)MROWS * Dh];                // ctx fp16 [M,1024]

// ======================= helpers =============================================
__device__ __forceinline__ uint32_t smem_u32(const void* p) {
    uint32_t a;
    asm("{ .reg .u64 t; cvta.to.shared.u64 t, %1; cvt.u32.u64 %0, t; }" : "=r"(a) : "l"(p));
    return a;
}
__device__ __forceinline__ void mma_bf16(float d[4],
                                         uint32_t a0, uint32_t a1, uint32_t a2, uint32_t a3,
                                         uint32_t b0, uint32_t b1) {
    asm("mma.sync.aligned.m16n8k16.row.col.f32.bf16.bf16.f32 "
        "{%0,%1,%2,%3}, {%4,%5,%6,%7}, {%8,%9}, {%0,%1,%2,%3};"
        : "+f"(d[0]), "+f"(d[1]), "+f"(d[2]), "+f"(d[3])
        : "r"(a0), "r"(a1), "r"(a2), "r"(a3), "r"(b0), "r"(b1));
}
__device__ __forceinline__ void mma_f16(float d[4],
                                        uint32_t a0, uint32_t a1, uint32_t a2, uint32_t a3,
                                        uint32_t b0, uint32_t b1) {
    asm("mma.sync.aligned.m16n8k16.row.col.f32.f16.f16.f32 "
        "{%0,%1,%2,%3}, {%4,%5,%6,%7}, {%8,%9}, {%0,%1,%2,%3};"
        : "+f"(d[0]), "+f"(d[1]), "+f"(d[2]), "+f"(d[3])
        : "r"(a0), "r"(a1), "r"(a2), "r"(a3), "r"(b0), "r"(b1));
}
__device__ __forceinline__ void ldm_x4(uint32_t& r0, uint32_t& r1, uint32_t& r2,
                                       uint32_t& r3, uint32_t addr) {
    asm volatile("ldmatrix.sync.aligned.m8n8.x4.shared.b16 {%0,%1,%2,%3}, [%4];"
        : "=r"(r0), "=r"(r1), "=r"(r2), "=r"(r3) : "r"(addr));
}
// pack two f32 -> bf16x2 {hi=v1, lo=v0}, plus residual pack
__device__ __forceinline__ void split_pack(float v0, float v1, uint32_t& ph, uint32_t& pl) {
    asm("cvt.rn.bf16x2.f32 %0, %1, %2;" : "=r"(ph) : "f"(v1), "f"(v0));
    float lo = __uint_as_float(ph << 16);
    float hi = __uint_as_float(ph & 0xffff0000u);
    asm("cvt.rn.bf16x2.f32 %0, %1, %2;" : "=r"(pl) : "f"(v1 - hi), "f"(v0 - lo));
}
#define CP_ASYNC16(dst_u32, src_ptr) \
    asm volatile("cp.async.ca.shared.global [%0], [%1], 16;" :: "r"(dst_u32), "l"(src_ptr))
#define CP_COMMIT() asm volatile("cp.async.commit_group;" ::: "memory")
#define CP_WAIT(n)  asm volatile("cp.async.wait_group %0;" :: "n"(n) : "memory")

// ================== fp32 -> fp16 convert / split =============================
__global__ __launch_bounds__(256) void cvt16(const float* __restrict__ in,
                                             half* __restrict__ out, int n4)
{
    int i = blockIdx.x * 256 + threadIdx.x;
    if (i >= n4) return;
    float4 v = ((const float4*)in)[i];
    __half2 a = __floats2half2_rn(v.x, v.y);
    __half2 b = __floats2half2_rn(v.z, v.w);
    *(uint2*)&out[(size_t)i * 4] = make_uint2(*(uint32_t*)&a, *(uint32_t*)&b);
}

__global__ __launch_bounds__(256) void splitW16(const float* __restrict__ in,
                                                half* __restrict__ hi, half* __restrict__ lo,
                                                int n4)
{
    int i = blockIdx.x * 256 + threadIdx.x;
    if (i >= n4) return;
    float4 v = ((const float4*)in)[i];
    half h0 = __float2half_rn(v.x), h1 = __float2half_rn(v.y);
    half h2 = __float2half_rn(v.z), h3 = __float2half_rn(v.w);
    half l0 = __float2half_rn(v.x - __half2float(h0));
    half l1 = __float2half_rn(v.y - __half2float(h1));
    half l2 = __float2half_rn(v.z - __half2float(h2));
    half l3 = __float2half_rn(v.w - __half2float(h3));
    __half2 H0 = __halves2half2(h0, h1), H1 = __halves2half2(h2, h3);
    __half2 L0 = __halves2half2(l0, l1), L1 = __halves2half2(l2, l3);
    *(uint2*)&hi[(size_t)i * 4] = make_uint2(*(uint32_t*)&H0, *(uint32_t*)&H1);
    *(uint2*)&lo[(size_t)i * 4] = make_uint2(*(uint32_t*)&L0, *(uint32_t*)&L1);
}

// =========== fp16 x2 (W-split) mma.sync GEMM: 256x128 tile, 512 thr ==========
// out[m,n] = sum_k A[m,k]*(Wh+Wl)[n,k] + bias[n]
#define AS        40                       // smem row stride in fp16 (32 + 8 pad)
#define A_STG     (256 * AS)               // 10240 fp16
#define W_STG     (128 * AS)               // 5120 fp16
#define SPAN      (A_STG + 2 * W_STG)      // 20480 fp16
#define GEMM_SMEM (2 * SPAN * 2)           // 81920 bytes

__global__ __launch_bounds__(512, 1) void gemm_f16x2(
    const half* __restrict__ A,
    const half* __restrict__ Wh, const half* __restrict__ Wl,
    const float* __restrict__ bias, float* __restrict__ outF,
    bf16* __restrict__ outH, bf16* __restrict__ outL, int mode)
{
    extern __shared__ half sb[];

    const int tid   = threadIdx.x;
    const int lane  = tid & 31;
    const int wid   = tid >> 5;
    const int warpM = wid >> 1;            // 0..7 -> 32-row slice of 256
    const int warpN = wid & 1;             // 0..1 -> 64-col slice
    const int m0 = blockIdx.y * 256;
    const int n0 = blockIdx.x * 128;
    const int gid = lane >> 2;
    const int tig = lane & 3;

    const int aRow = (lane & 7) + ((lane >> 3) & 1) * 8;
    const int aCol = (lane >> 4) * 8;
    const int bRow = (lane & 7) + (lane >> 4) * 8;
    const int bCol = ((lane >> 3) & 1) * 8;

    float d[2][8][4];
#pragma unroll
    for (int mt = 0; mt < 2; ++mt)
#pragma unroll
        for (int nt = 0; nt < 8; ++nt)
#pragma unroll
            for (int q = 0; q < 4; ++q) d[mt][nt][q] = 0.f;

    const uint32_t sbu = smem_u32(sb);

#define ISSUE(c) do {                                                              \
    const int stg = (c) & 1;                                                       \
    const uint32_t ob = sbu + (uint32_t)stg * SPAN * 2;                            \
    const half* sA  = A  + (size_t)m0 * Dh + (c) * 32;                             \
    const half* sWh = Wh + (size_t)n0 * Dh + (c) * 32;                             \
    const half* sWl = Wl + (size_t)n0 * Dh + (c) * 32;                             \
    _Pragma("unroll")                                                              \
    for (int rep = 0; rep < 2; ++rep) {                                            \
        int idx = rep * 512 + tid;         /* 0..1023: A 16B chunks */             \
        int r = idx >> 2, c8 = (idx & 3) * 8;                                      \
        CP_ASYNC16(ob + (uint32_t)(r * AS + c8) * 2, sA + (size_t)r * Dh + c8);    \
    }                                                                              \
    {                                                                              \
        int r = tid >> 2, c8 = (tid & 3) * 8;  /* 512 W chunks each */             \
        uint32_t doff = (uint32_t)(r * AS + c8) * 2;                               \
        CP_ASYNC16(ob + A_STG * 2 + doff,             sWh + (size_t)r * Dh + c8);  \
        CP_ASYNC16(ob + (A_STG + W_STG) * 2 + doff,   sWl + (size_t)r * Dh + c8);  \
    }                                                                              \
    CP_COMMIT();                                                                   \
} while (0)

    ISSUE(0);

    for (int c = 0; c < Dh / 32; ++c) {
        if (c + 1 < Dh / 32) { ISSUE(c + 1); CP_WAIT(1); }
        else                 { CP_WAIT(0); }
        __syncthreads();

        const uint32_t base = sbu + (uint32_t)(c & 1) * SPAN * 2;
        const uint32_t aB  = base;
        const uint32_t wHb = base + A_STG * 2;
        const uint32_t wLb = base + (A_STG + W_STG) * 2;

#pragma unroll
        for (int kk = 0; kk < 2; ++kk) {
            const int kb = kk * 16;

            uint32_t af[2][4];
#pragma unroll
            for (int mt = 0; mt < 2; ++mt) {
                const uint32_t off = (uint32_t)((warpM * 32 + mt * 16 + aRow) * AS + kb + aCol) * 2;
                ldm_x4(af[mt][0], af[mt][1], af[mt][2], af[mt][3], aB + off);
            }
#pragma unroll
            for (int P = 0; P < 4; ++P) {
                const uint32_t off = (uint32_t)((warpN * 64 + P * 16 + bRow) * AS + kb + bCol) * 2;
                uint32_t wh0, wh1, wh2, wh3, wl0, wl1, wl2, wl3;
                ldm_x4(wh0, wh1, wh2, wh3, wHb + off);
                ldm_x4(wl0, wl1, wl2, wl3, wLb + off);
                // interleaved: 4 independent accumulator chains, distance 4
                mma_f16(d[0][2*P],   af[0][0], af[0][1], af[0][2], af[0][3], wh0, wh1);
                mma_f16(d[1][2*P],   af[1][0], af[1][1], af[1][2], af[1][3], wh0, wh1);
                mma_f16(d[0][2*P+1], af[0][0], af[0][1], af[0][2], af[0][3], wh2, wh3);
                mma_f16(d[1][2*P+1], af[1][0], af[1][1], af[1][2], af[1][3], wh2, wh3);
                mma_f16(d[0][2*P],   af[0][0], af[0][1], af[0][2], af[0][3], wl0, wl1);
                mma_f16(d[1][2*P],   af[1][0], af[1][1], af[1][2], af[1][3], wl0, wl1);
                mma_f16(d[0][2*P+1], af[0][0], af[0][1], af[0][2], af[0][3], wl2, wl3);
                mma_f16(d[1][2*P+1], af[1][0], af[1][1], af[1][2], af[1][3], wl2, wl3);
            }
        }
        __syncthreads();
    }
#undef ISSUE

    const float scl = (mode == 3) ? 0.125f : 1.f;
#pragma unroll
    for (int mt = 0; mt < 2; ++mt) {
        const int mrow = m0 + warpM * 32 + mt * 16 + gid;
#pragma unroll
        for (int nt = 0; nt < 8; ++nt) {
            const int ncol = n0 + warpN * 64 + nt * 8 + tig * 2;
            const float b0 = bias[ncol], b1 = bias[ncol + 1];
            if (mode == 0) {
                *(float2*)&outF[(size_t)mrow * Dh + ncol] =
                    make_float2(d[mt][nt][0] + b0, d[mt][nt][1] + b1);
                *(float2*)&outF[(size_t)(mrow + 8) * Dh + ncol] =
                    make_float2(d[mt][nt][2] + b0, d[mt][nt][3] + b1);
            } else if (mode == 2) {
                const int h = ncol >> 6, dh0 = ncol & 63;
#pragma unroll
                for (int rr = 0; rr < 2; ++rr) {
                    const int m = mrow + rr * 8;
                    const int bb = m >> 11, s = m & 2047;
                    float v0 = d[mt][nt][rr * 2 + 0] + b0;
                    float v1 = d[mt][nt][rr * 2 + 1] + b1;
                    size_t base = ((size_t)(bb * NH + h) * HD) * SEQ + s;
                    bf16 h0 = __float2bfloat16_rn(v0);
                    bf16 h1 = __float2bfloat16_rn(v1);
                    outH[base + (size_t)dh0 * SEQ]       = h0;
                    outH[base + (size_t)(dh0 + 1) * SEQ] = h1;
                    outL[base + (size_t)dh0 * SEQ]       = __float2bfloat16_rn(v0 - __bfloat162float(h0));
                    outL[base + (size_t)(dh0 + 1) * SEQ] = __float2bfloat16_rn(v1 - __bfloat162float(h1));
                }
            } else {
                const int h = ncol >> 6, dh0 = ncol & 63;
#pragma unroll
                for (int rr = 0; rr < 2; ++rr) {
                    const int m = mrow + rr * 8;
                    const int bb = m >> 11, s = m & 2047;
                    float v0 = (d[mt][nt][rr * 2 + 0] + b0) * scl;
                    float v1 = (d[mt][nt][rr * 2 + 1] + b1) * scl;
                    uint32_t ph, pl;
                    split_pack(v0, v1, ph, pl);
                    size_t off = ((size_t)(bb * NH + h) * SEQ + s) * HD + dh0;
                    *(uint32_t*)&outH[off] = ph;
                    *(uint32_t*)&outL[off] = pl;
                }
            }
        }
    }
}

// ========= bf16x3 flash attention (mma.sync + ldmatrix + cp.async) ===========
#define AT_STRIDE 72                        // smem row stride in bf16 (64 + 8 pad)
#define AT_MAT    (64 * AT_STRIDE)          // one 64x64 matrix (bf16 units)
#define ATT_SPAN  (4 * AT_MAT)              // KH,KL,VH,VL per stage
#define ATT_SMEM  (2 * ATT_SPAN * 2)        // 73728 bytes

__global__ __launch_bounds__(256, 2) void attn_mma(
    const bf16* __restrict__ Qh, const bf16* __restrict__ Ql,
    const bf16* __restrict__ Kh, const bf16* __restrict__ Kl,
    const bf16* __restrict__ Vh, const bf16* __restrict__ Vl,
    half* __restrict__ ctx16)
{
    extern __shared__ bf16 asm_[];

    const int tid  = threadIdx.x;
    const int lane = tid & 31;
    const int wid  = tid >> 5;
    const int gid  = lane >> 2;
    const int tig  = lane & 3;
    const int bh   = blockIdx.y;
    const int q0   = blockIdx.x * 128;
    const int wq   = q0 + wid * 16;

    const int bRow = (lane & 7) + (lane >> 4) * 8;
    const int bCol = ((lane >> 3) & 1) * 8;
    const uint32_t smu = smem_u32(asm_);

    const bf16* bkh = Kh + (size_t)bh * SEQ * HD;
    const bf16* bkl = Kl + (size_t)bh * SEQ * HD;
    const bf16* bvh = Vh + (size_t)bh * SEQ * HD;   // [DH][SEQ]
    const bf16* bvl = Vl + (size_t)bh * SEQ * HD;

#define ISSUEA(t) do {                                                             \
    const int stg = (t) & 1;                                                       \
    const uint32_t ob = smu + (uint32_t)stg * ATT_SPAN * 2;                        \
    const bf16* pKH = bkh + (size_t)(t) * 64 * HD;                                 \
    const bf16* pKL = bkl + (size_t)(t) * 64 * HD;                                 \
    _Pragma("unroll")                                                              \
    for (int rep = 0; rep < 2; ++rep) {                                            \
        int idx = rep * 256 + tid;          /* 0..511 */                           \
        int row = idx >> 3, col8 = (idx & 7) * 8;                                  \
        uint32_t doff = (uint32_t)(row * AT_STRIDE + col8) * 2;                    \
        CP_ASYNC16(ob + doff,                 pKH + (size_t)row * HD + col8);      \
        CP_ASYNC16(ob + AT_MAT * 2 + doff,    pKL + (size_t)row * HD + col8);      \
        CP_ASYNC16(ob + 2 * AT_MAT * 2 + doff, bvh + (size_t)row * SEQ + (t) * 64 + col8); \
        CP_ASYNC16(ob + 3 * AT_MAT * 2 + doff, bvl + (size_t)row * SEQ + (t) * 64 + col8); \
    }                                                                              \
    CP_COMMIT();                                                                   \
} while (0)

    uint32_t qfh[4][4], qfl[4][4];
    {
        const bf16* bqh = Qh + ((size_t)bh * SEQ + wq) * HD;
        const bf16* bql = Ql + ((size_t)bh * SEQ + wq) * HD;
#pragma unroll
        for (int j = 0; j < 4; ++j) {
            int e0 = 16 * j + 2 * tig;
            qfh[j][0] = *(const uint32_t*)(bqh + (size_t)gid * HD + e0);
            qfh[j][1] = *(const uint32_t*)(bqh + (size_t)(gid + 8) * HD + e0);
            qfh[j][2] = *(const uint32_t*)(bqh + (size_t)gid * HD + e0 + 8);
            qfh[j][3] = *(const uint32_t*)(bqh + (size_t)(gid + 8) * HD + e0 + 8);
            qfl[j][0] = *(const uint32_t*)(bql + (size_t)gid * HD + e0);
            qfl[j][1] = *(const uint32_t*)(bql + (size_t)(gid + 8) * HD + e0);
            qfl[j][2] = *(const uint32_t*)(bql + (size_t)gid * HD + e0 + 8);
            qfl[j][3] = *(const uint32_t*)(bql + (size_t)(gid + 8) * HD + e0 + 8);
        }
    }

    float cx[8][4];
#pragma unroll
    for (int nt = 0; nt < 8; ++nt)
#pragma unroll
        for (int q = 0; q < 4; ++q) cx[nt][q] = 0.f;
    float m0 = -1e30f, m1 = -1e30f, l0 = 0.f, l1 = 0.f;

    ISSUEA(0);

    for (int kt = 0; kt < SEQ / 64; ++kt) {
        __syncthreads();
        if (kt + 1 < SEQ / 64) { ISSUEA(kt + 1); CP_WAIT(1); }
        else                   { CP_WAIT(0); }
        __syncthreads();

        const uint32_t sbase = smu + (uint32_t)(kt & 1) * ATT_SPAN * 2;
        const uint32_t uKH = sbase;
        const uint32_t uKL = sbase + AT_MAT * 2;
        const uint32_t uVH = sbase + 2 * AT_MAT * 2;
        const uint32_t uVL = sbase + 3 * AT_MAT * 2;

        float sacc[8][4];
#pragma unroll
        for (int nt = 0; nt < 8; ++nt)
#pragma unroll
            for (int q = 0; q < 4; ++q) sacc[nt][q] = 0.f;

#pragma unroll
        for (int j = 0; j < 4; ++j) {
            const uint32_t coff = (uint32_t)(16 * j + bCol) * 2;
#pragma unroll
            for (int P = 0; P < 4; ++P) {
                const uint32_t off = (uint32_t)((P * 16 + bRow) * AT_STRIDE) * 2 + coff;
                uint32_t kh0, kh1, kh2, kh3, kl0, kl1, kl2, kl3;
                ldm_x4(kh0, kh1, kh2, kh3, uKH + off);
                ldm_x4(kl0, kl1, kl2, kl3, uKL + off);
                // interleaved: two accumulator chains, distance 2
                mma_bf16(sacc[2*P],   qfh[j][0], qfh[j][1], qfh[j][2], qfh[j][3], kh0, kh1);
                mma_bf16(sacc[2*P+1], qfh[j][0], qfh[j][1], qfh[j][2], qfh[j][3], kh2, kh3);
                mma_bf16(sacc[2*P],   qfl[j][0], qfl[j][1], qfl[j][2], qfl[j][3], kh0, kh1);
                mma_bf16(sacc[2*P+1], qfl[j][0], qfl[j][1], qfl[j][2], qfl[j][3], kh2, kh3);
                mma_bf16(sacc[2*P],   qfh[j][0], qfh[j][1], qfh[j][2], qfh[j][3], kl0, kl1);
                mma_bf16(sacc[2*P+1], qfh[j][0], qfh[j][1], qfh[j][2], qfh[j][3], kl2, kl3);
            }
        }

        float mx0 = -1e30f, mx1 = -1e30f;
#pragma unroll
        for (int nt = 0; nt < 8; ++nt) {
            mx0 = fmaxf(mx0, fmaxf(sacc[nt][0], sacc[nt][1]));
            mx1 = fmaxf(mx1, fmaxf(sacc[nt][2], sacc[nt][3]));
        }
        mx0 = fmaxf(mx0, __shfl_xor_sync(0xffffffffu, mx0, 1));
        mx0 = fmaxf(mx0, __shfl_xor_sync(0xffffffffu, mx0, 2));
        mx1 = fmaxf(mx1, __shfl_xor_sync(0xffffffffu, mx1, 1));
        mx1 = fmaxf(mx1, __shfl_xor_sync(0xffffffffu, mx1, 2));
        float mn0 = fmaxf(m0, mx0), mn1 = fmaxf(m1, mx1);
        float r0 = __expf(m0 - mn0), r1 = __expf(m1 - mn1);
        m0 = mn0; m1 = mn1;

        float s0 = 0.f, s1 = 0.f;
#pragma unroll
        for (int nt = 0; nt < 8; ++nt) {
            float e0 = __expf(sacc[nt][0] - mn0);
            float e1 = __expf(sacc[nt][1] - mn0);
            float e2 = __expf(sacc[nt][2] - mn1);
            float e3 = __expf(sacc[nt][3] - mn1);
            sacc[nt][0] = e0; sacc[nt][1] = e1; sacc[nt][2] = e2; sacc[nt][3] = e3;
            s0 += e0 + e1; s1 += e2 + e3;
        }
        s0 += __shfl_xor_sync(0xffffffffu, s0, 1);
        s0 += __shfl_xor_sync(0xffffffffu, s0, 2);
        s1 += __shfl_xor_sync(0xffffffffu, s1, 1);
        s1 += __shfl_xor_sync(0xffffffffu, s1, 2);
        l0 = l0 * r0 + s0; l1 = l1 * r1 + s1;

#pragma unroll
        for (int nt = 0; nt < 8; ++nt) {
            cx[nt][0] *= r0; cx[nt][1] *= r0;
            cx[nt][2] *= r1; cx[nt][3] *= r1;
        }

#pragma unroll
        for (int j = 0; j < 4; ++j) {
            uint32_t pah[4], pal[4];
            split_pack(sacc[2*j][0],   sacc[2*j][1],   pah[0], pal[0]);
            split_pack(sacc[2*j][2],   sacc[2*j][3],   pah[1], pal[1]);
            split_pack(sacc[2*j+1][0], sacc[2*j+1][1], pah[2], pal[2]);
            split_pack(sacc[2*j+1][2], sacc[2*j+1][3], pah[3], pal[3]);
            const uint32_t coff = (uint32_t)(16 * j + bCol) * 2;
#pragma unroll
            for (int P = 0; P < 4; ++P) {
                const uint32_t off = (uint32_t)((P * 16 + bRow) * AT_STRIDE) * 2 + coff;
                uint32_t vh0, vh1, vh2, vh3, vl0_, vl1_, vl2_, vl3_;
                ldm_x4(vh0, vh1, vh2, vh3, uVH + off);
                ldm_x4(vl0_, vl1_, vl2_, vl3_, uVL + off);
                mma_bf16(cx[2*P],   pah[0], pah[1], pah[2], pah[3], vh0, vh1);
                mma_bf16(cx[2*P+1], pah[0], pah[1], pah[2], pah[3], vh2, vh3);
                mma_bf16(cx[2*P],   pal[0], pal[1], pal[2], pal[3], vh0, vh1);
                mma_bf16(cx[2*P+1], pal[0], pal[1], pal[2], pal[3], vh2, vh3);
                mma_bf16(cx[2*P],   pah[0], pah[1], pah[2], pah[3], vl0_, vl1_);
                mma_bf16(cx[2*P+1], pah[0], pah[1], pah[2], pah[3], vl2_, vl3_);
            }
        }
    }
#undef ISSUEA

    // ---- epilogue: ctx fp16 single, flat [M,1024] ----
    const int b = bh >> 4, h = bh & 15;
    const float inv0 = 1.f / l0, inv1 = 1.f / l1;
    const int row0 = wq + gid, row1 = wq + gid + 8;
#pragma unroll
    for (int nt = 0; nt < 8; ++nt) {
        const int dcol = h * HD + 8 * nt + 2 * tig;
        __half2 p0 = __floats2half2_rn(cx[nt][0] * inv0, cx[nt][1] * inv0);
        __half2 p1 = __floats2half2_rn(cx[nt][2] * inv1, cx[nt][3] * inv1);
        *(uint32_t*)&ctx16[(size_t)(b * SEQ + row0) * Dh + dcol] = *(uint32_t*)&p0;
        *(uint32_t*)&ctx16[(size_t)(b * SEQ + row1) * Dh + dcol] = *(uint32_t*)&p1;
    }
}

// ---------------- launch ------------------------------------------------------
extern "C" void kernel_launch(void* const* d_in, const int* in_sizes, int n_in,
                              void* d_out, int out_size)
{
    const float* X  = (const float*)d_in[0];
    const float* Wq = (const float*)d_in[1];
    const float* bq = (const float*)d_in[2];
    const float* Wk = (const float*)d_in[3];
    const float* bk = (const float*)d_in[4];
    const float* Wv = (const float*)d_in[5];
    const float* bv = (const float*)d_in[6];
    const float* Wo = (const float*)d_in[7];
    const float* bo = (const float*)d_in[8];
    float* out = (float*)d_out;

    half *x16, *wqh, *wql, *wkh, *wkl, *wvh, *wvl, *woh, *wol, *cx16;
    bf16 *qh, *ql, *kh, *kl, *vh, *vl;
    cudaGetSymbolAddress((void**)&x16, g_x16);
    cudaGetSymbolAddress((void**)&wqh, g_wq16h); cudaGetSymbolAddress((void**)&wql, g_wq16l);
    cudaGetSymbolAddress((void**)&wkh, g_wk16h); cudaGetSymbolAddress((void**)&wkl, g_wk16l);
    cudaGetSymbolAddress((void**)&wvh, g_wv16h); cudaGetSymbolAddress((void**)&wvl, g_wv16l);
    cudaGetSymbolAddress((void**)&woh, g_wo16h); cudaGetSymbolAddress((void**)&wol, g_wo16l);
    cudaGetSymbolAddress((void**)&qh,  g_qh);  cudaGetSymbolAddress((void**)&ql,  g_ql);
    cudaGetSymbolAddress((void**)&kh,  g_kh);  cudaGetSymbolAddress((void**)&kl,  g_kl);
    cudaGetSymbolAddress((void**)&vh,  g_vh);  cudaGetSymbolAddress((void**)&vl,  g_vl);
    cudaGetSymbolAddress((void**)&cx16, g_cx16);

    cudaFuncSetAttribute(gemm_f16x2, cudaFuncAttributeMaxDynamicSharedMemorySize, GEMM_SMEM);
    cudaFuncSetAttribute(attn_mma,   cudaFuncAttributeMaxDynamicSharedMemorySize, ATT_SMEM);

    dim3 thr(256);
    cvt16<<<(MROWS * Dh / 4 + 255) / 256, thr>>>(X, x16, MROWS * Dh / 4);
    splitW16<<<(Dh * Dh / 4 + 255) / 256, thr>>>(Wq, wqh, wql, Dh * Dh / 4);
    splitW16<<<(Dh * Dh / 4 + 255) / 256, thr>>>(Wk, wkh, wkl, Dh * Dh / 4);
    splitW16<<<(Dh * Dh / 4 + 255) / 256, thr>>>(Wv, wvh, wvl, Dh * Dh / 4);
    splitW16<<<(Dh * Dh / 4 + 255) / 256, thr>>>(Wo, woh, wol, Dh * Dh / 4);

    dim3 gthr(512);
    dim3 gg(Dh / 128, MROWS / 256);     // (8, 32)
    gemm_f16x2<<<gg, gthr, GEMM_SMEM>>>(x16, wqh, wql, bq, nullptr, qh, ql, 3);
    gemm_f16x2<<<gg, gthr, GEMM_SMEM>>>(x16, wkh, wkl, bk, nullptr, kh, kl, 1);
    gemm_f16x2<<<gg, gthr, GEMM_SMEM>>>(x16, wvh, wvl, bv, nullptr, vh, vl, 2);

    dim3 ga(SEQ / 128, BATCH * NH);     // (16, 64)
    attn_mma<<<ga, thr, ATT_SMEM>>>(qh, ql, kh, kl, vh, vl, cx16);

    gemm_f16x2<<<gg, gthr, GEMM_SMEM>>>(cx16, woh, wol, bo, out, nullptr, nullptr, 0);
}

// round 11
// speedup vs baseline: 7.3911x; 1.4168x over previous
#include <cuda_runtime.h>
#include <cuda_fp16.h>
#include <cstdint>
#include <math.h>

#define Dh     1024
#define NH     16
#define HD     64
#define SEQ    2048
#define BATCH  4
#define MROWS  8192   // BATCH*SEQ

// ---------------- scratch (static device globals; no allocation) -------------
__device__ half  g_x16[(size_t)MROWS * Dh];                 // X fp16 [M,1024]
__device__ half  g_wq16h[(size_t)Dh * Dh], g_wq16l[(size_t)Dh * Dh];
__device__ half  g_wk16h[(size_t)Dh * Dh], g_wk16l[(size_t)Dh * Dh];
__device__ half  g_wv16h[(size_t)Dh * Dh], g_wv16l[(size_t)Dh * Dh];
__device__ half  g_wo16h[(size_t)Dh * Dh], g_wo16l[(size_t)Dh * Dh];
__device__ half  g_q16[(size_t)MROWS * Dh];  // [B,H,S,DH] (pre-scaled by 0.125)
__device__ half  g_k16[(size_t)MROWS * Dh];  // [B,H,S,DH]
__device__ half  g_v16[(size_t)MROWS * Dh];  // [B,H,DH,S]  (transposed)
__device__ half  g_cx16[(size_t)MROWS * Dh];                // ctx fp16 [M,1024]

// ======================= helpers =============================================
__device__ __forceinline__ uint32_t smem_u32(const void* p) {
    uint32_t a;
    asm("{ .reg .u64 t; cvta.to.shared.u64 t, %1; cvt.u32.u64 %0, t; }" : "=r"(a) : "l"(p));
    return a;
}
__device__ __forceinline__ void mma_f16(float d[4],
                                        uint32_t a0, uint32_t a1, uint32_t a2, uint32_t a3,
                                        uint32_t b0, uint32_t b1) {
    asm("mma.sync.aligned.m16n8k16.row.col.f32.f16.f16.f32 "
        "{%0,%1,%2,%3}, {%4,%5,%6,%7}, {%8,%9}, {%0,%1,%2,%3};"
        : "+f"(d[0]), "+f"(d[1]), "+f"(d[2]), "+f"(d[3])
        : "r"(a0), "r"(a1), "r"(a2), "r"(a3), "r"(b0), "r"(b1));
}
__device__ __forceinline__ void ldm_x4(uint32_t& r0, uint32_t& r1, uint32_t& r2,
                                       uint32_t& r3, uint32_t addr) {
    asm volatile("ldmatrix.sync.aligned.m8n8.x4.shared.b16 {%0,%1,%2,%3}, [%4];"
        : "=r"(r0), "=r"(r1), "=r"(r2), "=r"(r3) : "r"(addr));
}
#define CP_ASYNC16(dst_u32, src_ptr) \
    asm volatile("cp.async.ca.shared.global [%0], [%1], 16;" :: "r"(dst_u32), "l"(src_ptr))
#define CP_COMMIT() asm volatile("cp.async.commit_group;" ::: "memory")
#define CP_WAIT(n)  asm volatile("cp.async.wait_group %0;" :: "n"(n) : "memory")

// ================== fp32 -> fp16 convert / split =============================
__global__ __launch_bounds__(256) void cvt16(const float* __restrict__ in,
                                             half* __restrict__ out, int n4)
{
    int i = blockIdx.x * 256 + threadIdx.x;
    if (i >= n4) return;
    float4 v = ((const float4*)in)[i];
    __half2 a = __floats2half2_rn(v.x, v.y);
    __half2 b = __floats2half2_rn(v.z, v.w);
    *(uint2*)&out[(size_t)i * 4] = make_uint2(*(uint32_t*)&a, *(uint32_t*)&b);
}

__global__ __launch_bounds__(256) void splitW16(const float* __restrict__ in,
                                                half* __restrict__ hi, half* __restrict__ lo,
                                                int n4)
{
    int i = blockIdx.x * 256 + threadIdx.x;
    if (i >= n4) return;
    float4 v = ((const float4*)in)[i];
    half h0 = __float2half_rn(v.x), h1 = __float2half_rn(v.y);
    half h2 = __float2half_rn(v.z), h3 = __float2half_rn(v.w);
    half l0 = __float2half_rn(v.x - __half2float(h0));
    half l1 = __float2half_rn(v.y - __half2float(h1));
    half l2 = __float2half_rn(v.z - __half2float(h2));
    half l3 = __float2half_rn(v.w - __half2float(h3));
    __half2 H0 = __halves2half2(h0, h1), H1 = __halves2half2(h2, h3);
    __half2 L0 = __halves2half2(l0, l1), L1 = __halves2half2(l2, l3);
    *(uint2*)&hi[(size_t)i * 4] = make_uint2(*(uint32_t*)&H0, *(uint32_t*)&H1);
    *(uint2*)&lo[(size_t)i * 4] = make_uint2(*(uint32_t*)&L0, *(uint32_t*)&L1);
}

// =========== fp16 x2 (W-split) mma.sync GEMM: 256x128 tile, 512 thr ==========
// out[m,n] = sum_k A[m,k]*(Wh+Wl)[n,k] + bias[n]
// mode 0: fp32 flat  mode 1: fp16 head layout  mode 2: fp16 transposed
// mode 3: fp16 head layout scaled 0.125
#define AS        40                       // smem row stride in fp16 (32 + 8 pad)
#define A_STG     (256 * AS)               // 10240 fp16
#define W_STG     (128 * AS)               // 5120 fp16
#define SPAN      (A_STG + 2 * W_STG)      // 20480 fp16
#define GEMM_SMEM (2 * SPAN * 2)           // 81920 bytes

__global__ __launch_bounds__(512, 1) void gemm_f16x2(
    const half* __restrict__ A,
    const half* __restrict__ Wh, const half* __restrict__ Wl,
    const float* __restrict__ bias, float* __restrict__ outF,
    half* __restrict__ outX, int mode)
{
    extern __shared__ half sb[];

    const int tid   = threadIdx.x;
    const int lane  = tid & 31;
    const int wid   = tid >> 5;
    const int warpM = wid >> 1;            // 0..7 -> 32-row slice of 256
    const int warpN = wid & 1;             // 0..1 -> 64-col slice
    const int m0 = blockIdx.y * 256;
    const int n0 = blockIdx.x * 128;
    const int gid = lane >> 2;
    const int tig = lane & 3;

    const int aRow = (lane & 7) + ((lane >> 3) & 1) * 8;
    const int aCol = (lane >> 4) * 8;
    const int bRow = (lane & 7) + (lane >> 4) * 8;
    const int bCol = ((lane >> 3) & 1) * 8;

    float d[2][8][4];
#pragma unroll
    for (int mt = 0; mt < 2; ++mt)
#pragma unroll
        for (int nt = 0; nt < 8; ++nt)
#pragma unroll
            for (int q = 0; q < 4; ++q) d[mt][nt][q] = 0.f;

    const uint32_t sbu = smem_u32(sb);

#define ISSUE(c) do {                                                              \
    const int stg = (c) & 1;                                                       \
    const uint32_t ob = sbu + (uint32_t)stg * SPAN * 2;                            \
    const half* sA  = A  + (size_t)m0 * Dh + (c) * 32;                             \
    const half* sWh = Wh + (size_t)n0 * Dh + (c) * 32;                             \
    const half* sWl = Wl + (size_t)n0 * Dh + (c) * 32;                             \
    _Pragma("unroll")                                                              \
    for (int rep = 0; rep < 2; ++rep) {                                            \
        int idx = rep * 512 + tid;         /* 0..1023: A 16B chunks */             \
        int r = idx >> 2, c8 = (idx & 3) * 8;                                      \
        CP_ASYNC16(ob + (uint32_t)(r * AS + c8) * 2, sA + (size_t)r * Dh + c8);    \
    }                                                                              \
    {                                                                              \
        int r = tid >> 2, c8 = (tid & 3) * 8;  /* 512 W chunks each */             \
        uint32_t doff = (uint32_t)(r * AS + c8) * 2;                               \
        CP_ASYNC16(ob + A_STG * 2 + doff,             sWh + (size_t)r * Dh + c8);  \
        CP_ASYNC16(ob + (A_STG + W_STG) * 2 + doff,   sWl + (size_t)r * Dh + c8);  \
    }                                                                              \
    CP_COMMIT();                                                                   \
} while (0)

    ISSUE(0);

    for (int c = 0; c < Dh / 32; ++c) {
        if (c + 1 < Dh / 32) { ISSUE(c + 1); CP_WAIT(1); }
        else                 { CP_WAIT(0); }
        __syncthreads();

        const uint32_t base = sbu + (uint32_t)(c & 1) * SPAN * 2;
        const uint32_t aB  = base;
        const uint32_t wHb = base + A_STG * 2;
        const uint32_t wLb = base + (A_STG + W_STG) * 2;

#pragma unroll
        for (int kk = 0; kk < 2; ++kk) {
            const int kb = kk * 16;

            uint32_t af[2][4];
#pragma unroll
            for (int mt = 0; mt < 2; ++mt) {
                const uint32_t off = (uint32_t)((warpM * 32 + mt * 16 + aRow) * AS + kb + aCol) * 2;
                ldm_x4(af[mt][0], af[mt][1], af[mt][2], af[mt][3], aB + off);
            }
#pragma unroll
            for (int P = 0; P < 4; ++P) {
                const uint32_t off = (uint32_t)((warpN * 64 + P * 16 + bRow) * AS + kb + bCol) * 2;
                uint32_t wh0, wh1, wh2, wh3, wl0, wl1, wl2, wl3;
                ldm_x4(wh0, wh1, wh2, wh3, wHb + off);
                ldm_x4(wl0, wl1, wl2, wl3, wLb + off);
                mma_f16(d[0][2*P],   af[0][0], af[0][1], af[0][2], af[0][3], wh0, wh1);
                mma_f16(d[1][2*P],   af[1][0], af[1][1], af[1][2], af[1][3], wh0, wh1);
                mma_f16(d[0][2*P+1], af[0][0], af[0][1], af[0][2], af[0][3], wh2, wh3);
                mma_f16(d[1][2*P+1], af[1][0], af[1][1], af[1][2], af[1][3], wh2, wh3);
                mma_f16(d[0][2*P],   af[0][0], af[0][1], af[0][2], af[0][3], wl0, wl1);
                mma_f16(d[1][2*P],   af[1][0], af[1][1], af[1][2], af[1][3], wl0, wl1);
                mma_f16(d[0][2*P+1], af[0][0], af[0][1], af[0][2], af[0][3], wl2, wl3);
                mma_f16(d[1][2*P+1], af[1][0], af[1][1], af[1][2], af[1][3], wl2, wl3);
            }
        }
        __syncthreads();
    }
#undef ISSUE

    const float scl = (mode == 3) ? 0.125f : 1.f;
#pragma unroll
    for (int mt = 0; mt < 2; ++mt) {
        const int mrow = m0 + warpM * 32 + mt * 16 + gid;
#pragma unroll
        for (int nt = 0; nt < 8; ++nt) {
            const int ncol = n0 + warpN * 64 + nt * 8 + tig * 2;
            const float b0 = bias[ncol], b1 = bias[ncol + 1];
            if (mode == 0) {
                *(float2*)&outF[(size_t)mrow * Dh + ncol] =
                    make_float2(d[mt][nt][0] + b0, d[mt][nt][1] + b1);
                *(float2*)&outF[(size_t)(mrow + 8) * Dh + ncol] =
                    make_float2(d[mt][nt][2] + b0, d[mt][nt][3] + b1);
            } else if (mode == 2) {
                // transposed [B,H,DH,S], fp16 single
                const int h = ncol >> 6, dh0 = ncol & 63;
#pragma unroll
                for (int rr = 0; rr < 2; ++rr) {
                    const int m = mrow + rr * 8;
                    const int bb = m >> 11, s = m & 2047;
                    size_t base = ((size_t)(bb * NH + h) * HD) * SEQ + s;
                    outX[base + (size_t)dh0 * SEQ]       = __float2half_rn(d[mt][nt][rr * 2 + 0] + b0);
                    outX[base + (size_t)(dh0 + 1) * SEQ] = __float2half_rn(d[mt][nt][rr * 2 + 1] + b1);
                }
            } else {
                // head layout [B,H,S,DH], fp16 single, optional scale
                const int h = ncol >> 6, dh0 = ncol & 63;
#pragma unroll
                for (int rr = 0; rr < 2; ++rr) {
                    const int m = mrow + rr * 8;
                    const int bb = m >> 11, s = m & 2047;
                    __half2 pk = __floats2half2_rn((d[mt][nt][rr * 2 + 0] + b0) * scl,
                                                   (d[mt][nt][rr * 2 + 1] + b1) * scl);
                    *(uint32_t*)&outX[((size_t)(bb * NH + h) * SEQ + s) * HD + dh0] = *(uint32_t*)&pk;
                }
            }
        }
    }
}

// ======== fp16 x1 flash attention (mma.sync + ldmatrix + cp.async) ===========
#define AT_STRIDE 72                        // smem row stride in fp16 (64 + 8 pad)
#define AT_MAT    (64 * AT_STRIDE)          // one 64x64 matrix (fp16 units)
#define ATT_SPAN  (2 * AT_MAT)              // K, V per stage
#define ATT_SMEM  (2 * ATT_SPAN * 2)        // 36864 bytes

__global__ __launch_bounds__(256, 2) void attn_mma(
    const half* __restrict__ Q, const half* __restrict__ K,
    const half* __restrict__ V, half* __restrict__ ctx16)
{
    extern __shared__ half asm_[];

    const int tid  = threadIdx.x;
    const int lane = tid & 31;
    const int wid  = tid >> 5;
    const int gid  = lane >> 2;
    const int tig  = lane & 3;
    const int bh   = blockIdx.y;
    const int q0   = blockIdx.x * 128;
    const int wq   = q0 + wid * 16;

    const int bRow = (lane & 7) + (lane >> 4) * 8;
    const int bCol = ((lane >> 3) & 1) * 8;
    const uint32_t smu = smem_u32(asm_);

    const half* bK = K + (size_t)bh * SEQ * HD;
    const half* bV = V + (size_t)bh * SEQ * HD;   // [DH][SEQ]

#define ISSUEA(t) do {                                                             \
    const int stg = (t) & 1;                                                       \
    const uint32_t ob = smu + (uint32_t)stg * ATT_SPAN * 2;                        \
    const half* pK = bK + (size_t)(t) * 64 * HD;                                   \
    _Pragma("unroll")                                                              \
    for (int rep = 0; rep < 2; ++rep) {                                            \
        int idx = rep * 256 + tid;          /* 0..511 */                           \
        int row = idx >> 3, col8 = (idx & 7) * 8;                                  \
        uint32_t doff = (uint32_t)(row * AT_STRIDE + col8) * 2;                    \
        CP_ASYNC16(ob + doff,              pK + (size_t)row * HD + col8);          \
        CP_ASYNC16(ob + AT_MAT * 2 + doff, bV + (size_t)row * SEQ + (t) * 64 + col8); \
    }                                                                              \
    CP_COMMIT();                                                                   \
} while (0)

    uint32_t qf[4][4];
    {
        const half* bq = Q + ((size_t)bh * SEQ + wq) * HD;
#pragma unroll
        for (int j = 0; j < 4; ++j) {
            int e0 = 16 * j + 2 * tig;
            qf[j][0] = *(const uint32_t*)(bq + (size_t)gid * HD + e0);
            qf[j][1] = *(const uint32_t*)(bq + (size_t)(gid + 8) * HD + e0);
            qf[j][2] = *(const uint32_t*)(bq + (size_t)gid * HD + e0 + 8);
            qf[j][3] = *(const uint32_t*)(bq + (size_t)(gid + 8) * HD + e0 + 8);
        }
    }

    float cx[8][4];
#pragma unroll
    for (int nt = 0; nt < 8; ++nt)
#pragma unroll
        for (int q = 0; q < 4; ++q) cx[nt][q] = 0.f;
    float m0 = -1e30f, m1 = -1e30f, l0 = 0.f, l1 = 0.f;

    ISSUEA(0);

    for (int kt = 0; kt < SEQ / 64; ++kt) {
        __syncthreads();
        if (kt + 1 < SEQ / 64) { ISSUEA(kt + 1); CP_WAIT(1); }
        else                   { CP_WAIT(0); }
        __syncthreads();

        const uint32_t sbase = smu + (uint32_t)(kt & 1) * ATT_SPAN * 2;
        const uint32_t uK = sbase;
        const uint32_t uV = sbase + AT_MAT * 2;

        float sacc[8][4];
#pragma unroll
        for (int nt = 0; nt < 8; ++nt)
#pragma unroll
            for (int q = 0; q < 4; ++q) sacc[nt][q] = 0.f;

#pragma unroll
        for (int j = 0; j < 4; ++j) {
            const uint32_t coff = (uint32_t)(16 * j + bCol) * 2;
#pragma unroll
            for (int P = 0; P < 4; ++P) {
                const uint32_t off = (uint32_t)((P * 16 + bRow) * AT_STRIDE) * 2 + coff;
                uint32_t k0, k1, k2, k3;
                ldm_x4(k0, k1, k2, k3, uK + off);
                mma_f16(sacc[2*P],   qf[j][0], qf[j][1], qf[j][2], qf[j][3], k0, k1);
                mma_f16(sacc[2*P+1], qf[j][0], qf[j][1], qf[j][2], qf[j][3], k2, k3);
            }
        }

        float mx0 = -1e30f, mx1 = -1e30f;
#pragma unroll
        for (int nt = 0; nt < 8; ++nt) {
            mx0 = fmaxf(mx0, fmaxf(sacc[nt][0], sacc[nt][1]));
            mx1 = fmaxf(mx1, fmaxf(sacc[nt][2], sacc[nt][3]));
        }
        mx0 = fmaxf(mx0, __shfl_xor_sync(0xffffffffu, mx0, 1));
        mx0 = fmaxf(mx0, __shfl_xor_sync(0xffffffffu, mx0, 2));
        mx1 = fmaxf(mx1, __shfl_xor_sync(0xffffffffu, mx1, 1));
        mx1 = fmaxf(mx1, __shfl_xor_sync(0xffffffffu, mx1, 2));
        float mn0 = fmaxf(m0, mx0), mn1 = fmaxf(m1, mx1);
        float r0 = __expf(m0 - mn0), r1 = __expf(m1 - mn1);
        m0 = mn0; m1 = mn1;

        float s0 = 0.f, s1 = 0.f;
#pragma unroll
        for (int nt = 0; nt < 8; ++nt) {
            float e0 = __expf(sacc[nt][0] - mn0);
            float e1 = __expf(sacc[nt][1] - mn0);
            float e2 = __expf(sacc[nt][2] - mn1);
            float e3 = __expf(sacc[nt][3] - mn1);
            sacc[nt][0] = e0; sacc[nt][1] = e1; sacc[nt][2] = e2; sacc[nt][3] = e3;
            s0 += e0 + e1; s1 += e2 + e3;
        }
        s0 += __shfl_xor_sync(0xffffffffu, s0, 1);
        s0 += __shfl_xor_sync(0xffffffffu, s0, 2);
        s1 += __shfl_xor_sync(0xffffffffu, s1, 1);
        s1 += __shfl_xor_sync(0xffffffffu, s1, 2);
        l0 = l0 * r0 + s0; l1 = l1 * r1 + s1;

#pragma unroll
        for (int nt = 0; nt < 8; ++nt) {
            cx[nt][0] *= r0; cx[nt][1] *= r0;
            cx[nt][2] *= r1; cx[nt][3] *= r1;
        }

#pragma unroll
        for (int j = 0; j < 4; ++j) {
            uint32_t pa[4];
            __half2 t0 = __floats2half2_rn(sacc[2*j][0],   sacc[2*j][1]);
            __half2 t1 = __floats2half2_rn(sacc[2*j][2],   sacc[2*j][3]);
            __half2 t2 = __floats2half2_rn(sacc[2*j+1][0], sacc[2*j+1][1]);
            __half2 t3 = __floats2half2_rn(sacc[2*j+1][2], sacc[2*j+1][3]);
            pa[0] = *(uint32_t*)&t0; pa[1] = *(uint32_t*)&t1;
            pa[2] = *(uint32_t*)&t2; pa[3] = *(uint32_t*)&t3;
            const uint32_t coff = (uint32_t)(16 * j + bCol) * 2;
#pragma unroll
            for (int P = 0; P < 4; ++P) {
                const uint32_t off = (uint32_t)((P * 16 + bRow) * AT_STRIDE) * 2 + coff;
                uint32_t v0, v1, v2, v3;
                ldm_x4(v0, v1, v2, v3, uV + off);
                mma_f16(cx[2*P],   pa[0], pa[1], pa[2], pa[3], v0, v1);
                mma_f16(cx[2*P+1], pa[0], pa[1], pa[2], pa[3], v2, v3);
            }
        }
    }
#undef ISSUEA

    // ---- epilogue: ctx fp16 single, flat [M,1024] ----
    const int b = bh >> 4, h = bh & 15;
    const float inv0 = 1.f / l0, inv1 = 1.f / l1;
    const int row0 = wq + gid, row1 = wq + gid + 8;
#pragma unroll
    for (int nt = 0; nt < 8; ++nt) {
        const int dcol = h * HD + 8 * nt + 2 * tig;
        __half2 p0 = __floats2half2_rn(cx[nt][0] * inv0, cx[nt][1] * inv0);
        __half2 p1 = __floats2half2_rn(cx[nt][2] * inv1, cx[nt][3] * inv1);
        *(uint32_t*)&ctx16[(size_t)(b * SEQ + row0) * Dh + dcol] = *(uint32_t*)&p0;
        *(uint32_t*)&ctx16[(size_t)(b * SEQ + row1) * Dh + dcol] = *(uint32_t*)&p1;
    }
}

// ---------------- launch ------------------------------------------------------
extern "C" void kernel_launch(void* const* d_in, const int* in_sizes, int n_in,
                              void* d_out, int out_size)
{
    const float* X  = (const float*)d_in[0];
    const float* Wq = (const float*)d_in[1];
    const float* bq = (const float*)d_in[2];
    const float* Wk = (const float*)d_in[3];
    const float* bk = (const float*)d_in[4];
    const float* Wv = (const float*)d_in[5];
    const float* bv = (const float*)d_in[6];
    const float* Wo = (const float*)d_in[7];
    const float* bo = (const float*)d_in[8];
    float* out = (float*)d_out;

    half *x16, *wqh, *wql, *wkh, *wkl, *wvh, *wvl, *woh, *wol;
    half *q16, *k16, *v16, *cx16;
    cudaGetSymbolAddress((void**)&x16, g_x16);
    cudaGetSymbolAddress((void**)&wqh, g_wq16h); cudaGetSymbolAddress((void**)&wql, g_wq16l);
    cudaGetSymbolAddress((void**)&wkh, g_wk16h); cudaGetSymbolAddress((void**)&wkl, g_wk16l);
    cudaGetSymbolAddress((void**)&wvh, g_wv16h); cudaGetSymbolAddress((void**)&wvl, g_wv16l);
    cudaGetSymbolAddress((void**)&woh, g_wo16h); cudaGetSymbolAddress((void**)&wol, g_wo16l);
    cudaGetSymbolAddress((void**)&q16, g_q16);
    cudaGetSymbolAddress((void**)&k16, g_k16);
    cudaGetSymbolAddress((void**)&v16, g_v16);
    cudaGetSymbolAddress((void**)&cx16, g_cx16);

    cudaFuncSetAttribute(gemm_f16x2, cudaFuncAttributeMaxDynamicSharedMemorySize, GEMM_SMEM);
    cudaFuncSetAttribute(attn_mma,   cudaFuncAttributeMaxDynamicSharedMemorySize, ATT_SMEM);

    dim3 thr(256);
    cvt16<<<(MROWS * Dh / 4 + 255) / 256, thr>>>(X, x16, MROWS * Dh / 4);
    splitW16<<<(Dh * Dh / 4 + 255) / 256, thr>>>(Wq, wqh, wql, Dh * Dh / 4);
    splitW16<<<(Dh * Dh / 4 + 255) / 256, thr>>>(Wk, wkh, wkl, Dh * Dh / 4);
    splitW16<<<(Dh * Dh / 4 + 255) / 256, thr>>>(Wv, wvh, wvl, Dh * Dh / 4);
    splitW16<<<(Dh * Dh / 4 + 255) / 256, thr>>>(Wo, woh, wol, Dh * Dh / 4);

    dim3 gthr(512);
    dim3 gg(Dh / 128, MROWS / 256);     // (8, 32)
    gemm_f16x2<<<gg, gthr, GEMM_SMEM>>>(x16, wqh, wql, bq, nullptr, q16, 3);
    gemm_f16x2<<<gg, gthr, GEMM_SMEM>>>(x16, wkh, wkl, bk, nullptr, k16, 1);
    gemm_f16x2<<<gg, gthr, GEMM_SMEM>>>(x16, wvh, wvl, bv, nullptr, v16, 2);

    dim3 ga(SEQ / 128, BATCH * NH);     // (16, 64)
    attn_mma<<<ga, thr, ATT_SMEM>>>(q16, k16, v16, cx16);

    gemm_f16x2<<<gg, gthr, GEMM_SMEM>>>(cx16, woh, wol, bo, out, nullptr, 0);
}

// round 12
// speedup vs baseline: 9.4714x; 1.2814x over previous
#include <cuda_runtime.h>
#include <cuda_fp16.h>
#include <cstdint>
#include <math.h>

#define Dh     1024
#define NH     16
#define HD     64
#define SEQ    2048
#define BATCH  4
#define MROWS  8192   // BATCH*SEQ

// ---------------- scratch (static device globals; no allocation) -------------
__device__ half  g_x16[(size_t)MROWS * Dh];                 // X fp16 [M,1024]
__device__ half  g_wq16[(size_t)Dh * Dh];
__device__ half  g_wk16[(size_t)Dh * Dh];
__device__ half  g_wv16[(size_t)Dh * Dh];
__device__ half  g_wo16[(size_t)Dh * Dh];
__device__ half  g_q16[(size_t)MROWS * Dh];  // [B,H,S,DH] (pre-scaled by 0.125)
__device__ half  g_k16[(size_t)MROWS * Dh];  // [B,H,S,DH]
__device__ half  g_v16[(size_t)MROWS * Dh];  // [B,H,DH,S]  (transposed)
__device__ half  g_cx16[(size_t)MROWS * Dh];                // ctx fp16 [M,1024]

// ======================= helpers =============================================
__device__ __forceinline__ uint32_t smem_u32(const void* p) {
    uint32_t a;
    asm("{ .reg .u64 t; cvta.to.shared.u64 t, %1; cvt.u32.u64 %0, t; }" : "=r"(a) : "l"(p));
    return a;
}
__device__ __forceinline__ void mma_f16(float d[4],
                                        uint32_t a0, uint32_t a1, uint32_t a2, uint32_t a3,
                                        uint32_t b0, uint32_t b1) {
    asm("mma.sync.aligned.m16n8k16.row.col.f32.f16.f16.f32 "
        "{%0,%1,%2,%3}, {%4,%5,%6,%7}, {%8,%9}, {%0,%1,%2,%3};"
        : "+f"(d[0]), "+f"(d[1]), "+f"(d[2]), "+f"(d[3])
        : "r"(a0), "r"(a1), "r"(a2), "r"(a3), "r"(b0), "r"(b1));
}
__device__ __forceinline__ void ldm_x4(uint32_t& r0, uint32_t& r1, uint32_t& r2,
                                       uint32_t& r3, uint32_t addr) {
    asm volatile("ldmatrix.sync.aligned.m8n8.x4.shared.b16 {%0,%1,%2,%3}, [%4];"
        : "=r"(r0), "=r"(r1), "=r"(r2), "=r"(r3) : "r"(addr));
}
#define CP_ASYNC16(dst_u32, src_ptr) \
    asm volatile("cp.async.ca.shared.global [%0], [%1], 16;" :: "r"(dst_u32), "l"(src_ptr))
#define CP_COMMIT() asm volatile("cp.async.commit_group;" ::: "memory")
#define CP_WAIT(n)  asm volatile("cp.async.wait_group %0;" :: "n"(n) : "memory")

// ================== fp32 -> fp16 convert =====================================
__global__ __launch_bounds__(256) void cvt16(const float* __restrict__ in,
                                             half* __restrict__ out, int n4)
{
    int i = blockIdx.x * 256 + threadIdx.x;
    if (i >= n4) return;
    float4 v = ((const float4*)in)[i];
    __half2 a = __floats2half2_rn(v.x, v.y);
    __half2 b = __floats2half2_rn(v.z, v.w);
    *(uint2*)&out[(size_t)i * 4] = make_uint2(*(uint32_t*)&a, *(uint32_t*)&b);
}

// ============== fp16 x1 mma.sync GEMM: 256x128 tile, 512 thr =================
// out[m,n] = sum_k A[m,k]*W[n,k] + bias[n]
// mode 0: fp32 flat  mode 1: fp16 head layout  mode 2: fp16 transposed
// mode 3: fp16 head layout scaled 0.125
#define AS        40                       // smem row stride in fp16 (32 + 8 pad)
#define A_STG     (256 * AS)               // 10240 fp16
#define W_STG     (128 * AS)               // 5120 fp16
#define SPAN      (A_STG + W_STG)          // 15360 fp16
#define GEMM_SMEM (2 * SPAN * 2)           // 61440 bytes

__global__ __launch_bounds__(512, 1) void gemm_f16(
    const half* __restrict__ A, const half* __restrict__ W,
    const float* __restrict__ bias, float* __restrict__ outF,
    half* __restrict__ outX, int mode)
{
    extern __shared__ half sb[];

    const int tid   = threadIdx.x;
    const int lane  = tid & 31;
    const int wid   = tid >> 5;
    const int warpM = wid >> 1;            // 0..7 -> 32-row slice of 256
    const int warpN = wid & 1;             // 0..1 -> 64-col slice
    const int m0 = blockIdx.y * 256;
    const int n0 = blockIdx.x * 128;
    const int gid = lane >> 2;
    const int tig = lane & 3;

    const int aRow = (lane & 7) + ((lane >> 3) & 1) * 8;
    const int aCol = (lane >> 4) * 8;
    const int bRow = (lane & 7) + (lane >> 4) * 8;
    const int bCol = ((lane >> 3) & 1) * 8;

    float d[2][8][4];
#pragma unroll
    for (int mt = 0; mt < 2; ++mt)
#pragma unroll
        for (int nt = 0; nt < 8; ++nt)
#pragma unroll
            for (int q = 0; q < 4; ++q) d[mt][nt][q] = 0.f;

    const uint32_t sbu = smem_u32(sb);

#define ISSUE(c) do {                                                              \
    const int stg = (c) & 1;                                                       \
    const uint32_t ob = sbu + (uint32_t)stg * SPAN * 2;                            \
    const half* sA = A + (size_t)m0 * Dh + (c) * 32;                               \
    const half* sW = W + (size_t)n0 * Dh + (c) * 32;                               \
    _Pragma("unroll")                                                              \
    for (int rep = 0; rep < 2; ++rep) {                                            \
        int idx = rep * 512 + tid;         /* 0..1023: A 16B chunks */             \
        int r = idx >> 2, c8 = (idx & 3) * 8;                                      \
        CP_ASYNC16(ob + (uint32_t)(r * AS + c8) * 2, sA + (size_t)r * Dh + c8);    \
    }                                                                              \
    {                                                                              \
        int r = tid >> 2, c8 = (tid & 3) * 8;  /* 512 W chunks */                  \
        CP_ASYNC16(ob + A_STG * 2 + (uint32_t)(r * AS + c8) * 2,                   \
                   sW + (size_t)r * Dh + c8);                                      \
    }                                                                              \
    CP_COMMIT();                                                                   \
} while (0)

    ISSUE(0);

    for (int c = 0; c < Dh / 32; ++c) {
        if (c + 1 < Dh / 32) { ISSUE(c + 1); CP_WAIT(1); }
        else                 { CP_WAIT(0); }
        __syncthreads();

        const uint32_t base = sbu + (uint32_t)(c & 1) * SPAN * 2;
        const uint32_t aB = base;
        const uint32_t wB = base + A_STG * 2;

#pragma unroll
        for (int kk = 0; kk < 2; ++kk) {
            const int kb = kk * 16;

            uint32_t af[2][4];
#pragma unroll
            for (int mt = 0; mt < 2; ++mt) {
                const uint32_t off = (uint32_t)((warpM * 32 + mt * 16 + aRow) * AS + kb + aCol) * 2;
                ldm_x4(af[mt][0], af[mt][1], af[mt][2], af[mt][3], aB + off);
            }
#pragma unroll
            for (int P = 0; P < 4; ++P) {
                const uint32_t off = (uint32_t)((warpN * 64 + P * 16 + bRow) * AS + kb + bCol) * 2;
                uint32_t w0, w1, w2, w3;
                ldm_x4(w0, w1, w2, w3, wB + off);
                mma_f16(d[0][2*P],   af[0][0], af[0][1], af[0][2], af[0][3], w0, w1);
                mma_f16(d[1][2*P],   af[1][0], af[1][1], af[1][2], af[1][3], w0, w1);
                mma_f16(d[0][2*P+1], af[0][0], af[0][1], af[0][2], af[0][3], w2, w3);
                mma_f16(d[1][2*P+1], af[1][0], af[1][1], af[1][2], af[1][3], w2, w3);
            }
        }
        __syncthreads();
    }
#undef ISSUE

    const float scl = (mode == 3) ? 0.125f : 1.f;
#pragma unroll
    for (int mt = 0; mt < 2; ++mt) {
        const int mrow = m0 + warpM * 32 + mt * 16 + gid;
#pragma unroll
        for (int nt = 0; nt < 8; ++nt) {
            const int ncol = n0 + warpN * 64 + nt * 8 + tig * 2;
            const float b0 = bias[ncol], b1 = bias[ncol + 1];
            if (mode == 0) {
                *(float2*)&outF[(size_t)mrow * Dh + ncol] =
                    make_float2(d[mt][nt][0] + b0, d[mt][nt][1] + b1);
                *(float2*)&outF[(size_t)(mrow + 8) * Dh + ncol] =
                    make_float2(d[mt][nt][2] + b0, d[mt][nt][3] + b1);
            } else if (mode == 2) {
                // transposed [B,H,DH,S], fp16 single
                const int h = ncol >> 6, dh0 = ncol & 63;
#pragma unroll
                for (int rr = 0; rr < 2; ++rr) {
                    const int m = mrow + rr * 8;
                    const int bb = m >> 11, s = m & 2047;
                    size_t base = ((size_t)(bb * NH + h) * HD) * SEQ + s;
                    outX[base + (size_t)dh0 * SEQ]       = __float2half_rn(d[mt][nt][rr * 2 + 0] + b0);
                    outX[base + (size_t)(dh0 + 1) * SEQ] = __float2half_rn(d[mt][nt][rr * 2 + 1] + b1);
                }
            } else {
                // head layout [B,H,S,DH], fp16 single, optional scale
                const int h = ncol >> 6, dh0 = ncol & 63;
#pragma unroll
                for (int rr = 0; rr < 2; ++rr) {
                    const int m = mrow + rr * 8;
                    const int bb = m >> 11, s = m & 2047;
                    __half2 pk = __floats2half2_rn((d[mt][nt][rr * 2 + 0] + b0) * scl,
                                                   (d[mt][nt][rr * 2 + 1] + b1) * scl);
                    *(uint32_t*)&outX[((size_t)(bb * NH + h) * SEQ + s) * HD + dh0] = *(uint32_t*)&pk;
                }
            }
        }
    }
}

// ======== fp16 x1 flash attention (mma.sync + ldmatrix + cp.async) ===========
#define AT_STRIDE 72                        // smem row stride in fp16 (64 + 8 pad)
#define AT_MAT    (64 * AT_STRIDE)          // one 64x64 matrix (fp16 units)
#define ATT_SPAN  (2 * AT_MAT)              // K, V per stage
#define ATT_SMEM  (2 * ATT_SPAN * 2)        // 36864 bytes

__global__ __launch_bounds__(256, 2) void attn_mma(
    const half* __restrict__ Q, const half* __restrict__ K,
    const half* __restrict__ V, half* __restrict__ ctx16)
{
    extern __shared__ half asm_[];

    const int tid  = threadIdx.x;
    const int lane = tid & 31;
    const int wid  = tid >> 5;
    const int gid  = lane >> 2;
    const int tig  = lane & 3;
    const int bh   = blockIdx.y;
    const int q0   = blockIdx.x * 128;
    const int wq   = q0 + wid * 16;

    const int bRow = (lane & 7) + (lane >> 4) * 8;
    const int bCol = ((lane >> 3) & 1) * 8;
    const uint32_t smu = smem_u32(asm_);

    const half* bK = K + (size_t)bh * SEQ * HD;
    const half* bV = V + (size_t)bh * SEQ * HD;   // [DH][SEQ]

#define ISSUEA(t) do {                                                             \
    const int stg = (t) & 1;                                                       \
    const uint32_t ob = smu + (uint32_t)stg * ATT_SPAN * 2;                        \
    const half* pK = bK + (size_t)(t) * 64 * HD;                                   \
    _Pragma("unroll")                                                              \
    for (int rep = 0; rep < 2; ++rep) {                                            \
        int idx = rep * 256 + tid;          /* 0..511 */                           \
        int row = idx >> 3, col8 = (idx & 7) * 8;                                  \
        uint32_t doff = (uint32_t)(row * AT_STRIDE + col8) * 2;                    \
        CP_ASYNC16(ob + doff,              pK + (size_t)row * HD + col8);          \
        CP_ASYNC16(ob + AT_MAT * 2 + doff, bV + (size_t)row * SEQ + (t) * 64 + col8); \
    }                                                                              \
    CP_COMMIT();                                                                   \
} while (0)

    uint32_t qf[4][4];
    {
        const half* bq = Q + ((size_t)bh * SEQ + wq) * HD;
#pragma unroll
        for (int j = 0; j < 4; ++j) {
            int e0 = 16 * j + 2 * tig;
            qf[j][0] = *(const uint32_t*)(bq + (size_t)gid * HD + e0);
            qf[j][1] = *(const uint32_t*)(bq + (size_t)(gid + 8) * HD + e0);
            qf[j][2] = *(const uint32_t*)(bq + (size_t)gid * HD + e0 + 8);
            qf[j][3] = *(const uint32_t*)(bq + (size_t)(gid + 8) * HD + e0 + 8);
        }
    }

    float cx[8][4];
#pragma unroll
    for (int nt = 0; nt < 8; ++nt)
#pragma unroll
        for (int q = 0; q < 4; ++q) cx[nt][q] = 0.f;
    float m0 = -1e30f, m1 = -1e30f, l0 = 0.f, l1 = 0.f;

    ISSUEA(0);

    for (int kt = 0; kt < SEQ / 64; ++kt) {
        __syncthreads();
        if (kt + 1 < SEQ / 64) { ISSUEA(kt + 1); CP_WAIT(1); }
        else                   { CP_WAIT(0); }
        __syncthreads();

        const uint32_t sbase = smu + (uint32_t)(kt & 1) * ATT_SPAN * 2;
        const uint32_t uK = sbase;
        const uint32_t uV = sbase + AT_MAT * 2;

        float sacc[8][4];
#pragma unroll
        for (int nt = 0; nt < 8; ++nt)
#pragma unroll
            for (int q = 0; q < 4; ++q) sacc[nt][q] = 0.f;

#pragma unroll
        for (int j = 0; j < 4; ++j) {
            const uint32_t coff = (uint32_t)(16 * j + bCol) * 2;
#pragma unroll
            for (int P = 0; P < 4; ++P) {
                const uint32_t off = (uint32_t)((P * 16 + bRow) * AT_STRIDE) * 2 + coff;
                uint32_t k0, k1, k2, k3;
                ldm_x4(k0, k1, k2, k3, uK + off);
                mma_f16(sacc[2*P],   qf[j][0], qf[j][1], qf[j][2], qf[j][3], k0, k1);
                mma_f16(sacc[2*P+1], qf[j][0], qf[j][1], qf[j][2], qf[j][3], k2, k3);
            }
        }

        float mx0 = -1e30f, mx1 = -1e30f;
#pragma unroll
        for (int nt = 0; nt < 8; ++nt) {
            mx0 = fmaxf(mx0, fmaxf(sacc[nt][0], sacc[nt][1]));
            mx1 = fmaxf(mx1, fmaxf(sacc[nt][2], sacc[nt][3]));
        }
        mx0 = fmaxf(mx0, __shfl_xor_sync(0xffffffffu, mx0, 1));
        mx0 = fmaxf(mx0, __shfl_xor_sync(0xffffffffu, mx0, 2));
        mx1 = fmaxf(mx1, __shfl_xor_sync(0xffffffffu, mx1, 1));
        mx1 = fmaxf(mx1, __shfl_xor_sync(0xffffffffu, mx1, 2));
        float mn0 = fmaxf(m0, mx0), mn1 = fmaxf(m1, mx1);
        float r0 = __expf(m0 - mn0), r1 = __expf(m1 - mn1);
        m0 = mn0; m1 = mn1;

        float s0 = 0.f, s1 = 0.f;
#pragma unroll
        for (int nt = 0; nt < 8; ++nt) {
            float e0 = __expf(sacc[nt][0] - mn0);
            float e1 = __expf(sacc[nt][1] - mn0);
            float e2 = __expf(sacc[nt][2] - mn1);
            float e3 = __expf(sacc[nt][3] - mn1);
            sacc[nt][0] = e0; sacc[nt][1] = e1; sacc[nt][2] = e2; sacc[nt][3] = e3;
            s0 += e0 + e1; s1 += e2 + e3;
        }
        s0 += __shfl_xor_sync(0xffffffffu, s0, 1);
        s0 += __shfl_xor_sync(0xffffffffu, s0, 2);
        s1 += __shfl_xor_sync(0xffffffffu, s1, 1);
        s1 += __shfl_xor_sync(0xffffffffu, s1, 2);
        l0 = l0 * r0 + s0; l1 = l1 * r1 + s1;

#pragma unroll
        for (int nt = 0; nt < 8; ++nt) {
            cx[nt][0] *= r0; cx[nt][1] *= r0;
            cx[nt][2] *= r1; cx[nt][3] *= r1;
        }

#pragma unroll
        for (int j = 0; j < 4; ++j) {
            uint32_t pa[4];
            __half2 t0 = __floats2half2_rn(sacc[2*j][0],   sacc[2*j][1]);
            __half2 t1 = __floats2half2_rn(sacc[2*j][2],   sacc[2*j][3]);
            __half2 t2 = __floats2half2_rn(sacc[2*j+1][0], sacc[2*j+1][1]);
            __half2 t3 = __floats2half2_rn(sacc[2*j+1][2], sacc[2*j+1][3]);
            pa[0] = *(uint32_t*)&t0; pa[1] = *(uint32_t*)&t1;
            pa[2] = *(uint32_t*)&t2; pa[3] = *(uint32_t*)&t3;
            const uint32_t coff = (uint32_t)(16 * j + bCol) * 2;
#pragma unroll
            for (int P = 0; P < 4; ++P) {
                const uint32_t off = (uint32_t)((P * 16 + bRow) * AT_STRIDE) * 2 + coff;
                uint32_t v0, v1, v2, v3;
                ldm_x4(v0, v1, v2, v3, uV + off);
                mma_f16(cx[2*P],   pa[0], pa[1], pa[2], pa[3], v0, v1);
                mma_f16(cx[2*P+1], pa[0], pa[1], pa[2], pa[3], v2, v3);
            }
        }
    }
#undef ISSUEA

    // ---- epilogue: ctx fp16 single, flat [M,1024] ----
    const int b = bh >> 4, h = bh & 15;
    const float inv0 = 1.f / l0, inv1 = 1.f / l1;
    const int row0 = wq + gid, row1 = wq + gid + 8;
#pragma unroll
    for (int nt = 0; nt < 8; ++nt) {
        const int dcol = h * HD + 8 * nt + 2 * tig;
        __half2 p0 = __floats2half2_rn(cx[nt][0] * inv0, cx[nt][1] * inv0);
        __half2 p1 = __floats2half2_rn(cx[nt][2] * inv1, cx[nt][3] * inv1);
        *(uint32_t*)&ctx16[(size_t)(b * SEQ + row0) * Dh + dcol] = *(uint32_t*)&p0;
        *(uint32_t*)&ctx16[(size_t)(b * SEQ + row1) * Dh + dcol] = *(uint32_t*)&p1;
    }
}

// ---------------- launch ------------------------------------------------------
extern "C" void kernel_launch(void* const* d_in, const int* in_sizes, int n_in,
                              void* d_out, int out_size)
{
    const float* X  = (const float*)d_in[0];
    const float* Wq = (const float*)d_in[1];
    const float* bq = (const float*)d_in[2];
    const float* Wk = (const float*)d_in[3];
    const float* bk = (const float*)d_in[4];
    const float* Wv = (const float*)d_in[5];
    const float* bv = (const float*)d_in[6];
    const float* Wo = (const float*)d_in[7];
    const float* bo = (const float*)d_in[8];
    float* out = (float*)d_out;

    half *x16, *wq16, *wk16, *wv16, *wo16, *q16, *k16, *v16, *cx16;
    cudaGetSymbolAddress((void**)&x16,  g_x16);
    cudaGetSymbolAddress((void**)&wq16, g_wq16);
    cudaGetSymbolAddress((void**)&wk16, g_wk16);
    cudaGetSymbolAddress((void**)&wv16, g_wv16);
    cudaGetSymbolAddress((void**)&wo16, g_wo16);
    cudaGetSymbolAddress((void**)&q16,  g_q16);
    cudaGetSymbolAddress((void**)&k16,  g_k16);
    cudaGetSymbolAddress((void**)&v16,  g_v16);
    cudaGetSymbolAddress((void**)&cx16, g_cx16);

    cudaFuncSetAttribute(gemm_f16, cudaFuncAttributeMaxDynamicSharedMemorySize, GEMM_SMEM);
    cudaFuncSetAttribute(attn_mma, cudaFuncAttributeMaxDynamicSharedMemorySize, ATT_SMEM);

    dim3 thr(256);
    cvt16<<<(MROWS * Dh / 4 + 255) / 256, thr>>>(X,  x16,  MROWS * Dh / 4);
    cvt16<<<(Dh * Dh / 4 + 255) / 256, thr>>>(Wq, wq16, Dh * Dh / 4);
    cvt16<<<(Dh * Dh / 4 + 255) / 256, thr>>>(Wk, wk16, Dh * Dh / 4);
    cvt16<<<(Dh * Dh / 4 + 255) / 256, thr>>>(Wv, wv16, Dh * Dh / 4);
    cvt16<<<(Dh * Dh / 4 + 255) / 256, thr>>>(Wo, wo16, Dh * Dh / 4);

    dim3 gthr(512);
    dim3 gg(Dh / 128, MROWS / 256);     // (8, 32)
    gemm_f16<<<gg, gthr, GEMM_SMEM>>>(x16, wq16, bq, nullptr, q16, 3);
    gemm_f16<<<gg, gthr, GEMM_SMEM>>>(x16, wk16, bk, nullptr, k16, 1);
    gemm_f16<<<gg, gthr, GEMM_SMEM>>>(x16, wv16, bv, nullptr, v16, 2);

    dim3 ga(SEQ / 128, BATCH * NH);     // (16, 64)
    attn_mma<<<ga, thr, ATT_SMEM>>>(q16, k16, v16, cx16);

    gemm_f16<<<gg, gthr, GEMM_SMEM>>>(cx16, wo16, bo, out, nullptr, 0);
}